// round 1
// baseline (speedup 1.0000x reference)
#include <cuda_runtime.h>
#include <math.h>

#define BB 4
#define SS 2048
#define EE 1024

// Scratch (allocation-free rule: __device__ globals)
__device__ float g_q[(size_t)BB * SS * EE];            // 32 MB
__device__ float g_k[(size_t)BB * SS * EE];            // 32 MB
__device__ float g_v[(size_t)BB * SS * EE];            // 32 MB
__device__ float g_p[(size_t)BB * SS * SS];            // 64 MB (scores / probs)

// ---------------------------------------------------------------------------
// Tiled SGEMM: C[M,N] = alpha * A[M,K] @ B(+bias)
//   TRANS_B = false : B is row-major [K, N]
//   TRANS_B = true  : B is row-major [N, K]  (C = A @ B^T)
// Tile 128x128x16, 256 threads, 8x8 per-thread microtile.
// All dims assumed divisible by tile sizes (true for this problem).
// ---------------------------------------------------------------------------
template <bool TRANS_B, bool HAS_BIAS>
__global__ __launch_bounds__(256, 2)
void sgemm_kernel(const float* __restrict__ A,
                  const float* __restrict__ Bm,
                  const float* __restrict__ bias,
                  float* __restrict__ C,
                  int M, int N, int K,
                  long long strideA, long long strideB, long long strideC,
                  float alpha)
{
    constexpr int BM = 128, BN = 128, BK = 16;
    __shared__ float As[BK][BM + 4];
    __shared__ float Bs[BK][BN + 4];

    const int tid = threadIdx.x;
    const int m0 = blockIdx.y * BM;
    const int n0 = blockIdx.x * BN;

    A  += (size_t)blockIdx.z * strideA;
    Bm += (size_t)blockIdx.z * strideB;
    C  += (size_t)blockIdx.z * strideC;

    const int lda = K;
    const int ldb = TRANS_B ? K : N;
    const int ldc = N;

    const int m_base = (tid >> 4) << 3;   // 0..120 step 8
    const int n_base = (tid & 15) << 3;   // 0..120 step 8

    float acc[8][8];
#pragma unroll
    for (int i = 0; i < 8; i++)
#pragma unroll
        for (int j = 0; j < 8; j++) acc[i][j] = 0.f;

    for (int kt = 0; kt < K; kt += BK) {
        // ---- load A tile: 128x16, float4 along K, store transposed ----
        {
            int idx = tid;
#pragma unroll
            for (int it = 0; it < 2; it++, idx += 256) {
                int row = idx >> 2;
                int kq  = (idx & 3) << 2;
                const float4 va = *(const float4*)&A[(size_t)(m0 + row) * lda + kt + kq];
                As[kq + 0][row] = va.x;
                As[kq + 1][row] = va.y;
                As[kq + 2][row] = va.z;
                As[kq + 3][row] = va.w;
            }
        }
        // ---- load B tile ----
        if (!TRANS_B) {
            int idx = tid;
#pragma unroll
            for (int it = 0; it < 2; it++, idx += 256) {
                int krow = idx >> 5;
                int nc   = (idx & 31) << 2;
                const float4 vb = *(const float4*)&Bm[(size_t)(kt + krow) * ldb + n0 + nc];
                *(float4*)&Bs[krow][nc] = vb;
            }
        } else {
            int idx = tid;
#pragma unroll
            for (int it = 0; it < 2; it++, idx += 256) {
                int n  = idx >> 2;
                int kq = (idx & 3) << 2;
                const float4 vb = *(const float4*)&Bm[(size_t)(n0 + n) * ldb + kt + kq];
                Bs[kq + 0][n] = vb.x;
                Bs[kq + 1][n] = vb.y;
                Bs[kq + 2][n] = vb.z;
                Bs[kq + 3][n] = vb.w;
            }
        }
        __syncthreads();

        // ---- compute ----
#pragma unroll
        for (int kk = 0; kk < BK; kk++) {
            float a[8], b[8];
            *(float4*)&a[0] = *(float4*)&As[kk][m_base];
            *(float4*)&a[4] = *(float4*)&As[kk][m_base + 4];
            *(float4*)&b[0] = *(float4*)&Bs[kk][n_base];
            *(float4*)&b[4] = *(float4*)&Bs[kk][n_base + 4];
#pragma unroll
            for (int i = 0; i < 8; i++)
#pragma unroll
                for (int j = 0; j < 8; j++)
                    acc[i][j] = fmaf(a[i], b[j], acc[i][j]);
        }
        __syncthreads();
    }

    // ---- epilogue ----
    float bb[8];
#pragma unroll
    for (int j = 0; j < 8; j++)
        bb[j] = HAS_BIAS ? bias[n0 + n_base + j] : 0.f;

#pragma unroll
    for (int i = 0; i < 8; i++) {
        float4 o0, o1;
        o0.x = acc[i][0] * alpha + bb[0];
        o0.y = acc[i][1] * alpha + bb[1];
        o0.z = acc[i][2] * alpha + bb[2];
        o0.w = acc[i][3] * alpha + bb[3];
        o1.x = acc[i][4] * alpha + bb[4];
        o1.y = acc[i][5] * alpha + bb[5];
        o1.z = acc[i][6] * alpha + bb[6];
        o1.w = acc[i][7] * alpha + bb[7];
        size_t off = (size_t)(m0 + m_base + i) * ldc + n0 + n_base;
        *(float4*)&C[off]     = o0;
        *(float4*)&C[off + 4] = o1;
    }
}

// ---------------------------------------------------------------------------
// Row softmax over g_p: 8192 rows x 2048 cols. One block (256 thr) per row.
// ---------------------------------------------------------------------------
__inline__ __device__ float warp_max(float v) {
#pragma unroll
    for (int o = 16; o; o >>= 1) v = fmaxf(v, __shfl_xor_sync(0xFFFFFFFFu, v, o));
    return v;
}
__inline__ __device__ float warp_sum(float v) {
#pragma unroll
    for (int o = 16; o; o >>= 1) v += __shfl_xor_sync(0xFFFFFFFFu, v, o);
    return v;
}

__global__ __launch_bounds__(256)
void softmax_rows_kernel(float* __restrict__ P, int n)
{
    __shared__ float red[8];
    const size_t row = blockIdx.x;
    float* p = P + row * (size_t)n;
    const int tid  = threadIdx.x;
    const int lane = tid & 31;
    const int warp = tid >> 5;

    float vals[8];
    float m = -INFINITY;
#pragma unroll
    for (int i = 0; i < 8; i++) {
        vals[i] = p[tid + i * 256];
        m = fmaxf(m, vals[i]);
    }
    m = warp_max(m);
    if (lane == 0) red[warp] = m;
    __syncthreads();
    if (warp == 0) {
        float x = (lane < 8) ? red[lane] : -INFINITY;
        x = warp_max(x);
        if (lane == 0) red[0] = x;
    }
    __syncthreads();
    m = red[0];
    __syncthreads();

    float s = 0.f;
#pragma unroll
    for (int i = 0; i < 8; i++) {
        vals[i] = expf(vals[i] - m);
        s += vals[i];
    }
    s = warp_sum(s);
    if (lane == 0) red[warp] = s;
    __syncthreads();
    if (warp == 0) {
        float x = (lane < 8) ? red[lane] : 0.f;
        x = warp_sum(x);
        if (lane == 0) red[0] = x;
    }
    __syncthreads();
    const float inv = 1.f / red[0];

#pragma unroll
    for (int i = 0; i < 8; i++)
        p[tid + i * 256] = vals[i] * inv;
}

// ---------------------------------------------------------------------------
extern "C" void kernel_launch(void* const* d_in, const int* in_sizes, int n_in,
                              void* d_out, int out_size)
{
    const float* query = (const float*)d_in[0];
    const float* key   = (const float*)d_in[1];
    const float* value = (const float*)d_in[2];
    const float* Wq    = (const float*)d_in[3];
    const float* bq    = (const float*)d_in[4];
    const float* Wk    = (const float*)d_in[5];
    const float* bk    = (const float*)d_in[6];
    const float* Wv    = (const float*)d_in[7];
    const float* bv    = (const float*)d_in[8];
    float* out = (float*)d_out;

    float *q, *k, *v, *p;
    cudaGetSymbolAddress((void**)&q, g_q);
    cudaGetSymbolAddress((void**)&k, g_k);
    cudaGetSymbolAddress((void**)&v, g_v);
    cudaGetSymbolAddress((void**)&p, g_p);

    const dim3 block(256);

    // 1-3) projections: [B*S, E] = [B*S, E] @ [E, E] + bias
    {
        dim3 grid(EE / 128, (BB * SS) / 128, 1);
        sgemm_kernel<false, true><<<grid, block>>>(query, Wq, bq, q,
            BB * SS, EE, EE, 0, 0, 0, 1.0f);
        sgemm_kernel<false, true><<<grid, block>>>(key, Wk, bk, k,
            BB * SS, EE, EE, 0, 0, 0, 1.0f);
        sgemm_kernel<false, true><<<grid, block>>>(value, Wv, bv, v,
            BB * SS, EE, EE, 0, 0, 0, 1.0f);
    }

    // 4) scores: per batch, P = (q @ k^T) / sqrt(E)
    {
        dim3 grid(SS / 128, SS / 128, BB);
        sgemm_kernel<true, false><<<grid, block>>>(q, k, nullptr, p,
            SS, SS, EE,
            (long long)SS * EE, (long long)SS * EE, (long long)SS * SS,
            1.0f / 32.0f);
    }

    // 5) softmax rows in-place
    softmax_rows_kernel<<<BB * SS, block>>>(p, SS);

    // 6) out: per batch, O = P @ v
    {
        dim3 grid(EE / 128, SS / 128, BB);
        sgemm_kernel<false, false><<<grid, block>>>(p, v, nullptr, out,
            SS, EE, SS,
            (long long)SS * SS, (long long)SS * EE, (long long)SS * EE,
            1.0f);
    }
}

// round 2
// speedup vs baseline: 1.0012x; 1.0012x over previous
#include <cuda_runtime.h>
#include <math.h>

#define BB 4
#define SS 2048
#define EE 1024

// Scratch (allocation-free rule: __device__ globals)
__device__ float g_q[(size_t)BB * SS * EE];            // 32 MB
__device__ float g_k[(size_t)BB * SS * EE];            // 32 MB
__device__ float g_v[(size_t)BB * SS * EE];            // 32 MB
__device__ float g_p[(size_t)BB * SS * SS];            // 64 MB (scores / probs)

// ---------------------------------------------------------------------------
// Tiled SGEMM: C[M,N] = alpha * A[M,K] @ B(+bias)
//   TRANS_B = false : B is row-major [K, N]
//   TRANS_B = true  : B is row-major [N, K]  (C = A @ B^T)
// Tile 128x128x16, 256 threads, 8x8 per-thread microtile.
// All dims assumed divisible by tile sizes (true for this problem).
// ---------------------------------------------------------------------------
template <bool TRANS_B, bool HAS_BIAS>
__global__ __launch_bounds__(256, 2)
void sgemm_kernel(const float* __restrict__ A,
                  const float* __restrict__ Bm,
                  const float* __restrict__ bias,
                  float* __restrict__ C,
                  int M, int N, int K,
                  long long strideA, long long strideB, long long strideC,
                  float alpha)
{
    constexpr int BM = 128, BN = 128, BK = 16;
    __shared__ float As[BK][BM + 4];
    __shared__ float Bs[BK][BN + 4];

    const int tid = threadIdx.x;
    const int m0 = blockIdx.y * BM;
    const int n0 = blockIdx.x * BN;

    A  += (size_t)blockIdx.z * strideA;
    Bm += (size_t)blockIdx.z * strideB;
    C  += (size_t)blockIdx.z * strideC;

    const int lda = K;
    const int ldb = TRANS_B ? K : N;
    const int ldc = N;

    const int m_base = (tid >> 4) << 3;   // 0..120 step 8
    const int n_base = (tid & 15) << 3;   // 0..120 step 8

    float acc[8][8];
#pragma unroll
    for (int i = 0; i < 8; i++)
#pragma unroll
        for (int j = 0; j < 8; j++) acc[i][j] = 0.f;

    for (int kt = 0; kt < K; kt += BK) {
        // ---- load A tile: 128x16, float4 along K, store transposed ----
        {
            int idx = tid;
#pragma unroll
            for (int it = 0; it < 2; it++, idx += 256) {
                int row = idx >> 2;
                int kq  = (idx & 3) << 2;
                const float4 va = *(const float4*)&A[(size_t)(m0 + row) * lda + kt + kq];
                As[kq + 0][row] = va.x;
                As[kq + 1][row] = va.y;
                As[kq + 2][row] = va.z;
                As[kq + 3][row] = va.w;
            }
        }
        // ---- load B tile ----
        if (!TRANS_B) {
            int idx = tid;
#pragma unroll
            for (int it = 0; it < 2; it++, idx += 256) {
                int krow = idx >> 5;
                int nc   = (idx & 31) << 2;
                const float4 vb = *(const float4*)&Bm[(size_t)(kt + krow) * ldb + n0 + nc];
                *(float4*)&Bs[krow][nc] = vb;
            }
        } else {
            int idx = tid;
#pragma unroll
            for (int it = 0; it < 2; it++, idx += 256) {
                int n  = idx >> 2;
                int kq = (idx & 3) << 2;
                const float4 vb = *(const float4*)&Bm[(size_t)(n0 + n) * ldb + kt + kq];
                Bs[kq + 0][n] = vb.x;
                Bs[kq + 1][n] = vb.y;
                Bs[kq + 2][n] = vb.z;
                Bs[kq + 3][n] = vb.w;
            }
        }
        __syncthreads();

        // ---- compute ----
#pragma unroll
        for (int kk = 0; kk < BK; kk++) {
            float a[8], b[8];
            *(float4*)&a[0] = *(float4*)&As[kk][m_base];
            *(float4*)&a[4] = *(float4*)&As[kk][m_base + 4];
            *(float4*)&b[0] = *(float4*)&Bs[kk][n_base];
            *(float4*)&b[4] = *(float4*)&Bs[kk][n_base + 4];
#pragma unroll
            for (int i = 0; i < 8; i++)
#pragma unroll
                for (int j = 0; j < 8; j++)
                    acc[i][j] = fmaf(a[i], b[j], acc[i][j]);
        }
        __syncthreads();
    }

    // ---- epilogue ----
    float bb[8];
#pragma unroll
    for (int j = 0; j < 8; j++)
        bb[j] = HAS_BIAS ? bias[n0 + n_base + j] : 0.f;

#pragma unroll
    for (int i = 0; i < 8; i++) {
        float4 o0, o1;
        o0.x = acc[i][0] * alpha + bb[0];
        o0.y = acc[i][1] * alpha + bb[1];
        o0.z = acc[i][2] * alpha + bb[2];
        o0.w = acc[i][3] * alpha + bb[3];
        o1.x = acc[i][4] * alpha + bb[4];
        o1.y = acc[i][5] * alpha + bb[5];
        o1.z = acc[i][6] * alpha + bb[6];
        o1.w = acc[i][7] * alpha + bb[7];
        size_t off = (size_t)(m0 + m_base + i) * ldc + n0 + n_base;
        *(float4*)&C[off]     = o0;
        *(float4*)&C[off + 4] = o1;
    }
}

// ---------------------------------------------------------------------------
// Row softmax over g_p: 8192 rows x 2048 cols. One block (256 thr) per row.
// ---------------------------------------------------------------------------
__inline__ __device__ float warp_max(float v) {
#pragma unroll
    for (int o = 16; o; o >>= 1) v = fmaxf(v, __shfl_xor_sync(0xFFFFFFFFu, v, o));
    return v;
}
__inline__ __device__ float warp_sum(float v) {
#pragma unroll
    for (int o = 16; o; o >>= 1) v += __shfl_xor_sync(0xFFFFFFFFu, v, o);
    return v;
}

__global__ __launch_bounds__(256)
void softmax_rows_kernel(float* __restrict__ P, int n)
{
    __shared__ float red[8];
    const size_t row = blockIdx.x;
    float* p = P + row * (size_t)n;
    const int tid  = threadIdx.x;
    const int lane = tid & 31;
    const int warp = tid >> 5;

    float vals[8];
    float m = -INFINITY;
#pragma unroll
    for (int i = 0; i < 8; i++) {
        vals[i] = p[tid + i * 256];
        m = fmaxf(m, vals[i]);
    }
    m = warp_max(m);
    if (lane == 0) red[warp] = m;
    __syncthreads();
    if (warp == 0) {
        float x = (lane < 8) ? red[lane] : -INFINITY;
        x = warp_max(x);
        if (lane == 0) red[0] = x;
    }
    __syncthreads();
    m = red[0];
    __syncthreads();

    float s = 0.f;
#pragma unroll
    for (int i = 0; i < 8; i++) {
        vals[i] = expf(vals[i] - m);
        s += vals[i];
    }
    s = warp_sum(s);
    if (lane == 0) red[warp] = s;
    __syncthreads();
    if (warp == 0) {
        float x = (lane < 8) ? red[lane] : 0.f;
        x = warp_sum(x);
        if (lane == 0) red[0] = x;
    }
    __syncthreads();
    const float inv = 1.f / red[0];

#pragma unroll
    for (int i = 0; i < 8; i++)
        p[tid + i * 256] = vals[i] * inv;
}

// ---------------------------------------------------------------------------
extern "C" void kernel_launch(void* const* d_in, const int* in_sizes, int n_in,
                              void* d_out, int out_size)
{
    const float* query = (const float*)d_in[0];
    const float* key   = (const float*)d_in[1];
    const float* value = (const float*)d_in[2];
    const float* Wq    = (const float*)d_in[3];
    const float* bq    = (const float*)d_in[4];
    const float* Wk    = (const float*)d_in[5];
    const float* bk    = (const float*)d_in[6];
    const float* Wv    = (const float*)d_in[7];
    const float* bv    = (const float*)d_in[8];
    float* out = (float*)d_out;

    float *q, *k, *v, *p;
    cudaGetSymbolAddress((void**)&q, g_q);
    cudaGetSymbolAddress((void**)&k, g_k);
    cudaGetSymbolAddress((void**)&v, g_v);
    cudaGetSymbolAddress((void**)&p, g_p);

    const dim3 block(256);

    // 1-3) projections: [B*S, E] = [B*S, E] @ [E, E] + bias
    {
        dim3 grid(EE / 128, (BB * SS) / 128, 1);
        sgemm_kernel<false, true><<<grid, block>>>(query, Wq, bq, q,
            BB * SS, EE, EE, 0, 0, 0, 1.0f);
        sgemm_kernel<false, true><<<grid, block>>>(key, Wk, bk, k,
            BB * SS, EE, EE, 0, 0, 0, 1.0f);
        sgemm_kernel<false, true><<<grid, block>>>(value, Wv, bv, v,
            BB * SS, EE, EE, 0, 0, 0, 1.0f);
    }

    // 4) scores: per batch, P = (q @ k^T) / sqrt(E)
    {
        dim3 grid(SS / 128, SS / 128, BB);
        sgemm_kernel<true, false><<<grid, block>>>(q, k, nullptr, p,
            SS, SS, EE,
            (long long)SS * EE, (long long)SS * EE, (long long)SS * SS,
            1.0f / 32.0f);
    }

    // 5) softmax rows in-place
    softmax_rows_kernel<<<BB * SS, block>>>(p, SS);

    // 6) out: per batch, O = P @ v
    {
        dim3 grid(EE / 128, SS / 128, BB);
        sgemm_kernel<false, false><<<grid, block>>>(p, v, nullptr, out,
            SS, EE, SS,
            (long long)SS * SS, (long long)SS * EE, (long long)SS * EE,
            1.0f);
    }
}

// round 4
// speedup vs baseline: 2.1502x; 2.1476x over previous
#include <cuda_runtime.h>
#include <cuda_fp16.h>
#include <math.h>
#include <stdint.h>

#define BB 4
#define SS 2048
#define EE 1024

#define NBS ((size_t)BB * SS * EE)   // 8388608
#define NW  ((size_t)EE * EE)        // 1048576
#define NP  ((size_t)BB * SS * SS)   // 16777216

// ---------------------------------------------------------------------------
// Scratch (__device__ globals; 16B-aligned for vector/cp.async access)
// ---------------------------------------------------------------------------
__device__ __align__(256) __half g_qin_hi[NBS], g_qin_lo[NBS];
__device__ __align__(256) __half g_kin_hi[NBS], g_kin_lo[NBS];
__device__ __align__(256) __half g_vin_hi[NBS], g_vin_lo[NBS];
__device__ __align__(256) __half g_wqt_hi[NW],  g_wqt_lo[NW];
__device__ __align__(256) __half g_wkt_hi[NW],  g_wkt_lo[NW];
__device__ __align__(256) __half g_wvt_hi[NW],  g_wvt_lo[NW];
__device__ __align__(256) __half g_q_hi[NBS],   g_q_lo[NBS];
__device__ __align__(256) __half g_k_hi[NBS],   g_k_lo[NBS];
__device__ __align__(256) __half g_vt_hi[NBS],  g_vt_lo[NBS];
__device__ __align__(256) float  g_v32[NBS];
__device__ __align__(256) float  g_p[NP];
__device__ __align__(256) __half g_p_hi[NP],    g_p_lo[NP];

// ---------------------------------------------------------------------------
// Baseline-PTX primitives (compute_103-safe: no tcgen05 / no 'a' features)
// ---------------------------------------------------------------------------
__device__ __forceinline__ uint32_t smem_u32(const void* p) {
    uint32_t a;
    asm("{ .reg .u64 t; cvta.to.shared.u64 t, %1; cvt.u32.u64 %0, t; }"
        : "=r"(a) : "l"(p));
    return a;
}

__device__ __forceinline__ void cp_async16(uint32_t s, const void* g) {
    asm volatile("cp.async.cg.shared.global [%0], [%1], 16;" :: "r"(s), "l"(g));
}
__device__ __forceinline__ void cp_commit() {
    asm volatile("cp.async.commit_group;" ::: "memory");
}
__device__ __forceinline__ void cp_wait1() {
    asm volatile("cp.async.wait_group 1;" ::: "memory");
}
__device__ __forceinline__ void cp_wait0() {
    asm volatile("cp.async.wait_group 0;" ::: "memory");
}

__device__ __forceinline__ void ldsm4(uint32_t* r, uint32_t addr) {
    asm volatile("ldmatrix.sync.aligned.m8n8.x4.shared.b16 {%0,%1,%2,%3}, [%4];"
        : "=r"(r[0]), "=r"(r[1]), "=r"(r[2]), "=r"(r[3]) : "r"(addr));
}

__device__ __forceinline__ void mma16816(float* c, const uint32_t* a,
                                         const uint32_t* b) {
    asm volatile(
        "mma.sync.aligned.m16n8k16.row.col.f32.f16.f16.f32 "
        "{%0,%1,%2,%3}, {%4,%5,%6,%7}, {%8,%9}, {%0,%1,%2,%3};"
        : "+f"(c[0]), "+f"(c[1]), "+f"(c[2]), "+f"(c[3])
        : "r"(a[0]), "r"(a[1]), "r"(a[2]), "r"(a[3]), "r"(b[0]), "r"(b[1]));
}

__device__ __forceinline__ void split2h(float x, __half& hi, __half& lo) {
    hi = __float2half_rn(x);
    lo = __float2half_rn(x - __half2float(hi));
}

// ---------------------------------------------------------------------------
// HMMA split-fp16 GEMM:  C[M,N] = alpha*(A @ B^T) (+bias)
//   A[M,K], B[N,K] K-major as (hi,lo) fp16 pairs.
//   Terms: Ahi*Bhi + Ahi*Blo + Alo*Bhi, fp32 accumulate.
//   CTA 128x128, BK=32, 8 warps (2x4), warp tile 64x32, cp.async 2-stage.
// ---------------------------------------------------------------------------
// smem geometry (halves): per tensor tile 128 rows x 40 (32 + 8 pad)
#define ROWH 40
#define TILE_H (128 * ROWH)            // 5120 halves = 10240 B
#define STAGE_H (4 * TILE_H)           // 20480 halves = 40960 B
#define SMEM_GEMM_BYTES (2 * STAGE_H * 2)  // 81920 B

template <bool SPLIT_OUT, bool HAS_BIAS>
__global__ __launch_bounds__(256, 1)
void hgemm_split(const __half* __restrict__ Ahi, const __half* __restrict__ Alo,
                 const __half* __restrict__ Bhi, const __half* __restrict__ Blo,
                 const float* __restrict__ bias,
                 float* __restrict__ Cf,
                 __half* __restrict__ Chi, __half* __restrict__ Clo,
                 int M, int N, int K,
                 long long sA, long long sB, long long sC,
                 float alpha)
{
    extern __shared__ __half sm[];
    const uint32_t sbase = smem_u32(sm);

    const int tid  = threadIdx.x;
    const int lane = tid & 31;
    const int wid  = tid >> 5;
    const int wm   = (wid >> 2) * 64;   // warp m offset (0,64)
    const int wn   = (wid & 3) * 32;    // warp n offset (0..96)

    const int n0 = blockIdx.x * 128;
    const int m0 = blockIdx.y * 128;

    Ahi += (size_t)blockIdx.z * sA;  Alo += (size_t)blockIdx.z * sA;
    Bhi += (size_t)blockIdx.z * sB;  Blo += (size_t)blockIdx.z * sB;

    const __half* gp[4] = { Ahi, Alo, Bhi, Blo };

    const int nch = K >> 5;  // K / 32

    // per-thread load slots: 8 x 16B chunks per stage
    // chunk id i in [0,2048): tensor=i>>9, r=(i&511)>>2, cm=i&3
    auto issue_stage = [&](int c, int buf) {
        const int kt = c << 5;
        const uint32_t st = (uint32_t)buf * (STAGE_H * 2);  // bytes
#pragma unroll
        for (int it = 0; it < 8; ++it) {
            const int i = it * 256 + tid;
            const int tensor = i >> 9;
            const int r  = (i & 511) >> 2;
            const int cm = i & 3;
            const int grow = (tensor < 2) ? (m0 + r) : (n0 + r);
            const __half* g = gp[tensor] + (size_t)grow * K + kt + cm * 8;
            const uint32_t s = sbase + st + (uint32_t)tensor * (TILE_H * 2)
                             + (uint32_t)r * (ROWH * 2) + (uint32_t)cm * 16;
            cp_async16(s, g);
        }
        cp_commit();
    };

    float acc[4][4][4];
#pragma unroll
    for (int i = 0; i < 4; ++i)
#pragma unroll
        for (int j = 0; j < 4; ++j)
#pragma unroll
            for (int q = 0; q < 4; ++q) acc[i][j][q] = 0.f;

    issue_stage(0, 0);

    for (int c = 0; c < nch; ++c) {
        const int buf = c & 1;
        if (c + 1 < nch) {
            issue_stage(c + 1, (c + 1) & 1);
            cp_wait1();
        } else {
            cp_wait0();
        }
        __syncthreads();

        const uint32_t st  = (uint32_t)buf * (STAGE_H * 2);
        const uint32_t sAh = sbase + st;
        const uint32_t sAl = sAh + TILE_H * 2;
        const uint32_t sBh = sAh + 2 * TILE_H * 2;
        const uint32_t sBl = sAh + 3 * TILE_H * 2;

#pragma unroll
        for (int ks = 0; ks < 32; ks += 16) {
            // ---- A fragments (hi, lo): 4 m16 tiles ----
            uint32_t ah[4][4], al[4][4];
            {
                const int row = wm + (lane & 15);
                const int col = ks + ((lane >> 4) << 3);
#pragma unroll
                for (int mi = 0; mi < 4; ++mi) {
                    const uint32_t off = (uint32_t)(row + mi * 16) * (ROWH * 2)
                                       + (uint32_t)col * 2;
                    ldsm4(ah[mi], sAh + off);
                    ldsm4(al[mi], sAl + off);
                }
            }
            // ---- B fragments (hi, lo): 2 n16 tiles (each = 2 n8 frags) ----
            uint32_t bh[2][4], bl[2][4];
            {
                const int nrow = wn + ((lane >> 4) << 3) + (lane & 7);
                const int col  = ks + (((lane >> 3) & 1) << 3);
#pragma unroll
                for (int nb = 0; nb < 2; ++nb) {
                    const uint32_t off = (uint32_t)(nrow + nb * 16) * (ROWH * 2)
                                       + (uint32_t)col * 2;
                    ldsm4(bh[nb], sBh + off);
                    ldsm4(bl[nb], sBl + off);
                }
            }
            // ---- 48 mma: term-outermost for ILP ----
#pragma unroll
            for (int mi = 0; mi < 4; ++mi)
#pragma unroll
                for (int nf = 0; nf < 4; ++nf)
                    mma16816(acc[mi][nf], ah[mi], &bh[nf >> 1][(nf & 1) << 1]);
#pragma unroll
            for (int mi = 0; mi < 4; ++mi)
#pragma unroll
                for (int nf = 0; nf < 4; ++nf)
                    mma16816(acc[mi][nf], ah[mi], &bl[nf >> 1][(nf & 1) << 1]);
#pragma unroll
            for (int mi = 0; mi < 4; ++mi)
#pragma unroll
                for (int nf = 0; nf < 4; ++nf)
                    mma16816(acc[mi][nf], al[mi], &bh[nf >> 1][(nf & 1) << 1]);
        }
        __syncthreads();
    }

    // ---- epilogue ----
    const long long cbo = (long long)blockIdx.z * sC;
#pragma unroll
    for (int mi = 0; mi < 4; ++mi) {
        const int r0 = m0 + wm + mi * 16 + (lane >> 2);
#pragma unroll
        for (int nf = 0; nf < 4; ++nf) {
            const int col = n0 + wn + (nf >> 1) * 16 + (nf & 1) * 8 + (lane & 3) * 2;
            float b0 = 0.f, b1 = 0.f;
            if (HAS_BIAS) { b0 = __ldg(&bias[col]); b1 = __ldg(&bias[col + 1]); }
            const float v0 = acc[mi][nf][0] * alpha + b0;
            const float v1 = acc[mi][nf][1] * alpha + b1;
            const float v2 = acc[mi][nf][2] * alpha + b0;
            const float v3 = acc[mi][nf][3] * alpha + b1;
            const long long o0 = cbo + (long long)r0 * N + col;
            const long long o1 = o0 + 8LL * N;
            if (SPLIT_OUT) {
                __half h0, l0, h1, l1, h2, l2, h3, l3;
                split2h(v0, h0, l0); split2h(v1, h1, l1);
                split2h(v2, h2, l2); split2h(v3, h3, l3);
                *reinterpret_cast<__half2*>(Chi + o0) = __halves2half2(h0, h1);
                *reinterpret_cast<__half2*>(Clo + o0) = __halves2half2(l0, l1);
                *reinterpret_cast<__half2*>(Chi + o1) = __halves2half2(h2, h3);
                *reinterpret_cast<__half2*>(Clo + o1) = __halves2half2(l2, l3);
            } else {
                *reinterpret_cast<float2*>(Cf + o0) = make_float2(v0, v1);
                *reinterpret_cast<float2*>(Cf + o1) = make_float2(v2, v3);
            }
        }
    }
}

// ---------------------------------------------------------------------------
// fp32 -> fp16 hi/lo split (elementwise)
// ---------------------------------------------------------------------------
__global__ __launch_bounds__(256)
void split_kernel(const float* __restrict__ in,
                  __half* __restrict__ oh, __half* __restrict__ ol, size_t n)
{
    size_t i = ((size_t)blockIdx.x * 256 + threadIdx.x) * 4;
    if (i >= n) return;
    float4 v = *reinterpret_cast<const float4*>(in + i);
    __half h[4], l[4];
    split2h(v.x, h[0], l[0]); split2h(v.y, h[1], l[1]);
    split2h(v.z, h[2], l[2]); split2h(v.w, h[3], l[3]);
    *reinterpret_cast<uint2*>(oh + i) = *reinterpret_cast<const uint2*>(h);
    *reinterpret_cast<uint2*>(ol + i) = *reinterpret_cast<const uint2*>(l);
}

// ---------------------------------------------------------------------------
// fp32 [R,C] -> transposed fp16 hi/lo [C,R] (batched via blockIdx.z)
// ---------------------------------------------------------------------------
__global__ __launch_bounds__(256)
void transpose_split_kernel(const float* __restrict__ in,
                            __half* __restrict__ oh, __half* __restrict__ ol,
                            int R, int C)
{
    __shared__ float t[32][33];
    const size_t bo = (size_t)blockIdx.z * R * C;
    const int c0 = blockIdx.x * 32, r0 = blockIdx.y * 32;
    const int tx = threadIdx.x, ty = threadIdx.y;  // 32 x 8
#pragma unroll
    for (int j = 0; j < 4; ++j)
        t[ty + 8 * j][tx] = in[bo + (size_t)(r0 + ty + 8 * j) * C + c0 + tx];
    __syncthreads();
#pragma unroll
    for (int j = 0; j < 4; ++j) {
        float v = t[tx][ty + 8 * j];
        __half h, l;
        split2h(v, h, l);
        const size_t o = bo + (size_t)(c0 + ty + 8 * j) * R + r0 + tx;
        oh[o] = h;
        ol[o] = l;
    }
}

// ---------------------------------------------------------------------------
// Row softmax (2048 cols) + fp16 hi/lo split output
// ---------------------------------------------------------------------------
__inline__ __device__ float warp_max(float v) {
#pragma unroll
    for (int o = 16; o; o >>= 1) v = fmaxf(v, __shfl_xor_sync(0xFFFFFFFFu, v, o));
    return v;
}
__inline__ __device__ float warp_sum(float v) {
#pragma unroll
    for (int o = 16; o; o >>= 1) v += __shfl_xor_sync(0xFFFFFFFFu, v, o);
    return v;
}

__global__ __launch_bounds__(256)
void softmax_split_kernel(const float* __restrict__ P,
                          __half* __restrict__ oh, __half* __restrict__ ol, int n)
{
    __shared__ float red[8];
    const size_t row = blockIdx.x;
    const float* p = P + row * (size_t)n;
    const int tid  = threadIdx.x;
    const int lane = tid & 31;
    const int warp = tid >> 5;

    float vals[8];
    float m = -INFINITY;
#pragma unroll
    for (int i = 0; i < 8; i++) {
        vals[i] = p[tid + i * 256];
        m = fmaxf(m, vals[i]);
    }
    m = warp_max(m);
    if (lane == 0) red[warp] = m;
    __syncthreads();
    if (warp == 0) {
        float x = (lane < 8) ? red[lane] : -INFINITY;
        x = warp_max(x);
        if (lane == 0) red[0] = x;
    }
    __syncthreads();
    m = red[0];
    __syncthreads();

    float s = 0.f;
#pragma unroll
    for (int i = 0; i < 8; i++) {
        vals[i] = expf(vals[i] - m);
        s += vals[i];
    }
    s = warp_sum(s);
    if (lane == 0) red[warp] = s;
    __syncthreads();
    if (warp == 0) {
        float x = (lane < 8) ? red[lane] : 0.f;
        x = warp_sum(x);
        if (lane == 0) red[0] = x;
    }
    __syncthreads();
    const float inv = 1.f / red[0];

#pragma unroll
    for (int i = 0; i < 8; i++) {
        __half h, l;
        split2h(vals[i] * inv, h, l);
        oh[row * (size_t)n + tid + i * 256] = h;
        ol[row * (size_t)n + tid + i * 256] = l;
    }
}

// ---------------------------------------------------------------------------
extern "C" void kernel_launch(void* const* d_in, const int* in_sizes, int n_in,
                              void* d_out, int out_size)
{
    const float* query = (const float*)d_in[0];
    const float* key   = (const float*)d_in[1];
    const float* value = (const float*)d_in[2];
    const float* Wq    = (const float*)d_in[3];
    const float* bq    = (const float*)d_in[4];
    const float* Wk    = (const float*)d_in[5];
    const float* bk    = (const float*)d_in[6];
    const float* Wv    = (const float*)d_in[7];
    const float* bv    = (const float*)d_in[8];
    float* out = (float*)d_out;

    __half *qin_hi, *qin_lo, *kin_hi, *kin_lo, *vin_hi, *vin_lo;
    __half *wqt_hi, *wqt_lo, *wkt_hi, *wkt_lo, *wvt_hi, *wvt_lo;
    __half *q_hi, *q_lo, *k_hi, *k_lo, *vt_hi, *vt_lo, *p_hi, *p_lo;
    float *v32, *p32;
    cudaGetSymbolAddress((void**)&qin_hi, g_qin_hi); cudaGetSymbolAddress((void**)&qin_lo, g_qin_lo);
    cudaGetSymbolAddress((void**)&kin_hi, g_kin_hi); cudaGetSymbolAddress((void**)&kin_lo, g_kin_lo);
    cudaGetSymbolAddress((void**)&vin_hi, g_vin_hi); cudaGetSymbolAddress((void**)&vin_lo, g_vin_lo);
    cudaGetSymbolAddress((void**)&wqt_hi, g_wqt_hi); cudaGetSymbolAddress((void**)&wqt_lo, g_wqt_lo);
    cudaGetSymbolAddress((void**)&wkt_hi, g_wkt_hi); cudaGetSymbolAddress((void**)&wkt_lo, g_wkt_lo);
    cudaGetSymbolAddress((void**)&wvt_hi, g_wvt_hi); cudaGetSymbolAddress((void**)&wvt_lo, g_wvt_lo);
    cudaGetSymbolAddress((void**)&q_hi, g_q_hi);     cudaGetSymbolAddress((void**)&q_lo, g_q_lo);
    cudaGetSymbolAddress((void**)&k_hi, g_k_hi);     cudaGetSymbolAddress((void**)&k_lo, g_k_lo);
    cudaGetSymbolAddress((void**)&vt_hi, g_vt_hi);   cudaGetSymbolAddress((void**)&vt_lo, g_vt_lo);
    cudaGetSymbolAddress((void**)&p_hi, g_p_hi);     cudaGetSymbolAddress((void**)&p_lo, g_p_lo);
    cudaGetSymbolAddress((void**)&v32, g_v32);       cudaGetSymbolAddress((void**)&p32, g_p);

    cudaFuncSetAttribute(hgemm_split<true,  true >, cudaFuncAttributeMaxDynamicSharedMemorySize, SMEM_GEMM_BYTES);
    cudaFuncSetAttribute(hgemm_split<false, true >, cudaFuncAttributeMaxDynamicSharedMemorySize, SMEM_GEMM_BYTES);
    cudaFuncSetAttribute(hgemm_split<false, false>, cudaFuncAttributeMaxDynamicSharedMemorySize, SMEM_GEMM_BYTES);

    // 1) split fp32 inputs -> fp16 hi/lo
    {
        const int blocks = (int)(NBS / (256 * 4));
        split_kernel<<<blocks, 256>>>(query, qin_hi, qin_lo, NBS);
        split_kernel<<<blocks, 256>>>(key,   kin_hi, kin_lo, NBS);
        split_kernel<<<blocks, 256>>>(value, vin_hi, vin_lo, NBS);
    }
    // 2) transpose+split weights: W[in,out] -> Wt[out,in]
    {
        dim3 g(EE / 32, EE / 32, 1), b(32, 8);
        transpose_split_kernel<<<g, b>>>(Wq, wqt_hi, wqt_lo, EE, EE);
        transpose_split_kernel<<<g, b>>>(Wk, wkt_hi, wkt_lo, EE, EE);
        transpose_split_kernel<<<g, b>>>(Wv, wvt_hi, wvt_lo, EE, EE);
    }
    // 3) projections: [8192,1024] = X @ Wt^T + bias
    {
        dim3 g(EE / 128, (BB * SS) / 128, 1);
        hgemm_split<true, true><<<g, 256, SMEM_GEMM_BYTES>>>(
            qin_hi, qin_lo, wqt_hi, wqt_lo, bq, nullptr, q_hi, q_lo,
            BB * SS, EE, EE, 0, 0, 0, 1.0f);
        hgemm_split<true, true><<<g, 256, SMEM_GEMM_BYTES>>>(
            kin_hi, kin_lo, wkt_hi, wkt_lo, bk, nullptr, k_hi, k_lo,
            BB * SS, EE, EE, 0, 0, 0, 1.0f);
        hgemm_split<false, true><<<g, 256, SMEM_GEMM_BYTES>>>(
            vin_hi, vin_lo, wvt_hi, wvt_lo, bv, v32, nullptr, nullptr,
            BB * SS, EE, EE, 0, 0, 0, 1.0f);
    }
    // 4) transpose+split v: [S,E] -> [E,S] per batch
    {
        dim3 g(EE / 32, SS / 32, BB), b(32, 8);
        transpose_split_kernel<<<g, b>>>(v32, vt_hi, vt_lo, SS, EE);
    }
    // 5) scores: P = (q @ k^T) / 32, per batch
    {
        dim3 g(SS / 128, SS / 128, BB);
        hgemm_split<false, false><<<g, 256, SMEM_GEMM_BYTES>>>(
            q_hi, q_lo, k_hi, k_lo, nullptr, p32, nullptr, nullptr,
            SS, SS, EE,
            (long long)SS * EE, (long long)SS * EE, (long long)SS * SS,
            1.0f / 32.0f);
    }
    // 6) softmax + split
    softmax_split_kernel<<<BB * SS, 256>>>(p32, p_hi, p_lo, SS);
    // 7) out = P @ vt^T, per batch -> d_out (fp32)
    {
        dim3 g(EE / 128, SS / 128, BB);
        hgemm_split<false, false><<<g, 256, SMEM_GEMM_BYTES>>>(
            p_hi, p_lo, vt_hi, vt_lo, nullptr, out, nullptr, nullptr,
            SS, EE, SS,
            (long long)SS * SS, (long long)SS * EE, (long long)SS * EE,
            1.0f);
    }
}

// round 5
// speedup vs baseline: 2.9910x; 1.3910x over previous
#include <cuda_runtime.h>
#include <cuda_fp16.h>
#include <math.h>
#include <stdint.h>

#define BB 4
#define SS 2048
#define EE 1024

#define NBS ((size_t)BB * SS * EE)   // 8388608
#define NW  ((size_t)EE * EE)        // 1048576
#define NP  ((size_t)BB * SS * SS)   // 16777216

// ---------------------------------------------------------------------------
// Scratch (__device__ globals)
// ---------------------------------------------------------------------------
__device__ __align__(256) __half g_qin_hi[NBS], g_qin_lo[NBS];
__device__ __align__(256) __half g_kin_hi[NBS], g_kin_lo[NBS];
__device__ __align__(256) __half g_vin_hi[NBS], g_vin_lo[NBS];
__device__ __align__(256) __half g_wqt_hi[NW];
__device__ __align__(256) __half g_wkt_hi[NW];
__device__ __align__(256) __half g_wvt_hi[NW];
__device__ __align__(256) __half g_q_hi[NBS],   g_q_lo[NBS];
__device__ __align__(256) __half g_k_hi[NBS];
__device__ __align__(256) __half g_vt_hi[NBS];
__device__ __align__(256) float  g_v32[NBS];
__device__ __align__(256) float  g_p[NP];
__device__ __align__(256) __half g_p_hi[NP],    g_p_lo[NP];

// ---------------------------------------------------------------------------
// Baseline-PTX primitives (compute_103-safe)
// ---------------------------------------------------------------------------
__device__ __forceinline__ uint32_t smem_u32(const void* p) {
    uint32_t a;
    asm("{ .reg .u64 t; cvta.to.shared.u64 t, %1; cvt.u32.u64 %0, t; }"
        : "=r"(a) : "l"(p));
    return a;
}

__device__ __forceinline__ void cp_async16(uint32_t s, const void* g) {
    asm volatile("cp.async.cg.shared.global [%0], [%1], 16;" :: "r"(s), "l"(g));
}
__device__ __forceinline__ void cp_commit() {
    asm volatile("cp.async.commit_group;" ::: "memory");
}
__device__ __forceinline__ void cp_wait1() {
    asm volatile("cp.async.wait_group 1;" ::: "memory");
}

__device__ __forceinline__ void ldsm4(uint32_t* r, uint32_t addr) {
    asm volatile("ldmatrix.sync.aligned.m8n8.x4.shared.b16 {%0,%1,%2,%3}, [%4];"
        : "=r"(r[0]), "=r"(r[1]), "=r"(r[2]), "=r"(r[3]) : "r"(addr));
}

__device__ __forceinline__ void mma16816(float* c, const uint32_t* a,
                                         const uint32_t* b) {
    asm volatile(
        "mma.sync.aligned.m16n8k16.row.col.f32.f16.f16.f32 "
        "{%0,%1,%2,%3}, {%4,%5,%6,%7}, {%8,%9}, {%0,%1,%2,%3};"
        : "+f"(c[0]), "+f"(c[1]), "+f"(c[2]), "+f"(c[3])
        : "r"(a[0]), "r"(a[1]), "r"(a[2]), "r"(a[3]), "r"(b[0]), "r"(b[1]));
}

__device__ __forceinline__ void split2h(float x, __half& hi, __half& lo) {
    hi = __float2half_rn(x);
    lo = __float2half_rn(x - __half2float(hi));
}

// ---------------------------------------------------------------------------
// HMMA 2-term split GEMM:  C[M,N] = alpha*((Ahi+Alo) @ Bhi^T) (+bias)
//   CTA 128x128, BK=32, 8 warps (2x4), warp tile 64x32.
//   3-stage cp.async pipeline, one __syncthreads per K-chunk.
//   OUT_MODE: 0 = fp32, 1 = fp16 hi+lo split, 2 = fp16 hi only
// ---------------------------------------------------------------------------
#define ROWH 40
#define TILE_B (128 * ROWH * 2)          // 10240 B per tensor tile
#define STAGE_B (3 * TILE_B)             // 30720 B (Ahi, Alo, Bhi)
#define SMEM_GEMM_BYTES (3 * STAGE_B)    // 92160 B, 3 stages

template <int OUT_MODE, bool HAS_BIAS>
__global__ __launch_bounds__(256, 1)
void hgemm_split(const __half* __restrict__ Ahi, const __half* __restrict__ Alo,
                 const __half* __restrict__ Bhi,
                 const float* __restrict__ bias,
                 float* __restrict__ Cf,
                 __half* __restrict__ Chi, __half* __restrict__ Clo,
                 int M, int N, int K,
                 long long sA, long long sB, long long sC,
                 float alpha)
{
    extern __shared__ __half sm[];
    const uint32_t sbase = smem_u32(sm);

    const int tid  = threadIdx.x;
    const int lane = tid & 31;
    const int wid  = tid >> 5;
    const int wm   = (wid >> 2) * 64;
    const int wn   = (wid & 3) * 32;

    const int n0 = blockIdx.x * 128;
    const int m0 = blockIdx.y * 128;

    Ahi += (size_t)blockIdx.z * sA;  Alo += (size_t)blockIdx.z * sA;
    Bhi += (size_t)blockIdx.z * sB;

    const __half* gp[3] = { Ahi, Alo, Bhi };

    const int nch = K >> 5;

    // 1536 16B-chunks per stage, 6 per thread
    auto issue_stage = [&](int c, int buf) {
        const int kt = c << 5;
        const uint32_t st = (uint32_t)buf * STAGE_B;
#pragma unroll
        for (int it = 0; it < 6; ++it) {
            const int i = it * 256 + tid;
            const int tensor = i >> 9;
            const int r  = (i & 511) >> 2;
            const int cm = i & 3;
            const int grow = (tensor < 2) ? (m0 + r) : (n0 + r);
            const __half* g = gp[tensor] + (size_t)grow * K + kt + cm * 8;
            const uint32_t s = sbase + st + (uint32_t)tensor * TILE_B
                             + (uint32_t)r * (ROWH * 2) + (uint32_t)cm * 16;
            cp_async16(s, g);
        }
        cp_commit();
    };

    float acc[4][4][4];
#pragma unroll
    for (int i = 0; i < 4; ++i)
#pragma unroll
        for (int j = 0; j < 4; ++j)
#pragma unroll
            for (int q = 0; q < 4; ++q) acc[i][j][q] = 0.f;

    issue_stage(0, 0);
    issue_stage(1, 1);

    for (int c = 0; c < nch; ++c) {
        cp_wait1();            // this thread's stage-c chunks arrived
        __syncthreads();       // all threads' stage-c chunks arrived;
                               // also: all warps finished compute(c-1)

        if (c + 2 < nch) issue_stage(c + 2, (c + 2) % 3);
        else             cp_commit();   // keep group counts aligned

        const uint32_t st  = (uint32_t)(c % 3) * STAGE_B;
        const uint32_t sAh = sbase + st;
        const uint32_t sAl = sAh + TILE_B;
        const uint32_t sBh = sAh + 2 * TILE_B;

#pragma unroll
        for (int ks = 0; ks < 32; ks += 16) {
            uint32_t ah[4][4], al[4][4];
            {
                const int row = wm + (lane & 15);
                const int col = ks + ((lane >> 4) << 3);
#pragma unroll
                for (int mi = 0; mi < 4; ++mi) {
                    const uint32_t off = (uint32_t)(row + mi * 16) * (ROWH * 2)
                                       + (uint32_t)col * 2;
                    ldsm4(ah[mi], sAh + off);
                    ldsm4(al[mi], sAl + off);
                }
            }
            uint32_t bh[2][4];
            {
                const int nrow = wn + ((lane >> 4) << 3) + (lane & 7);
                const int col  = ks + (((lane >> 3) & 1) << 3);
#pragma unroll
                for (int nb = 0; nb < 2; ++nb) {
                    const uint32_t off = (uint32_t)(nrow + nb * 16) * (ROWH * 2)
                                       + (uint32_t)col * 2;
                    ldsm4(bh[nb], sBh + off);
                }
            }
#pragma unroll
            for (int mi = 0; mi < 4; ++mi)
#pragma unroll
                for (int nf = 0; nf < 4; ++nf)
                    mma16816(acc[mi][nf], ah[mi], &bh[nf >> 1][(nf & 1) << 1]);
#pragma unroll
            for (int mi = 0; mi < 4; ++mi)
#pragma unroll
                for (int nf = 0; nf < 4; ++nf)
                    mma16816(acc[mi][nf], al[mi], &bh[nf >> 1][(nf & 1) << 1]);
        }
    }

    // ---- epilogue ----
    const long long cbo = (long long)blockIdx.z * sC;
#pragma unroll
    for (int mi = 0; mi < 4; ++mi) {
        const int r0 = m0 + wm + mi * 16 + (lane >> 2);
#pragma unroll
        for (int nf = 0; nf < 4; ++nf) {
            const int col = n0 + wn + (nf >> 1) * 16 + (nf & 1) * 8 + (lane & 3) * 2;
            float b0 = 0.f, b1 = 0.f;
            if (HAS_BIAS) { b0 = __ldg(&bias[col]); b1 = __ldg(&bias[col + 1]); }
            const float v0 = acc[mi][nf][0] * alpha + b0;
            const float v1 = acc[mi][nf][1] * alpha + b1;
            const float v2 = acc[mi][nf][2] * alpha + b0;
            const float v3 = acc[mi][nf][3] * alpha + b1;
            const long long o0 = cbo + (long long)r0 * N + col;
            const long long o1 = o0 + 8LL * N;
            if (OUT_MODE == 0) {
                *reinterpret_cast<float2*>(Cf + o0) = make_float2(v0, v1);
                *reinterpret_cast<float2*>(Cf + o1) = make_float2(v2, v3);
            } else {
                __half h0, l0, h1, l1, h2, l2, h3, l3;
                split2h(v0, h0, l0); split2h(v1, h1, l1);
                split2h(v2, h2, l2); split2h(v3, h3, l3);
                *reinterpret_cast<__half2*>(Chi + o0) = __halves2half2(h0, h1);
                *reinterpret_cast<__half2*>(Chi + o1) = __halves2half2(h2, h3);
                if (OUT_MODE == 1) {
                    *reinterpret_cast<__half2*>(Clo + o0) = __halves2half2(l0, l1);
                    *reinterpret_cast<__half2*>(Clo + o1) = __halves2half2(l2, l3);
                }
            }
        }
    }
}

// ---------------------------------------------------------------------------
// fp32 -> fp16 hi/lo split (elementwise)
// ---------------------------------------------------------------------------
__global__ __launch_bounds__(256)
void split_kernel(const float* __restrict__ in,
                  __half* __restrict__ oh, __half* __restrict__ ol, size_t n)
{
    size_t i = ((size_t)blockIdx.x * 256 + threadIdx.x) * 4;
    if (i >= n) return;
    float4 v = *reinterpret_cast<const float4*>(in + i);
    __half h[4], l[4];
    split2h(v.x, h[0], l[0]); split2h(v.y, h[1], l[1]);
    split2h(v.z, h[2], l[2]); split2h(v.w, h[3], l[3]);
    *reinterpret_cast<uint2*>(oh + i) = *reinterpret_cast<const uint2*>(h);
    *reinterpret_cast<uint2*>(ol + i) = *reinterpret_cast<const uint2*>(l);
}

// ---------------------------------------------------------------------------
// fp32 [R,C] -> transposed fp16 hi (and optionally lo) [C,R]
// ---------------------------------------------------------------------------
template <bool WRITE_LO>
__global__ __launch_bounds__(256)
void transpose_split_kernel(const float* __restrict__ in,
                            __half* __restrict__ oh, __half* __restrict__ ol,
                            int R, int C)
{
    __shared__ float t[32][33];
    const size_t bo = (size_t)blockIdx.z * R * C;
    const int c0 = blockIdx.x * 32, r0 = blockIdx.y * 32;
    const int tx = threadIdx.x, ty = threadIdx.y;  // 32 x 8
#pragma unroll
    for (int j = 0; j < 4; ++j)
        t[ty + 8 * j][tx] = in[bo + (size_t)(r0 + ty + 8 * j) * C + c0 + tx];
    __syncthreads();
#pragma unroll
    for (int j = 0; j < 4; ++j) {
        float v = t[tx][ty + 8 * j];
        __half h, l;
        split2h(v, h, l);
        const size_t o = bo + (size_t)(c0 + ty + 8 * j) * R + r0 + tx;
        oh[o] = h;
        if (WRITE_LO) ol[o] = l;
    }
}

// ---------------------------------------------------------------------------
// Row softmax (2048 cols) + fp16 hi/lo split output
// ---------------------------------------------------------------------------
__inline__ __device__ float warp_max(float v) {
#pragma unroll
    for (int o = 16; o; o >>= 1) v = fmaxf(v, __shfl_xor_sync(0xFFFFFFFFu, v, o));
    return v;
}
__inline__ __device__ float warp_sum(float v) {
#pragma unroll
    for (int o = 16; o; o >>= 1) v += __shfl_xor_sync(0xFFFFFFFFu, v, o);
    return v;
}

__global__ __launch_bounds__(256)
void softmax_split_kernel(const float* __restrict__ P,
                          __half* __restrict__ oh, __half* __restrict__ ol, int n)
{
    __shared__ float red[8];
    const size_t row = blockIdx.x;
    const float* p = P + row * (size_t)n;
    const int tid  = threadIdx.x;
    const int lane = tid & 31;
    const int warp = tid >> 5;

    float vals[8];
    float m = -INFINITY;
#pragma unroll
    for (int i = 0; i < 8; i++) {
        vals[i] = p[tid + i * 256];
        m = fmaxf(m, vals[i]);
    }
    m = warp_max(m);
    if (lane == 0) red[warp] = m;
    __syncthreads();
    if (warp == 0) {
        float x = (lane < 8) ? red[lane] : -INFINITY;
        x = warp_max(x);
        if (lane == 0) red[0] = x;
    }
    __syncthreads();
    m = red[0];
    __syncthreads();

    float s = 0.f;
#pragma unroll
    for (int i = 0; i < 8; i++) {
        vals[i] = expf(vals[i] - m);
        s += vals[i];
    }
    s = warp_sum(s);
    if (lane == 0) red[warp] = s;
    __syncthreads();
    if (warp == 0) {
        float x = (lane < 8) ? red[lane] : 0.f;
        x = warp_sum(x);
        if (lane == 0) red[0] = x;
    }
    __syncthreads();
    const float inv = 1.f / red[0];

#pragma unroll
    for (int i = 0; i < 8; i++) {
        __half h, l;
        split2h(vals[i] * inv, h, l);
        oh[row * (size_t)n + tid + i * 256] = h;
        ol[row * (size_t)n + tid + i * 256] = l;
    }
}

// ---------------------------------------------------------------------------
extern "C" void kernel_launch(void* const* d_in, const int* in_sizes, int n_in,
                              void* d_out, int out_size)
{
    const float* query = (const float*)d_in[0];
    const float* key   = (const float*)d_in[1];
    const float* value = (const float*)d_in[2];
    const float* Wq    = (const float*)d_in[3];
    const float* bq    = (const float*)d_in[4];
    const float* Wk    = (const float*)d_in[5];
    const float* bk    = (const float*)d_in[6];
    const float* Wv    = (const float*)d_in[7];
    const float* bv    = (const float*)d_in[8];
    float* out = (float*)d_out;

    __half *qin_hi, *qin_lo, *kin_hi, *kin_lo, *vin_hi, *vin_lo;
    __half *wqt_hi, *wkt_hi, *wvt_hi;
    __half *q_hi, *q_lo, *k_hi, *vt_hi, *p_hi, *p_lo;
    float *v32, *p32;
    cudaGetSymbolAddress((void**)&qin_hi, g_qin_hi); cudaGetSymbolAddress((void**)&qin_lo, g_qin_lo);
    cudaGetSymbolAddress((void**)&kin_hi, g_kin_hi); cudaGetSymbolAddress((void**)&kin_lo, g_kin_lo);
    cudaGetSymbolAddress((void**)&vin_hi, g_vin_hi); cudaGetSymbolAddress((void**)&vin_lo, g_vin_lo);
    cudaGetSymbolAddress((void**)&wqt_hi, g_wqt_hi);
    cudaGetSymbolAddress((void**)&wkt_hi, g_wkt_hi);
    cudaGetSymbolAddress((void**)&wvt_hi, g_wvt_hi);
    cudaGetSymbolAddress((void**)&q_hi, g_q_hi);     cudaGetSymbolAddress((void**)&q_lo, g_q_lo);
    cudaGetSymbolAddress((void**)&k_hi, g_k_hi);
    cudaGetSymbolAddress((void**)&vt_hi, g_vt_hi);
    cudaGetSymbolAddress((void**)&p_hi, g_p_hi);     cudaGetSymbolAddress((void**)&p_lo, g_p_lo);
    cudaGetSymbolAddress((void**)&v32, g_v32);       cudaGetSymbolAddress((void**)&p32, g_p);

    cudaFuncSetAttribute(hgemm_split<1, true >, cudaFuncAttributeMaxDynamicSharedMemorySize, SMEM_GEMM_BYTES);
    cudaFuncSetAttribute(hgemm_split<2, true >, cudaFuncAttributeMaxDynamicSharedMemorySize, SMEM_GEMM_BYTES);
    cudaFuncSetAttribute(hgemm_split<0, true >, cudaFuncAttributeMaxDynamicSharedMemorySize, SMEM_GEMM_BYTES);
    cudaFuncSetAttribute(hgemm_split<0, false>, cudaFuncAttributeMaxDynamicSharedMemorySize, SMEM_GEMM_BYTES);

    // 1) split fp32 inputs -> fp16 hi/lo (A operands of projections)
    {
        const int blocks = (int)(NBS / (256 * 4));
        split_kernel<<<blocks, 256>>>(query, qin_hi, qin_lo, NBS);
        split_kernel<<<blocks, 256>>>(key,   kin_hi, kin_lo, NBS);
        split_kernel<<<blocks, 256>>>(value, vin_hi, vin_lo, NBS);
    }
    // 2) transpose weights: W[in,out] -> Wt[out,in], hi only (B operands)
    {
        dim3 g(EE / 32, EE / 32, 1), b(32, 8);
        transpose_split_kernel<false><<<g, b>>>(Wq, wqt_hi, nullptr, EE, EE);
        transpose_split_kernel<false><<<g, b>>>(Wk, wkt_hi, nullptr, EE, EE);
        transpose_split_kernel<false><<<g, b>>>(Wv, wvt_hi, nullptr, EE, EE);
    }
    // 3) projections
    {
        dim3 g(EE / 128, (BB * SS) / 128, 1);
        hgemm_split<1, true><<<g, 256, SMEM_GEMM_BYTES>>>(
            qin_hi, qin_lo, wqt_hi, bq, nullptr, q_hi, q_lo,
            BB * SS, EE, EE, 0, 0, 0, 1.0f);
        hgemm_split<2, true><<<g, 256, SMEM_GEMM_BYTES>>>(
            kin_hi, kin_lo, wkt_hi, bk, nullptr, k_hi, nullptr,
            BB * SS, EE, EE, 0, 0, 0, 1.0f);
        hgemm_split<0, true><<<g, 256, SMEM_GEMM_BYTES>>>(
            vin_hi, vin_lo, wvt_hi, bv, v32, nullptr, nullptr,
            BB * SS, EE, EE, 0, 0, 0, 1.0f);
    }
    // 4) transpose v: [S,E] -> [E,S] per batch, hi only (B operand of PV)
    {
        dim3 g(EE / 32, SS / 32, BB), b(32, 8);
        transpose_split_kernel<false><<<g, b>>>(v32, vt_hi, nullptr, SS, EE);
    }
    // 5) scores: P = (q @ k^T) / 32, per batch
    {
        dim3 g(SS / 128, SS / 128, BB);
        hgemm_split<0, false><<<g, 256, SMEM_GEMM_BYTES>>>(
            q_hi, q_lo, k_hi, nullptr, p32, nullptr, nullptr,
            SS, SS, EE,
            (long long)SS * EE, (long long)SS * EE, (long long)SS * SS,
            1.0f / 32.0f);
    }
    // 6) softmax + split
    softmax_split_kernel<<<BB * SS, 256>>>(p32, p_hi, p_lo, SS);
    // 7) out = P @ vt^T, per batch -> d_out (fp32)
    {
        dim3 g(EE / 128, SS / 128, BB);
        hgemm_split<0, false><<<g, 256, SMEM_GEMM_BYTES>>>(
            p_hi, p_lo, vt_hi, nullptr, out, nullptr, nullptr,
            SS, EE, SS,
            (long long)SS * SS, (long long)SS * EE, (long long)SS * EE,
            1.0f);
    }
}

// round 6
// speedup vs baseline: 3.6402x; 1.2171x over previous
#include <cuda_runtime.h>
#include <cuda_fp16.h>
#include <math.h>
#include <stdint.h>

#define BB 4
#define SS 2048
#define EE 1024

#define NBS ((size_t)BB * SS * EE)   // 8388608
#define NW  ((size_t)EE * EE)        // 1048576
#define NP  ((size_t)BB * SS * SS)   // 16777216

// ---------------------------------------------------------------------------
// Scratch (__device__ globals)
// ---------------------------------------------------------------------------
__device__ __align__(256) __half g_qin_hi[NBS], g_qin_lo[NBS];
__device__ __align__(256) __half g_kin_hi[NBS], g_kin_lo[NBS];
__device__ __align__(256) __half g_vin_hi[NBS], g_vin_lo[NBS];
__device__ __align__(256) __half g_wqt_hi[NW];
__device__ __align__(256) __half g_wkt_hi[NW];
__device__ __align__(256) __half g_wvt_hi[NW];
__device__ __align__(256) __half g_q_hi[NBS];
__device__ __align__(256) __half g_k_hi[NBS];
__device__ __align__(256) __half g_vt_hi[NBS];
__device__ __align__(256) float  g_v32[NBS];
__device__ __align__(256) float  g_p[NP];
__device__ __align__(256) __half g_p_hi[NP];

// ---------------------------------------------------------------------------
// Baseline-PTX primitives (compute_103-safe)
// ---------------------------------------------------------------------------
__device__ __forceinline__ uint32_t smem_u32(const void* p) {
    uint32_t a;
    asm("{ .reg .u64 t; cvta.to.shared.u64 t, %1; cvt.u32.u64 %0, t; }"
        : "=r"(a) : "l"(p));
    return a;
}

__device__ __forceinline__ void cp_async16(uint32_t s, const void* g) {
    asm volatile("cp.async.cg.shared.global [%0], [%1], 16;" :: "r"(s), "l"(g));
}
__device__ __forceinline__ void cp_commit() {
    asm volatile("cp.async.commit_group;" ::: "memory");
}
__device__ __forceinline__ void cp_wait1() {
    asm volatile("cp.async.wait_group 1;" ::: "memory");
}

__device__ __forceinline__ void ldsm4(uint32_t* r, uint32_t addr) {
    asm volatile("ldmatrix.sync.aligned.m8n8.x4.shared.b16 {%0,%1,%2,%3}, [%4];"
        : "=r"(r[0]), "=r"(r[1]), "=r"(r[2]), "=r"(r[3]) : "r"(addr));
}

__device__ __forceinline__ void mma16816(float* c, const uint32_t* a,
                                         const uint32_t* b) {
    asm volatile(
        "mma.sync.aligned.m16n8k16.row.col.f32.f16.f16.f32 "
        "{%0,%1,%2,%3}, {%4,%5,%6,%7}, {%8,%9}, {%0,%1,%2,%3};"
        : "+f"(c[0]), "+f"(c[1]), "+f"(c[2]), "+f"(c[3])
        : "r"(a[0]), "r"(a[1]), "r"(a[2]), "r"(a[3]), "r"(b[0]), "r"(b[1]));
}

__device__ __forceinline__ void split2h(float x, __half& hi, __half& lo) {
    hi = __float2half_rn(x);
    lo = __float2half_rn(x - __half2float(hi));
}

// ---------------------------------------------------------------------------
// HMMA GEMM:  C[M,N] = alpha*(A @ Bhi^T) (+bias)
//   A_SPLIT: A = Ahi + Alo (2 MMA terms); else A = Ahi (1 term)
//   CTA 128x128, BK=32, 8 warps (2x4), warp tile 64x32.
//   3-stage cp.async pipeline, one __syncthreads per K-chunk.
//   OUT_MODE: 0 = fp32, 2 = fp16 hi only
// ---------------------------------------------------------------------------
#define ROWH 40
#define TILE_B (128 * ROWH * 2)          // 10240 B per tensor tile

template <int OUT_MODE, bool HAS_BIAS, bool A_SPLIT>
__global__ __launch_bounds__(256, 1)
void hgemm_split(const __half* __restrict__ Ahi, const __half* __restrict__ Alo,
                 const __half* __restrict__ Bhi,
                 const float* __restrict__ bias,
                 float* __restrict__ Cf,
                 __half* __restrict__ Chi,
                 int M, int N, int K,
                 long long sA, long long sB, long long sC,
                 float alpha)
{
    constexpr int NT = A_SPLIT ? 3 : 2;          // tensors per stage
    constexpr int STAGE_B = NT * TILE_B;
    extern __shared__ __half sm[];
    const uint32_t sbase = smem_u32(sm);

    const int tid  = threadIdx.x;
    const int lane = tid & 31;
    const int wid  = tid >> 5;
    const int wm   = (wid >> 2) * 64;
    const int wn   = (wid & 3) * 32;

    const int n0 = blockIdx.x * 128;
    const int m0 = blockIdx.y * 128;

    Ahi += (size_t)blockIdx.z * sA;
    if (A_SPLIT) Alo += (size_t)blockIdx.z * sA;
    Bhi += (size_t)blockIdx.z * sB;

    const __half* gp[3] = { Ahi, A_SPLIT ? Alo : Bhi, Bhi };

    const int nch = K >> 5;

    // NT*512 16B-chunks per stage, NT*2 per thread
    auto issue_stage = [&](int c, int buf) {
        const int kt = c << 5;
        const uint32_t st = (uint32_t)buf * STAGE_B;
#pragma unroll
        for (int it = 0; it < NT * 2; ++it) {
            const int i = it * 256 + tid;
            const int tensor = i >> 9;
            const int r  = (i & 511) >> 2;
            const int cm = i & 3;
            const bool isA = A_SPLIT ? (tensor < 2) : (tensor < 1);
            const int grow = isA ? (m0 + r) : (n0 + r);
            const __half* g = gp[tensor] + (size_t)grow * K + kt + cm * 8;
            const uint32_t s = sbase + st + (uint32_t)tensor * TILE_B
                             + (uint32_t)r * (ROWH * 2) + (uint32_t)cm * 16;
            cp_async16(s, g);
        }
        cp_commit();
    };

    float acc[4][4][4];
#pragma unroll
    for (int i = 0; i < 4; ++i)
#pragma unroll
        for (int j = 0; j < 4; ++j)
#pragma unroll
            for (int q = 0; q < 4; ++q) acc[i][j][q] = 0.f;

    issue_stage(0, 0);
    issue_stage(1, 1);

    for (int c = 0; c < nch; ++c) {
        cp_wait1();
        __syncthreads();

        if (c + 2 < nch) issue_stage(c + 2, (c + 2) % 3);
        else             cp_commit();   // keep group counts aligned

        const uint32_t st  = (uint32_t)(c % 3) * STAGE_B;
        const uint32_t sAh = sbase + st;
        const uint32_t sAl = sAh + TILE_B;                 // valid iff A_SPLIT
        const uint32_t sBh = sAh + (uint32_t)(NT - 1) * TILE_B;

#pragma unroll
        for (int ks = 0; ks < 32; ks += 16) {
            uint32_t ah[4][4], al[4][4];
            {
                const int row = wm + (lane & 15);
                const int col = ks + ((lane >> 4) << 3);
#pragma unroll
                for (int mi = 0; mi < 4; ++mi) {
                    const uint32_t off = (uint32_t)(row + mi * 16) * (ROWH * 2)
                                       + (uint32_t)col * 2;
                    ldsm4(ah[mi], sAh + off);
                    if (A_SPLIT) ldsm4(al[mi], sAl + off);
                }
            }
            uint32_t bh[2][4];
            {
                const int nrow = wn + ((lane >> 4) << 3) + (lane & 7);
                const int col  = ks + (((lane >> 3) & 1) << 3);
#pragma unroll
                for (int nb = 0; nb < 2; ++nb) {
                    const uint32_t off = (uint32_t)(nrow + nb * 16) * (ROWH * 2)
                                       + (uint32_t)col * 2;
                    ldsm4(bh[nb], sBh + off);
                }
            }
#pragma unroll
            for (int mi = 0; mi < 4; ++mi)
#pragma unroll
                for (int nf = 0; nf < 4; ++nf)
                    mma16816(acc[mi][nf], ah[mi], &bh[nf >> 1][(nf & 1) << 1]);
            if (A_SPLIT) {
#pragma unroll
                for (int mi = 0; mi < 4; ++mi)
#pragma unroll
                    for (int nf = 0; nf < 4; ++nf)
                        mma16816(acc[mi][nf], al[mi], &bh[nf >> 1][(nf & 1) << 1]);
            }
        }
    }

    // ---- epilogue ----
    const long long cbo = (long long)blockIdx.z * sC;
#pragma unroll
    for (int mi = 0; mi < 4; ++mi) {
        const int r0 = m0 + wm + mi * 16 + (lane >> 2);
#pragma unroll
        for (int nf = 0; nf < 4; ++nf) {
            const int col = n0 + wn + (nf >> 1) * 16 + (nf & 1) * 8 + (lane & 3) * 2;
            float b0 = 0.f, b1 = 0.f;
            if (HAS_BIAS) { b0 = __ldg(&bias[col]); b1 = __ldg(&bias[col + 1]); }
            const float v0 = acc[mi][nf][0] * alpha + b0;
            const float v1 = acc[mi][nf][1] * alpha + b1;
            const float v2 = acc[mi][nf][2] * alpha + b0;
            const float v3 = acc[mi][nf][3] * alpha + b1;
            const long long o0 = cbo + (long long)r0 * N + col;
            const long long o1 = o0 + 8LL * N;
            if (OUT_MODE == 0) {
                *reinterpret_cast<float2*>(Cf + o0) = make_float2(v0, v1);
                *reinterpret_cast<float2*>(Cf + o1) = make_float2(v2, v3);
            } else {
                *reinterpret_cast<__half2*>(Chi + o0) =
                    __halves2half2(__float2half_rn(v0), __float2half_rn(v1));
                *reinterpret_cast<__half2*>(Chi + o1) =
                    __halves2half2(__float2half_rn(v2), __float2half_rn(v3));
            }
        }
    }
}

#define SMEM_GEMM3 (3 * 3 * TILE_B)   // 92160 B (A_SPLIT)
#define SMEM_GEMM2 (3 * 2 * TILE_B)   // 61440 B (hi-only)

// ---------------------------------------------------------------------------
// fp32 -> fp16 hi/lo split (elementwise)
// ---------------------------------------------------------------------------
__global__ __launch_bounds__(256)
void split_kernel(const float* __restrict__ in,
                  __half* __restrict__ oh, __half* __restrict__ ol, size_t n)
{
    size_t i = ((size_t)blockIdx.x * 256 + threadIdx.x) * 4;
    if (i >= n) return;
    float4 v = *reinterpret_cast<const float4*>(in + i);
    __half h[4], l[4];
    split2h(v.x, h[0], l[0]); split2h(v.y, h[1], l[1]);
    split2h(v.z, h[2], l[2]); split2h(v.w, h[3], l[3]);
    *reinterpret_cast<uint2*>(oh + i) = *reinterpret_cast<const uint2*>(h);
    *reinterpret_cast<uint2*>(ol + i) = *reinterpret_cast<const uint2*>(l);
}

// ---------------------------------------------------------------------------
// fp32 [R,C] -> transposed fp16 hi [C,R] (batched via blockIdx.z)
// ---------------------------------------------------------------------------
__global__ __launch_bounds__(256)
void transpose_h_kernel(const float* __restrict__ in,
                        __half* __restrict__ oh, int R, int C)
{
    __shared__ float t[32][33];
    const size_t bo = (size_t)blockIdx.z * R * C;
    const int c0 = blockIdx.x * 32, r0 = blockIdx.y * 32;
    const int tx = threadIdx.x, ty = threadIdx.y;  // 32 x 8
#pragma unroll
    for (int j = 0; j < 4; ++j)
        t[ty + 8 * j][tx] = in[bo + (size_t)(r0 + ty + 8 * j) * C + c0 + tx];
    __syncthreads();
#pragma unroll
    for (int j = 0; j < 4; ++j) {
        const size_t o = bo + (size_t)(c0 + ty + 8 * j) * R + r0 + tx;
        oh[o] = __float2half_rn(t[tx][ty + 8 * j]);
    }
}

// ---------------------------------------------------------------------------
// Row softmax (2048 cols) -> fp16 output
// ---------------------------------------------------------------------------
__inline__ __device__ float warp_max(float v) {
#pragma unroll
    for (int o = 16; o; o >>= 1) v = fmaxf(v, __shfl_xor_sync(0xFFFFFFFFu, v, o));
    return v;
}
__inline__ __device__ float warp_sum(float v) {
#pragma unroll
    for (int o = 16; o; o >>= 1) v += __shfl_xor_sync(0xFFFFFFFFu, v, o);
    return v;
}

__global__ __launch_bounds__(256)
void softmax_h_kernel(const float* __restrict__ P,
                      __half* __restrict__ oh, int n)
{
    __shared__ float red[8];
    const size_t row = blockIdx.x;
    const float* p = P + row * (size_t)n;
    const int tid  = threadIdx.x;
    const int lane = tid & 31;
    const int warp = tid >> 5;

    float vals[8];
    float m = -INFINITY;
#pragma unroll
    for (int i = 0; i < 8; i++) {
        vals[i] = p[tid + i * 256];
        m = fmaxf(m, vals[i]);
    }
    m = warp_max(m);
    if (lane == 0) red[warp] = m;
    __syncthreads();
    if (warp == 0) {
        float x = (lane < 8) ? red[lane] : -INFINITY;
        x = warp_max(x);
        if (lane == 0) red[0] = x;
    }
    __syncthreads();
    m = red[0];
    __syncthreads();

    float s = 0.f;
#pragma unroll
    for (int i = 0; i < 8; i++) {
        vals[i] = expf(vals[i] - m);
        s += vals[i];
    }
    s = warp_sum(s);
    if (lane == 0) red[warp] = s;
    __syncthreads();
    if (warp == 0) {
        float x = (lane < 8) ? red[lane] : 0.f;
        x = warp_sum(x);
        if (lane == 0) red[0] = x;
    }
    __syncthreads();
    const float inv = 1.f / red[0];

#pragma unroll
    for (int i = 0; i < 8; i++)
        oh[row * (size_t)n + tid + i * 256] = __float2half_rn(vals[i] * inv);
}

// ---------------------------------------------------------------------------
extern "C" void kernel_launch(void* const* d_in, const int* in_sizes, int n_in,
                              void* d_out, int out_size)
{
    const float* query = (const float*)d_in[0];
    const float* key   = (const float*)d_in[1];
    const float* value = (const float*)d_in[2];
    const float* Wq    = (const float*)d_in[3];
    const float* bq    = (const float*)d_in[4];
    const float* Wk    = (const float*)d_in[5];
    const float* bk    = (const float*)d_in[6];
    const float* Wv    = (const float*)d_in[7];
    const float* bv    = (const float*)d_in[8];
    float* out = (float*)d_out;

    __half *qin_hi, *qin_lo, *kin_hi, *kin_lo, *vin_hi, *vin_lo;
    __half *wqt_hi, *wkt_hi, *wvt_hi;
    __half *q_hi, *k_hi, *vt_hi, *p_hi;
    float *v32, *p32;
    cudaGetSymbolAddress((void**)&qin_hi, g_qin_hi); cudaGetSymbolAddress((void**)&qin_lo, g_qin_lo);
    cudaGetSymbolAddress((void**)&kin_hi, g_kin_hi); cudaGetSymbolAddress((void**)&kin_lo, g_kin_lo);
    cudaGetSymbolAddress((void**)&vin_hi, g_vin_hi); cudaGetSymbolAddress((void**)&vin_lo, g_vin_lo);
    cudaGetSymbolAddress((void**)&wqt_hi, g_wqt_hi);
    cudaGetSymbolAddress((void**)&wkt_hi, g_wkt_hi);
    cudaGetSymbolAddress((void**)&wvt_hi, g_wvt_hi);
    cudaGetSymbolAddress((void**)&q_hi, g_q_hi);
    cudaGetSymbolAddress((void**)&k_hi, g_k_hi);
    cudaGetSymbolAddress((void**)&vt_hi, g_vt_hi);
    cudaGetSymbolAddress((void**)&p_hi, g_p_hi);
    cudaGetSymbolAddress((void**)&v32, g_v32);
    cudaGetSymbolAddress((void**)&p32, g_p);

    cudaFuncSetAttribute(hgemm_split<2, true,  true >, cudaFuncAttributeMaxDynamicSharedMemorySize, SMEM_GEMM3);
    cudaFuncSetAttribute(hgemm_split<0, true,  true >, cudaFuncAttributeMaxDynamicSharedMemorySize, SMEM_GEMM3);
    cudaFuncSetAttribute(hgemm_split<0, false, false>, cudaFuncAttributeMaxDynamicSharedMemorySize, SMEM_GEMM2);

    // 1) split fp32 inputs -> fp16 hi/lo (A operands of projections)
    {
        const int blocks = (int)(NBS / (256 * 4));
        split_kernel<<<blocks, 256>>>(query, qin_hi, qin_lo, NBS);
        split_kernel<<<blocks, 256>>>(key,   kin_hi, kin_lo, NBS);
        split_kernel<<<blocks, 256>>>(value, vin_hi, vin_lo, NBS);
    }
    // 2) transpose weights: W[in,out] -> Wt[out,in], hi only (B operands)
    {
        dim3 g(EE / 32, EE / 32, 1), b(32, 8);
        transpose_h_kernel<<<g, b>>>(Wq, wqt_hi, EE, EE);
        transpose_h_kernel<<<g, b>>>(Wk, wkt_hi, EE, EE);
        transpose_h_kernel<<<g, b>>>(Wv, wvt_hi, EE, EE);
    }
    // 3) projections (A split, 2 terms)
    {
        dim3 g(EE / 128, (BB * SS) / 128, 1);
        hgemm_split<2, true, true><<<g, 256, SMEM_GEMM3>>>(
            qin_hi, qin_lo, wqt_hi, bq, nullptr, q_hi,
            BB * SS, EE, EE, 0, 0, 0, 1.0f);
        hgemm_split<2, true, true><<<g, 256, SMEM_GEMM3>>>(
            kin_hi, kin_lo, wkt_hi, bk, nullptr, k_hi,
            BB * SS, EE, EE, 0, 0, 0, 1.0f);
        hgemm_split<0, true, true><<<g, 256, SMEM_GEMM3>>>(
            vin_hi, vin_lo, wvt_hi, bv, v32, nullptr,
            BB * SS, EE, EE, 0, 0, 0, 1.0f);
    }
    // 4) transpose v: [S,E] -> [E,S] per batch (B operand of PV)
    {
        dim3 g(EE / 32, SS / 32, BB), b(32, 8);
        transpose_h_kernel<<<g, b>>>(v32, vt_hi, SS, EE);
    }
    // 5) scores: P = (q @ k^T) / 32, per batch (hi-only, 1 term)
    {
        dim3 g(SS / 128, SS / 128, BB);
        hgemm_split<0, false, false><<<g, 256, SMEM_GEMM2>>>(
            q_hi, nullptr, k_hi, nullptr, p32, nullptr,
            SS, SS, EE,
            (long long)SS * EE, (long long)SS * EE, (long long)SS * SS,
            1.0f / 32.0f);
    }
    // 6) softmax -> fp16
    softmax_h_kernel<<<BB * SS, 256>>>(p32, p_hi, SS);
    // 7) out = P @ vt^T, per batch -> d_out (fp32, hi-only, 1 term)
    {
        dim3 g(EE / 128, SS / 128, BB);
        hgemm_split<0, false, false><<<g, 256, SMEM_GEMM2>>>(
            p_hi, nullptr, vt_hi, nullptr, out, nullptr,
            SS, EE, SS,
            (long long)SS * SS, (long long)SS * EE, (long long)SS * EE,
            1.0f);
    }
}

// round 7
// speedup vs baseline: 4.1699x; 1.1455x over previous
#include <cuda_runtime.h>
#include <cuda_fp16.h>
#include <math.h>
#include <stdint.h>

#define BB 4
#define SS 2048
#define EE 1024

#define NBS ((size_t)BB * SS * EE)   // 8388608
#define NW  ((size_t)EE * EE)        // 1048576
#define NP  ((size_t)BB * SS * SS)   // 16777216

// ---------------------------------------------------------------------------
// Scratch (__device__ globals)
// ---------------------------------------------------------------------------
__device__ __align__(256) __half g_qin_hi[NBS], g_qin_lo[NBS];
__device__ __align__(256) __half g_kin_hi[NBS], g_kin_lo[NBS];
__device__ __align__(256) __half g_vin_hi[NBS], g_vin_lo[NBS];
__device__ __align__(256) __half g_wqt_hi[NW];
__device__ __align__(256) __half g_wkt_hi[NW];
__device__ __align__(256) __half g_wvt_hi[NW];
__device__ __align__(256) __half g_q_hi[NBS];
__device__ __align__(256) __half g_k_hi[NBS];
__device__ __align__(256) __half g_vt_hi[NBS];
__device__ __align__(256) float  g_v32[NBS];
__device__ __align__(256) float  g_p[NP];
__device__ __align__(256) __half g_p_hi[NP];

// ---------------------------------------------------------------------------
// Baseline-PTX primitives (compute_103-safe)
// ---------------------------------------------------------------------------
__device__ __forceinline__ uint32_t smem_u32(const void* p) {
    uint32_t a;
    asm("{ .reg .u64 t; cvta.to.shared.u64 t, %1; cvt.u32.u64 %0, t; }"
        : "=r"(a) : "l"(p));
    return a;
}

__device__ __forceinline__ void cp_async16(uint32_t s, const void* g) {
    asm volatile("cp.async.cg.shared.global [%0], [%1], 16;" :: "r"(s), "l"(g));
}
__device__ __forceinline__ void cp_commit() {
    asm volatile("cp.async.commit_group;" ::: "memory");
}
__device__ __forceinline__ void cp_wait1() {
    asm volatile("cp.async.wait_group 1;" ::: "memory");
}

__device__ __forceinline__ void ldsm4(uint32_t* r, uint32_t addr) {
    asm volatile("ldmatrix.sync.aligned.m8n8.x4.shared.b16 {%0,%1,%2,%3}, [%4];"
        : "=r"(r[0]), "=r"(r[1]), "=r"(r[2]), "=r"(r[3]) : "r"(addr));
}

__device__ __forceinline__ void mma16816(float* c, const uint32_t* a,
                                         const uint32_t* b) {
    asm volatile(
        "mma.sync.aligned.m16n8k16.row.col.f32.f16.f16.f32 "
        "{%0,%1,%2,%3}, {%4,%5,%6,%7}, {%8,%9}, {%0,%1,%2,%3};"
        : "+f"(c[0]), "+f"(c[1]), "+f"(c[2]), "+f"(c[3])
        : "r"(a[0]), "r"(a[1]), "r"(a[2]), "r"(a[3]), "r"(b[0]), "r"(b[1]));
}

__device__ __forceinline__ void split2h(float x, __half& hi, __half& lo) {
    hi = __float2half_rn(x);
    lo = __float2half_rn(x - __half2float(hi));
}

// ---------------------------------------------------------------------------
// HMMA GEMM:  C[M,N] = alpha*(A @ Bhi^T) (+bias)
//   A_SPLIT: A = Ahi + Alo (2 MMA terms); else A = Ahi (1 term)
//   CTA 128x256, BK=32, 8 warps (2x4), warp tile 64x64.
//   3-stage cp.async pipeline, one __syncthreads per K-chunk.
//   OUT_MODE: 0 = fp32, 2 = fp16 hi only
// ---------------------------------------------------------------------------
#define ROWH 40
#define TILE_A (128 * ROWH * 2)          // 10240 B (A tile, 128 rows)
#define TILE_BB (256 * ROWH * 2)         // 20480 B (B tile, 256 rows)

template <int OUT_MODE, bool HAS_BIAS, bool A_SPLIT>
__global__ __launch_bounds__(256, 1)
void hgemm_split(const __half* __restrict__ Ahi, const __half* __restrict__ Alo,
                 const __half* __restrict__ Bhi,
                 const float* __restrict__ bias,
                 float* __restrict__ Cf,
                 __half* __restrict__ Chi,
                 int M, int N, int K,
                 long long sA, long long sB, long long sC,
                 float alpha)
{
    constexpr int NA = A_SPLIT ? 2 : 1;               // A tensors per stage
    constexpr int STAGE_B = NA * TILE_A + TILE_BB;
    extern __shared__ __half sm[];
    const uint32_t sbase = smem_u32(sm);

    const int tid  = threadIdx.x;
    const int lane = tid & 31;
    const int wid  = tid >> 5;
    const int wm   = (wid >> 2) * 64;      // 0,64
    const int wn   = (wid & 3) * 64;       // 0,64,128,192

    const int n0 = blockIdx.x * 256;
    const int m0 = blockIdx.y * 128;

    Ahi += (size_t)blockIdx.z * sA;
    if (A_SPLIT) Alo += (size_t)blockIdx.z * sA;
    Bhi += (size_t)blockIdx.z * sB;

    const int nch = K >> 5;

    auto issue_stage = [&](int c, int buf) {
        const int kt = c << 5;
        const uint32_t st = (uint32_t)buf * STAGE_B;
        // A tensors: NA * 512 chunks
#pragma unroll
        for (int it = 0; it < NA * 2; ++it) {
            const int i = it * 256 + tid;
            const int tensor = i >> 9;            // 0=Ahi, 1=Alo
            const int r  = (i & 511) >> 2;
            const int cm = i & 3;
            const __half* g = (tensor ? Alo : Ahi) + (size_t)(m0 + r) * K + kt + cm * 8;
            const uint32_t s = sbase + st + (uint32_t)tensor * TILE_A
                             + (uint32_t)r * (ROWH * 2) + (uint32_t)cm * 16;
            cp_async16(s, g);
        }
        // B tensor: 1024 chunks
#pragma unroll
        for (int it = 0; it < 4; ++it) {
            const int i = it * 256 + tid;
            const int r  = i >> 2;
            const int cm = i & 3;
            const __half* g = Bhi + (size_t)(n0 + r) * K + kt + cm * 8;
            const uint32_t s = sbase + st + (uint32_t)NA * TILE_A
                             + (uint32_t)r * (ROWH * 2) + (uint32_t)cm * 16;
            cp_async16(s, g);
        }
        cp_commit();
    };

    float acc[4][8][4];
#pragma unroll
    for (int i = 0; i < 4; ++i)
#pragma unroll
        for (int j = 0; j < 8; ++j)
#pragma unroll
            for (int q = 0; q < 4; ++q) acc[i][j][q] = 0.f;

    issue_stage(0, 0);
    issue_stage(1, 1);

    for (int c = 0; c < nch; ++c) {
        cp_wait1();
        __syncthreads();

        if (c + 2 < nch) issue_stage(c + 2, (c + 2) % 3);
        else             cp_commit();   // keep group counts aligned

        const uint32_t st  = (uint32_t)(c % 3) * STAGE_B;
        const uint32_t sAh = sbase + st;
        const uint32_t sAl = sAh + TILE_A;                  // valid iff A_SPLIT
        const uint32_t sBh = sbase + st + (uint32_t)NA * TILE_A;

#pragma unroll
        for (int ks = 0; ks < 32; ks += 16) {
            uint32_t ah[4][4], al[4][4];
            {
                const int row = wm + (lane & 15);
                const int col = ks + ((lane >> 4) << 3);
#pragma unroll
                for (int mi = 0; mi < 4; ++mi) {
                    const uint32_t off = (uint32_t)(row + mi * 16) * (ROWH * 2)
                                       + (uint32_t)col * 2;
                    ldsm4(ah[mi], sAh + off);
                    if (A_SPLIT) ldsm4(al[mi], sAl + off);
                }
            }
            uint32_t bh[4][4];
            {
                const int nrow = wn + ((lane >> 4) << 3) + (lane & 7);
                const int col  = ks + (((lane >> 3) & 1) << 3);
#pragma unroll
                for (int nb = 0; nb < 4; ++nb) {
                    const uint32_t off = (uint32_t)(nrow + nb * 16) * (ROWH * 2)
                                       + (uint32_t)col * 2;
                    ldsm4(bh[nb], sBh + off);
                }
            }
#pragma unroll
            for (int mi = 0; mi < 4; ++mi)
#pragma unroll
                for (int nf = 0; nf < 8; ++nf)
                    mma16816(acc[mi][nf], ah[mi], &bh[nf >> 1][(nf & 1) << 1]);
            if (A_SPLIT) {
#pragma unroll
                for (int mi = 0; mi < 4; ++mi)
#pragma unroll
                    for (int nf = 0; nf < 8; ++nf)
                        mma16816(acc[mi][nf], al[mi], &bh[nf >> 1][(nf & 1) << 1]);
            }
        }
    }

    // ---- epilogue: each warp writes 64x64 ----
    const long long cbo = (long long)blockIdx.z * sC;
#pragma unroll
    for (int mi = 0; mi < 4; ++mi) {
        const int r0 = m0 + wm + mi * 16 + (lane >> 2);
#pragma unroll
        for (int nf = 0; nf < 8; ++nf) {
            const int col = n0 + wn + nf * 8 + (lane & 3) * 2;
            float b0 = 0.f, b1 = 0.f;
            if (HAS_BIAS) { b0 = __ldg(&bias[col]); b1 = __ldg(&bias[col + 1]); }
            const float v0 = acc[mi][nf][0] * alpha + b0;
            const float v1 = acc[mi][nf][1] * alpha + b1;
            const float v2 = acc[mi][nf][2] * alpha + b0;
            const float v3 = acc[mi][nf][3] * alpha + b1;
            const long long o0 = cbo + (long long)r0 * N + col;
            const long long o1 = o0 + 8LL * N;
            if (OUT_MODE == 0) {
                *reinterpret_cast<float2*>(Cf + o0) = make_float2(v0, v1);
                *reinterpret_cast<float2*>(Cf + o1) = make_float2(v2, v3);
            } else {
                *reinterpret_cast<__half2*>(Chi + o0) =
                    __halves2half2(__float2half_rn(v0), __float2half_rn(v1));
                *reinterpret_cast<__half2*>(Chi + o1) =
                    __halves2half2(__float2half_rn(v2), __float2half_rn(v3));
            }
        }
    }
}

#define SMEM_GEMM3 (3 * (2 * TILE_A + TILE_BB))   // 122880 B (A_SPLIT)
#define SMEM_GEMM2 (3 * (1 * TILE_A + TILE_BB))   // 92160 B (hi-only)

// ---------------------------------------------------------------------------
// fp32 -> fp16 hi/lo split (elementwise)
// ---------------------------------------------------------------------------
__global__ __launch_bounds__(256)
void split_kernel(const float* __restrict__ in,
                  __half* __restrict__ oh, __half* __restrict__ ol, size_t n)
{
    size_t i = ((size_t)blockIdx.x * 256 + threadIdx.x) * 4;
    if (i >= n) return;
    float4 v = *reinterpret_cast<const float4*>(in + i);
    __half h[4], l[4];
    split2h(v.x, h[0], l[0]); split2h(v.y, h[1], l[1]);
    split2h(v.z, h[2], l[2]); split2h(v.w, h[3], l[3]);
    *reinterpret_cast<uint2*>(oh + i) = *reinterpret_cast<const uint2*>(h);
    *reinterpret_cast<uint2*>(ol + i) = *reinterpret_cast<const uint2*>(l);
}

// ---------------------------------------------------------------------------
// fp32 [R,C] -> transposed fp16 hi [C,R] (batched via blockIdx.z)
// ---------------------------------------------------------------------------
__global__ __launch_bounds__(256)
void transpose_h_kernel(const float* __restrict__ in,
                        __half* __restrict__ oh, int R, int C)
{
    __shared__ float t[32][33];
    const size_t bo = (size_t)blockIdx.z * R * C;
    const int c0 = blockIdx.x * 32, r0 = blockIdx.y * 32;
    const int tx = threadIdx.x, ty = threadIdx.y;  // 32 x 8
#pragma unroll
    for (int j = 0; j < 4; ++j)
        t[ty + 8 * j][tx] = in[bo + (size_t)(r0 + ty + 8 * j) * C + c0 + tx];
    __syncthreads();
#pragma unroll
    for (int j = 0; j < 4; ++j) {
        const size_t o = bo + (size_t)(c0 + ty + 8 * j) * R + r0 + tx;
        oh[o] = __float2half_rn(t[tx][ty + 8 * j]);
    }
}

// ---------------------------------------------------------------------------
// Row softmax (2048 cols) -> fp16 output
// ---------------------------------------------------------------------------
__inline__ __device__ float warp_max(float v) {
#pragma unroll
    for (int o = 16; o; o >>= 1) v = fmaxf(v, __shfl_xor_sync(0xFFFFFFFFu, v, o));
    return v;
}
__inline__ __device__ float warp_sum(float v) {
#pragma unroll
    for (int o = 16; o; o >>= 1) v += __shfl_xor_sync(0xFFFFFFFFu, v, o);
    return v;
}

__global__ __launch_bounds__(256)
void softmax_h_kernel(const float* __restrict__ P,
                      __half* __restrict__ oh, int n)
{
    __shared__ float red[8];
    const size_t row = blockIdx.x;
    const float* p = P + row * (size_t)n;
    const int tid  = threadIdx.x;
    const int lane = tid & 31;
    const int warp = tid >> 5;

    float vals[8];
    float m = -INFINITY;
#pragma unroll
    for (int i = 0; i < 8; i++) {
        vals[i] = p[tid + i * 256];
        m = fmaxf(m, vals[i]);
    }
    m = warp_max(m);
    if (lane == 0) red[warp] = m;
    __syncthreads();
    if (warp == 0) {
        float x = (lane < 8) ? red[lane] : -INFINITY;
        x = warp_max(x);
        if (lane == 0) red[0] = x;
    }
    __syncthreads();
    m = red[0];
    __syncthreads();

    float s = 0.f;
#pragma unroll
    for (int i = 0; i < 8; i++) {
        vals[i] = expf(vals[i] - m);
        s += vals[i];
    }
    s = warp_sum(s);
    if (lane == 0) red[warp] = s;
    __syncthreads();
    if (warp == 0) {
        float x = (lane < 8) ? red[lane] : 0.f;
        x = warp_sum(x);
        if (lane == 0) red[0] = x;
    }
    __syncthreads();
    const float inv = 1.f / red[0];

#pragma unroll
    for (int i = 0; i < 8; i++)
        oh[row * (size_t)n + tid + i * 256] = __float2half_rn(vals[i] * inv);
}

// ---------------------------------------------------------------------------
extern "C" void kernel_launch(void* const* d_in, const int* in_sizes, int n_in,
                              void* d_out, int out_size)
{
    const float* query = (const float*)d_in[0];
    const float* key   = (const float*)d_in[1];
    const float* value = (const float*)d_in[2];
    const float* Wq    = (const float*)d_in[3];
    const float* bq    = (const float*)d_in[4];
    const float* Wk    = (const float*)d_in[5];
    const float* bk    = (const float*)d_in[6];
    const float* Wv    = (const float*)d_in[7];
    const float* bv    = (const float*)d_in[8];
    float* out = (float*)d_out;

    __half *qin_hi, *qin_lo, *kin_hi, *kin_lo, *vin_hi, *vin_lo;
    __half *wqt_hi, *wkt_hi, *wvt_hi;
    __half *q_hi, *k_hi, *vt_hi, *p_hi;
    float *v32, *p32;
    cudaGetSymbolAddress((void**)&qin_hi, g_qin_hi); cudaGetSymbolAddress((void**)&qin_lo, g_qin_lo);
    cudaGetSymbolAddress((void**)&kin_hi, g_kin_hi); cudaGetSymbolAddress((void**)&kin_lo, g_kin_lo);
    cudaGetSymbolAddress((void**)&vin_hi, g_vin_hi); cudaGetSymbolAddress((void**)&vin_lo, g_vin_lo);
    cudaGetSymbolAddress((void**)&wqt_hi, g_wqt_hi);
    cudaGetSymbolAddress((void**)&wkt_hi, g_wkt_hi);
    cudaGetSymbolAddress((void**)&wvt_hi, g_wvt_hi);
    cudaGetSymbolAddress((void**)&q_hi, g_q_hi);
    cudaGetSymbolAddress((void**)&k_hi, g_k_hi);
    cudaGetSymbolAddress((void**)&vt_hi, g_vt_hi);
    cudaGetSymbolAddress((void**)&p_hi, g_p_hi);
    cudaGetSymbolAddress((void**)&v32, g_v32);
    cudaGetSymbolAddress((void**)&p32, g_p);

    cudaFuncSetAttribute(hgemm_split<2, true,  true >, cudaFuncAttributeMaxDynamicSharedMemorySize, SMEM_GEMM3);
    cudaFuncSetAttribute(hgemm_split<0, true,  true >, cudaFuncAttributeMaxDynamicSharedMemorySize, SMEM_GEMM3);
    cudaFuncSetAttribute(hgemm_split<0, false, false>, cudaFuncAttributeMaxDynamicSharedMemorySize, SMEM_GEMM2);

    // 1) split fp32 inputs -> fp16 hi/lo (A operands of projections)
    {
        const int blocks = (int)(NBS / (256 * 4));
        split_kernel<<<blocks, 256>>>(query, qin_hi, qin_lo, NBS);
        split_kernel<<<blocks, 256>>>(key,   kin_hi, kin_lo, NBS);
        split_kernel<<<blocks, 256>>>(value, vin_hi, vin_lo, NBS);
    }
    // 2) transpose weights: W[in,out] -> Wt[out,in], hi only (B operands)
    {
        dim3 g(EE / 32, EE / 32, 1), b(32, 8);
        transpose_h_kernel<<<g, b>>>(Wq, wqt_hi, EE, EE);
        transpose_h_kernel<<<g, b>>>(Wk, wkt_hi, EE, EE);
        transpose_h_kernel<<<g, b>>>(Wv, wvt_hi, EE, EE);
    }
    // 3) projections (A split, 2 terms)
    {
        dim3 g(EE / 256, (BB * SS) / 128, 1);
        hgemm_split<2, true, true><<<g, 256, SMEM_GEMM3>>>(
            qin_hi, qin_lo, wqt_hi, bq, nullptr, q_hi,
            BB * SS, EE, EE, 0, 0, 0, 1.0f);
        hgemm_split<2, true, true><<<g, 256, SMEM_GEMM3>>>(
            kin_hi, kin_lo, wkt_hi, bk, nullptr, k_hi,
            BB * SS, EE, EE, 0, 0, 0, 1.0f);
        hgemm_split<0, true, true><<<g, 256, SMEM_GEMM3>>>(
            vin_hi, vin_lo, wvt_hi, bv, v32, nullptr,
            BB * SS, EE, EE, 0, 0, 0, 1.0f);
    }
    // 4) transpose v: [S,E] -> [E,S] per batch (B operand of PV)
    {
        dim3 g(EE / 32, SS / 32, BB), b(32, 8);
        transpose_h_kernel<<<g, b>>>(v32, vt_hi, SS, EE);
    }
    // 5) scores: P = (q @ k^T) / 32, per batch (hi-only, 1 term)
    {
        dim3 g(SS / 256, SS / 128, BB);
        hgemm_split<0, false, false><<<g, 256, SMEM_GEMM2>>>(
            q_hi, nullptr, k_hi, nullptr, p32, nullptr,
            SS, SS, EE,
            (long long)SS * EE, (long long)SS * EE, (long long)SS * SS,
            1.0f / 32.0f);
    }
    // 6) softmax -> fp16
    softmax_h_kernel<<<BB * SS, 256>>>(p32, p_hi, SS);
    // 7) out = P @ vt^T, per batch -> d_out (fp32, hi-only, 1 term)
    {
        dim3 g(EE / 256, SS / 128, BB);
        hgemm_split<0, false, false><<<g, 256, SMEM_GEMM2>>>(
            p_hi, nullptr, vt_hi, nullptr, out, nullptr,
            SS, EE, SS,
            (long long)SS * SS, (long long)SS * EE, (long long)SS * EE,
            1.0f);
    }
}

// round 8
// speedup vs baseline: 5.8551x; 1.4041x over previous
#include <cuda_runtime.h>
#include <cuda_fp16.h>
#include <math.h>
#include <stdint.h>

#define BB 4
#define SS 2048
#define EE 1024

#define NBS ((size_t)BB * SS * EE)   // 8388608
#define NW  ((size_t)EE * EE)        // 1048576
#define NP  ((size_t)BB * SS * SS)   // 16777216

// ---------------------------------------------------------------------------
// Scratch (__device__ globals)
// ---------------------------------------------------------------------------
__device__ __align__(256) __half g_qin[NBS];
__device__ __align__(256) __half g_kin[NBS];
__device__ __align__(256) __half g_vin[NBS];
__device__ __align__(256) __half g_wqt[NW];
__device__ __align__(256) __half g_wkt[NW];
__device__ __align__(256) __half g_wvt[NW];
__device__ __align__(256) __half g_q[NBS];
__device__ __align__(256) __half g_k[NBS];
__device__ __align__(256) __half g_v[NBS];     // [S,E] fp16 per batch
__device__ __align__(256) __half g_vt[NBS];    // [E,S] fp16 per batch
__device__ __align__(256) float  g_p[NP];
__device__ __align__(256) __half g_ph[NP];

// ---------------------------------------------------------------------------
// Baseline-PTX primitives (compute_103-safe)
// ---------------------------------------------------------------------------
__device__ __forceinline__ uint32_t smem_u32(const void* p) {
    uint32_t a;
    asm("{ .reg .u64 t; cvta.to.shared.u64 t, %1; cvt.u32.u64 %0, t; }"
        : "=r"(a) : "l"(p));
    return a;
}

__device__ __forceinline__ void cp_async16(uint32_t s, const void* g) {
    asm volatile("cp.async.cg.shared.global [%0], [%1], 16;" :: "r"(s), "l"(g));
}
__device__ __forceinline__ void cp_commit() {
    asm volatile("cp.async.commit_group;" ::: "memory");
}
__device__ __forceinline__ void cp_wait1() {
    asm volatile("cp.async.wait_group 1;" ::: "memory");
}

__device__ __forceinline__ void ldsm4(uint32_t* r, uint32_t addr) {
    asm volatile("ldmatrix.sync.aligned.m8n8.x4.shared.b16 {%0,%1,%2,%3}, [%4];"
        : "=r"(r[0]), "=r"(r[1]), "=r"(r[2]), "=r"(r[3]) : "r"(addr));
}

__device__ __forceinline__ void mma16816(float* c, const uint32_t* a,
                                         const uint32_t* b) {
    asm volatile(
        "mma.sync.aligned.m16n8k16.row.col.f32.f16.f16.f32 "
        "{%0,%1,%2,%3}, {%4,%5,%6,%7}, {%8,%9}, {%0,%1,%2,%3};"
        : "+f"(c[0]), "+f"(c[1]), "+f"(c[2]), "+f"(c[3])
        : "r"(a[0]), "r"(a[1]), "r"(a[2]), "r"(a[3]), "r"(b[0]), "r"(b[1]));
}

// ---------------------------------------------------------------------------
// HMMA fp16 GEMM:  C[M,N] = alpha*(A @ B^T) (+bias)
//   A[M,K], B[N,K] fp16 K-major.
//   CTA 128x256, BK=64, 8 warps (2x4), warp tile 64x64.
//   3-stage cp.async pipeline, one __syncthreads per K-chunk (16 chunks @ K=1024).
//   OUT_MODE: 0 = fp32, 2 = fp16
// ---------------------------------------------------------------------------
#define ROWH 72                          // 64 + 8 pad halves (144 B pitch)
#define TILE_A (128 * ROWH * 2)          // 18432 B
#define TILE_B2 (256 * ROWH * 2)         // 36864 B
#define STAGE_B (TILE_A + TILE_B2)       // 55296 B
#define SMEM_GEMM (3 * STAGE_B)          // 165888 B

template <int OUT_MODE, bool HAS_BIAS>
__global__ __launch_bounds__(256, 1)
void hgemm(const __half* __restrict__ A, const __half* __restrict__ B,
           const float* __restrict__ bias,
           float* __restrict__ Cf, __half* __restrict__ Ch,
           int M, int N, int K,
           long long sA, long long sB, long long sC,
           float alpha)
{
    extern __shared__ __half sm[];
    const uint32_t sbase = smem_u32(sm);

    const int tid  = threadIdx.x;
    const int lane = tid & 31;
    const int wid  = tid >> 5;
    const int wm   = (wid >> 2) * 64;      // 0,64
    const int wn   = (wid & 3) * 64;       // 0..192

    const int n0 = blockIdx.x * 256;
    const int m0 = blockIdx.y * 128;

    A += (size_t)blockIdx.z * sA;
    B += (size_t)blockIdx.z * sB;

    const int nch = K >> 6;                // BK = 64

    auto issue_stage = [&](int c, int buf) {
        const int kt = c << 6;
        const uint32_t st = (uint32_t)buf * STAGE_B;
        // A: 128 rows x 8 chunks = 1024 chunks, 4/thread
#pragma unroll
        for (int it = 0; it < 4; ++it) {
            const int i = it * 256 + tid;
            const int r  = i >> 3;
            const int cm = i & 7;
            const __half* g = A + (size_t)(m0 + r) * K + kt + cm * 8;
            const uint32_t s = sbase + st + (uint32_t)r * (ROWH * 2)
                             + (uint32_t)cm * 16;
            cp_async16(s, g);
        }
        // B: 256 rows x 8 chunks = 2048 chunks, 8/thread
#pragma unroll
        for (int it = 0; it < 8; ++it) {
            const int i = it * 256 + tid;
            const int r  = i >> 3;
            const int cm = i & 7;
            const __half* g = B + (size_t)(n0 + r) * K + kt + cm * 8;
            const uint32_t s = sbase + st + (uint32_t)TILE_A
                             + (uint32_t)r * (ROWH * 2) + (uint32_t)cm * 16;
            cp_async16(s, g);
        }
        cp_commit();
    };

    float acc[4][8][4];
#pragma unroll
    for (int i = 0; i < 4; ++i)
#pragma unroll
        for (int j = 0; j < 8; ++j)
#pragma unroll
            for (int q = 0; q < 4; ++q) acc[i][j][q] = 0.f;

    issue_stage(0, 0);
    issue_stage(1, 1);

    for (int c = 0; c < nch; ++c) {
        cp_wait1();
        __syncthreads();

        if (c + 2 < nch) issue_stage(c + 2, (c + 2) % 3);
        else             cp_commit();   // keep group counts aligned

        const uint32_t st = (uint32_t)(c % 3) * STAGE_B;
        const uint32_t sA_ = sbase + st;
        const uint32_t sB_ = sA_ + TILE_A;

#pragma unroll
        for (int ks = 0; ks < 64; ks += 16) {
            uint32_t ah[4][4];
            {
                const int row = wm + (lane & 15);
                const int col = ks + ((lane >> 4) << 3);
#pragma unroll
                for (int mi = 0; mi < 4; ++mi)
                    ldsm4(ah[mi], sA_ + (uint32_t)(row + mi * 16) * (ROWH * 2)
                                      + (uint32_t)col * 2);
            }
            uint32_t bh[4][4];
            {
                const int nrow = wn + ((lane >> 4) << 3) + (lane & 7);
                const int col  = ks + (((lane >> 3) & 1) << 3);
#pragma unroll
                for (int nb = 0; nb < 4; ++nb)
                    ldsm4(bh[nb], sB_ + (uint32_t)(nrow + nb * 16) * (ROWH * 2)
                                      + (uint32_t)col * 2);
            }
#pragma unroll
            for (int mi = 0; mi < 4; ++mi)
#pragma unroll
                for (int nf = 0; nf < 8; ++nf)
                    mma16816(acc[mi][nf], ah[mi], &bh[nf >> 1][(nf & 1) << 1]);
        }
    }

    // ---- epilogue: each warp writes 64x64 ----
    const long long cbo = (long long)blockIdx.z * sC;
#pragma unroll
    for (int mi = 0; mi < 4; ++mi) {
        const int r0 = m0 + wm + mi * 16 + (lane >> 2);
#pragma unroll
        for (int nf = 0; nf < 8; ++nf) {
            const int col = n0 + wn + nf * 8 + (lane & 3) * 2;
            float b0 = 0.f, b1 = 0.f;
            if (HAS_BIAS) { b0 = __ldg(&bias[col]); b1 = __ldg(&bias[col + 1]); }
            const float v0 = acc[mi][nf][0] * alpha + b0;
            const float v1 = acc[mi][nf][1] * alpha + b1;
            const float v2 = acc[mi][nf][2] * alpha + b0;
            const float v3 = acc[mi][nf][3] * alpha + b1;
            const long long o0 = cbo + (long long)r0 * N + col;
            const long long o1 = o0 + 8LL * N;
            if (OUT_MODE == 0) {
                *reinterpret_cast<float2*>(Cf + o0) = make_float2(v0, v1);
                *reinterpret_cast<float2*>(Cf + o1) = make_float2(v2, v3);
            } else {
                *reinterpret_cast<__half2*>(Ch + o0) =
                    __halves2half2(__float2half_rn(v0), __float2half_rn(v1));
                *reinterpret_cast<__half2*>(Ch + o1) =
                    __halves2half2(__float2half_rn(v2), __float2half_rn(v3));
            }
        }
    }
}

// ---------------------------------------------------------------------------
// fp32 -> fp16 convert (elementwise)
// ---------------------------------------------------------------------------
__global__ __launch_bounds__(256)
void convert_h_kernel(const float* __restrict__ in, __half* __restrict__ o,
                      size_t n)
{
    size_t i = ((size_t)blockIdx.x * 256 + threadIdx.x) * 4;
    if (i >= n) return;
    float4 v = *reinterpret_cast<const float4*>(in + i);
    __half h[4];
    h[0] = __float2half_rn(v.x); h[1] = __float2half_rn(v.y);
    h[2] = __float2half_rn(v.z); h[3] = __float2half_rn(v.w);
    *reinterpret_cast<uint2*>(o + i) = *reinterpret_cast<const uint2*>(h);
}

// ---------------------------------------------------------------------------
// fp32 [R,C] -> transposed fp16 [C,R] (batched via blockIdx.z)
// ---------------------------------------------------------------------------
__global__ __launch_bounds__(256)
void transpose_f32_h_kernel(const float* __restrict__ in,
                            __half* __restrict__ oh, int R, int C)
{
    __shared__ float t[32][33];
    const size_t bo = (size_t)blockIdx.z * R * C;
    const int c0 = blockIdx.x * 32, r0 = blockIdx.y * 32;
    const int tx = threadIdx.x, ty = threadIdx.y;  // 32 x 8
#pragma unroll
    for (int j = 0; j < 4; ++j)
        t[ty + 8 * j][tx] = in[bo + (size_t)(r0 + ty + 8 * j) * C + c0 + tx];
    __syncthreads();
#pragma unroll
    for (int j = 0; j < 4; ++j) {
        const size_t o = bo + (size_t)(c0 + ty + 8 * j) * R + r0 + tx;
        oh[o] = __float2half_rn(t[tx][ty + 8 * j]);
    }
}

// ---------------------------------------------------------------------------
// fp16 [R,C] -> transposed fp16 [C,R] (batched via blockIdx.z)
// ---------------------------------------------------------------------------
__global__ __launch_bounds__(256)
void transpose_h_h_kernel(const __half* __restrict__ in,
                          __half* __restrict__ oh, int R, int C)
{
    __shared__ __half t[32][34];
    const size_t bo = (size_t)blockIdx.z * R * C;
    const int c0 = blockIdx.x * 32, r0 = blockIdx.y * 32;
    const int tx = threadIdx.x, ty = threadIdx.y;  // 32 x 8
#pragma unroll
    for (int j = 0; j < 4; ++j)
        t[ty + 8 * j][tx] = in[bo + (size_t)(r0 + ty + 8 * j) * C + c0 + tx];
    __syncthreads();
#pragma unroll
    for (int j = 0; j < 4; ++j) {
        const size_t o = bo + (size_t)(c0 + ty + 8 * j) * R + r0 + tx;
        oh[o] = t[tx][ty + 8 * j];
    }
}

// ---------------------------------------------------------------------------
// Row softmax (2048 cols) -> fp16 output
// ---------------------------------------------------------------------------
__inline__ __device__ float warp_max(float v) {
#pragma unroll
    for (int o = 16; o; o >>= 1) v = fmaxf(v, __shfl_xor_sync(0xFFFFFFFFu, v, o));
    return v;
}
__inline__ __device__ float warp_sum(float v) {
#pragma unroll
    for (int o = 16; o; o >>= 1) v += __shfl_xor_sync(0xFFFFFFFFu, v, o);
    return v;
}

__global__ __launch_bounds__(256)
void softmax_h_kernel(const float* __restrict__ P,
                      __half* __restrict__ oh, int n)
{
    __shared__ float red[8];
    const size_t row = blockIdx.x;
    const float* p = P + row * (size_t)n;
    const int tid  = threadIdx.x;
    const int lane = tid & 31;
    const int warp = tid >> 5;

    float vals[8];
    float m = -INFINITY;
#pragma unroll
    for (int i = 0; i < 8; i++) {
        vals[i] = p[tid + i * 256];
        m = fmaxf(m, vals[i]);
    }
    m = warp_max(m);
    if (lane == 0) red[warp] = m;
    __syncthreads();
    if (warp == 0) {
        float x = (lane < 8) ? red[lane] : -INFINITY;
        x = warp_max(x);
        if (lane == 0) red[0] = x;
    }
    __syncthreads();
    m = red[0];
    __syncthreads();

    float s = 0.f;
#pragma unroll
    for (int i = 0; i < 8; i++) {
        vals[i] = expf(vals[i] - m);
        s += vals[i];
    }
    s = warp_sum(s);
    if (lane == 0) red[warp] = s;
    __syncthreads();
    if (warp == 0) {
        float x = (lane < 8) ? red[lane] : 0.f;
        x = warp_sum(x);
        if (lane == 0) red[0] = x;
    }
    __syncthreads();
    const float inv = 1.f / red[0];

#pragma unroll
    for (int i = 0; i < 8; i++)
        oh[row * (size_t)n + tid + i * 256] = __float2half_rn(vals[i] * inv);
}

// ---------------------------------------------------------------------------
extern "C" void kernel_launch(void* const* d_in, const int* in_sizes, int n_in,
                              void* d_out, int out_size)
{
    const float* query = (const float*)d_in[0];
    const float* key   = (const float*)d_in[1];
    const float* value = (const float*)d_in[2];
    const float* Wq    = (const float*)d_in[3];
    const float* bq    = (const float*)d_in[4];
    const float* Wk    = (const float*)d_in[5];
    const float* bk    = (const float*)d_in[6];
    const float* Wv    = (const float*)d_in[7];
    const float* bv    = (const float*)d_in[8];
    float* out = (float*)d_out;

    __half *qin, *kin, *vin, *wqt, *wkt, *wvt, *q, *k, *v, *vt, *ph;
    float *p32;
    cudaGetSymbolAddress((void**)&qin, g_qin);
    cudaGetSymbolAddress((void**)&kin, g_kin);
    cudaGetSymbolAddress((void**)&vin, g_vin);
    cudaGetSymbolAddress((void**)&wqt, g_wqt);
    cudaGetSymbolAddress((void**)&wkt, g_wkt);
    cudaGetSymbolAddress((void**)&wvt, g_wvt);
    cudaGetSymbolAddress((void**)&q,   g_q);
    cudaGetSymbolAddress((void**)&k,   g_k);
    cudaGetSymbolAddress((void**)&v,   g_v);
    cudaGetSymbolAddress((void**)&vt,  g_vt);
    cudaGetSymbolAddress((void**)&ph,  g_ph);
    cudaGetSymbolAddress((void**)&p32, g_p);

    cudaFuncSetAttribute(hgemm<2, true >, cudaFuncAttributeMaxDynamicSharedMemorySize, SMEM_GEMM);
    cudaFuncSetAttribute(hgemm<0, false>, cudaFuncAttributeMaxDynamicSharedMemorySize, SMEM_GEMM);

    // 1) convert fp32 inputs -> fp16
    {
        const int blocks = (int)(NBS / (256 * 4));
        convert_h_kernel<<<blocks, 256>>>(query, qin, NBS);
        convert_h_kernel<<<blocks, 256>>>(key,   kin, NBS);
        convert_h_kernel<<<blocks, 256>>>(value, vin, NBS);
    }
    // 2) transpose weights: W[in,out] -> Wt[out,in] fp16
    {
        dim3 g(EE / 32, EE / 32, 1), b(32, 8);
        transpose_f32_h_kernel<<<g, b>>>(Wq, wqt, EE, EE);
        transpose_f32_h_kernel<<<g, b>>>(Wk, wkt, EE, EE);
        transpose_f32_h_kernel<<<g, b>>>(Wv, wvt, EE, EE);
    }
    // 3) projections -> fp16
    {
        dim3 g(EE / 256, (BB * SS) / 128, 1);
        hgemm<2, true><<<g, 256, SMEM_GEMM>>>(qin, wqt, bq, nullptr, q,
            BB * SS, EE, EE, 0, 0, 0, 1.0f);
        hgemm<2, true><<<g, 256, SMEM_GEMM>>>(kin, wkt, bk, nullptr, k,
            BB * SS, EE, EE, 0, 0, 0, 1.0f);
        hgemm<2, true><<<g, 256, SMEM_GEMM>>>(vin, wvt, bv, nullptr, v,
            BB * SS, EE, EE, 0, 0, 0, 1.0f);
    }
    // 4) transpose v: [S,E] -> [E,S] per batch (fp16 -> fp16)
    {
        dim3 g(EE / 32, SS / 32, BB), b(32, 8);
        transpose_h_h_kernel<<<g, b>>>(v, vt, SS, EE);
    }
    // 5) scores: P = (q @ k^T) / 32, per batch
    {
        dim3 g(SS / 256, SS / 128, BB);
        hgemm<0, false><<<g, 256, SMEM_GEMM>>>(q, k, nullptr, p32, nullptr,
            SS, SS, EE,
            (long long)SS * EE, (long long)SS * EE, (long long)SS * SS,
            1.0f / 32.0f);
    }
    // 6) softmax -> fp16
    softmax_h_kernel<<<BB * SS, 256>>>(p32, ph, SS);
    // 7) out = P @ vt^T, per batch -> d_out (fp32)
    {
        dim3 g(EE / 256, SS / 128, BB);
        hgemm<0, false><<<g, 256, SMEM_GEMM>>>(ph, vt, nullptr, out, nullptr,
            SS, EE, SS,
            (long long)SS * SS, (long long)SS * EE, (long long)SS * EE,
            1.0f);
    }
}

// round 9
// speedup vs baseline: 6.0048x; 1.0256x over previous
#include <cuda_runtime.h>
#include <cuda_fp16.h>
#include <math.h>
#include <stdint.h>

#define BB 4
#define SS 2048
#define EE 1024

#define NBS ((size_t)BB * SS * EE)   // 8388608
#define NW  ((size_t)EE * EE)        // 1048576
#define NP  ((size_t)BB * SS * SS)   // 16777216

// ---------------------------------------------------------------------------
// Scratch (__device__ globals) — contiguous slabs so grid.z can stride
// ---------------------------------------------------------------------------
__device__ __align__(256) __half g_in[3 * NBS];    // fp16 inputs   (q,k,v slabs)
__device__ __align__(256) __half g_wt[3 * NW];     // fp16 W^T      (q,k,v slabs)
__device__ __align__(256) float  g_bias[3 * EE];   // fp32 biases   (q,k,v slabs)
__device__ __align__(256) __half g_qkv[3 * NBS];   // fp16 q,k,v projections
__device__ __align__(256) float  g_p[NP];          // fp32 scores
__device__ __align__(256) __half g_ph[NP];         // fp16 probs

struct Src3 { const float* p0; const float* p1; const float* p2; };

// ---------------------------------------------------------------------------
// Baseline-PTX primitives (compute_103-safe)
// ---------------------------------------------------------------------------
__device__ __forceinline__ uint32_t smem_u32(const void* p) {
    uint32_t a;
    asm("{ .reg .u64 t; cvta.to.shared.u64 t, %1; cvt.u32.u64 %0, t; }"
        : "=r"(a) : "l"(p));
    return a;
}

__device__ __forceinline__ void cp_async16(uint32_t s, const void* g) {
    asm volatile("cp.async.cg.shared.global [%0], [%1], 16;" :: "r"(s), "l"(g));
}
__device__ __forceinline__ void cp_commit() {
    asm volatile("cp.async.commit_group;" ::: "memory");
}
__device__ __forceinline__ void cp_wait1() {
    asm volatile("cp.async.wait_group 1;" ::: "memory");
}

__device__ __forceinline__ void ldsm4(uint32_t* r, uint32_t addr) {
    asm volatile("ldmatrix.sync.aligned.m8n8.x4.shared.b16 {%0,%1,%2,%3}, [%4];"
        : "=r"(r[0]), "=r"(r[1]), "=r"(r[2]), "=r"(r[3]) : "r"(addr));
}
__device__ __forceinline__ void ldsm4t(uint32_t* r, uint32_t addr) {
    asm volatile("ldmatrix.sync.aligned.m8n8.x4.trans.shared.b16 {%0,%1,%2,%3}, [%4];"
        : "=r"(r[0]), "=r"(r[1]), "=r"(r[2]), "=r"(r[3]) : "r"(addr));
}

__device__ __forceinline__ void mma16816(float* c, const uint32_t* a,
                                         const uint32_t* b) {
    asm volatile(
        "mma.sync.aligned.m16n8k16.row.col.f32.f16.f16.f32 "
        "{%0,%1,%2,%3}, {%4,%5,%6,%7}, {%8,%9}, {%0,%1,%2,%3};"
        : "+f"(c[0]), "+f"(c[1]), "+f"(c[2]), "+f"(c[3])
        : "r"(a[0]), "r"(a[1]), "r"(a[2]), "r"(a[3]), "r"(b[0]), "r"(b[1]));
}

// ---------------------------------------------------------------------------
// HMMA fp16 GEMM.
//   TRANS_B = false: C = alpha*(A[M,K] @ B[N,K]^T)+bias  (B K-major)
//   TRANS_B = true : C = alpha*(A[M,K] @ B[K,N])+bias    (B N-major, e.g. V[S,E])
//   CTA 128x256, BK=64, 8 warps (2x4), warp tile 64x64, 3-stage cp.async.
//   OUT_MODE: 0 = fp32, 2 = fp16
// ---------------------------------------------------------------------------
#define ROWH 72                           // K-major pitch: 64 + 8 pad halves
#define TBPITCH 264                       // N-major pitch: 256 + 8 pad halves
#define TILE_A (128 * ROWH * 2)           // 18432 B
#define TILE_BK (256 * ROWH * 2)          // 36864 B (B K-major, 256 rows)
#define TILE_BT (64 * TBPITCH * 2)        // 33792 B (B N-major, 64 k-rows)

template <int OUT_MODE, bool HAS_BIAS, bool TRANS_B>
__global__ __launch_bounds__(256, 1)
void hgemm(const __half* __restrict__ A, const __half* __restrict__ B,
           const float* __restrict__ bias,
           float* __restrict__ Cf, __half* __restrict__ Ch,
           int M, int N, int K,
           long long sA, long long sB, long long sC,
           int biasStride, float alpha)
{
    constexpr int TILE_BSZ = TRANS_B ? TILE_BT : TILE_BK;
    constexpr int STAGE = TILE_A + TILE_BSZ;
    extern __shared__ __half sm[];
    const uint32_t sbase = smem_u32(sm);

    const int tid  = threadIdx.x;
    const int lane = tid & 31;
    const int wid  = tid >> 5;
    const int wm   = (wid >> 2) * 64;      // 0,64
    const int wn   = (wid & 3) * 64;       // 0..192

    const int n0 = blockIdx.x * 256;
    const int m0 = blockIdx.y * 128;

    A += (size_t)blockIdx.z * sA;
    B += (size_t)blockIdx.z * sB;
    if (HAS_BIAS) bias += (size_t)blockIdx.z * biasStride;

    const int nch = K >> 6;                // BK = 64

    auto issue_stage = [&](int c, int buf) {
        const int kt = c << 6;
        const uint32_t st = (uint32_t)buf * STAGE;
        // A: 128 rows x 8 chunks = 1024 chunks, 4/thread
#pragma unroll
        for (int it = 0; it < 4; ++it) {
            const int i = it * 256 + tid;
            const int r  = i >> 3;
            const int cm = i & 7;
            const __half* g = A + (size_t)(m0 + r) * K + kt + cm * 8;
            const uint32_t s = sbase + st + (uint32_t)r * (ROWH * 2)
                             + (uint32_t)cm * 16;
            cp_async16(s, g);
        }
        if (!TRANS_B) {
            // B: 256 n-rows x 8 chunks = 2048 chunks, 8/thread
#pragma unroll
            for (int it = 0; it < 8; ++it) {
                const int i = it * 256 + tid;
                const int r  = i >> 3;
                const int cm = i & 7;
                const __half* g = B + (size_t)(n0 + r) * K + kt + cm * 8;
                const uint32_t s = sbase + st + (uint32_t)TILE_A
                                 + (uint32_t)r * (ROWH * 2) + (uint32_t)cm * 16;
                cp_async16(s, g);
            }
        } else {
            // B: 64 k-rows x 32 chunks = 2048 chunks, 8/thread
#pragma unroll
            for (int it = 0; it < 8; ++it) {
                const int i = it * 256 + tid;
                const int r  = i >> 5;
                const int cm = i & 31;
                const __half* g = B + (size_t)(kt + r) * N + n0 + cm * 8;
                const uint32_t s = sbase + st + (uint32_t)TILE_A
                                 + (uint32_t)r * (TBPITCH * 2) + (uint32_t)cm * 16;
                cp_async16(s, g);
            }
        }
        cp_commit();
    };

    float acc[4][8][4];
#pragma unroll
    for (int i = 0; i < 4; ++i)
#pragma unroll
        for (int j = 0; j < 8; ++j)
#pragma unroll
            for (int q = 0; q < 4; ++q) acc[i][j][q] = 0.f;

    issue_stage(0, 0);
    issue_stage(1, 1);

    for (int c = 0; c < nch; ++c) {
        cp_wait1();
        __syncthreads();

        if (c + 2 < nch) issue_stage(c + 2, (c + 2) % 3);
        else             cp_commit();   // keep group counts aligned

        const uint32_t st = (uint32_t)(c % 3) * STAGE;
        const uint32_t sA_ = sbase + st;
        const uint32_t sB_ = sA_ + TILE_A;

#pragma unroll
        for (int ks = 0; ks < 64; ks += 16) {
            uint32_t ah[4][4];
            {
                const int row = wm + (lane & 15);
                const int col = ks + ((lane >> 4) << 3);
#pragma unroll
                for (int mi = 0; mi < 4; ++mi)
                    ldsm4(ah[mi], sA_ + (uint32_t)(row + mi * 16) * (ROWH * 2)
                                      + (uint32_t)col * 2);
            }
            uint32_t bh[4][4];
            if (!TRANS_B) {
                const int nrow = wn + ((lane >> 4) << 3) + (lane & 7);
                const int col  = ks + (((lane >> 3) & 1) << 3);
#pragma unroll
                for (int nb = 0; nb < 4; ++nb)
                    ldsm4(bh[nb], sB_ + (uint32_t)(nrow + nb * 16) * (ROWH * 2)
                                      + (uint32_t)col * 2);
            } else {
                // B smem tile is [k][n]; ldsm.trans yields b[n][k] fragments.
                const int srow = ks + (((lane >> 3) & 1) << 3) + (lane & 7);
                const int ecol = ((lane >> 4) << 3);
#pragma unroll
                for (int nb = 0; nb < 4; ++nb)
                    ldsm4t(bh[nb], sB_ + (uint32_t)srow * (TBPITCH * 2)
                                       + (uint32_t)(wn + nb * 16 + ecol) * 2);
            }
#pragma unroll
            for (int mi = 0; mi < 4; ++mi)
#pragma unroll
                for (int nf = 0; nf < 8; ++nf)
                    mma16816(acc[mi][nf], ah[mi], &bh[nf >> 1][(nf & 1) << 1]);
        }
    }

    // ---- epilogue: each warp writes 64x64 ----
    const long long cbo = (long long)blockIdx.z * sC;
#pragma unroll
    for (int mi = 0; mi < 4; ++mi) {
        const int r0 = m0 + wm + mi * 16 + (lane >> 2);
#pragma unroll
        for (int nf = 0; nf < 8; ++nf) {
            const int col = n0 + wn + nf * 8 + (lane & 3) * 2;
            float b0 = 0.f, b1 = 0.f;
            if (HAS_BIAS) { b0 = __ldg(&bias[col]); b1 = __ldg(&bias[col + 1]); }
            const float v0 = acc[mi][nf][0] * alpha + b0;
            const float v1 = acc[mi][nf][1] * alpha + b1;
            const float v2 = acc[mi][nf][2] * alpha + b0;
            const float v3 = acc[mi][nf][3] * alpha + b1;
            const long long o0 = cbo + (long long)r0 * N + col;
            const long long o1 = o0 + 8LL * N;
            if (OUT_MODE == 0) {
                *reinterpret_cast<float2*>(Cf + o0) = make_float2(v0, v1);
                *reinterpret_cast<float2*>(Cf + o1) = make_float2(v2, v3);
            } else {
                *reinterpret_cast<__half2*>(Ch + o0) =
                    __halves2half2(__float2half_rn(v0), __float2half_rn(v1));
                *reinterpret_cast<__half2*>(Ch + o1) =
                    __halves2half2(__float2half_rn(v2), __float2half_rn(v3));
            }
        }
    }
}

#define SMEM_GEMM_K (3 * (TILE_A + TILE_BK))   // 165888 B
#define SMEM_GEMM_T (3 * (TILE_A + TILE_BT))   // 156672 B

// ---------------------------------------------------------------------------
// fp32 -> fp16 convert, 3 tensors in one launch (grid.z)
// ---------------------------------------------------------------------------
__global__ __launch_bounds__(256)
void convert3_kernel(Src3 src, __half* __restrict__ dst, size_t n)
{
    const float* in = (blockIdx.z == 0) ? src.p0 : (blockIdx.z == 1) ? src.p1 : src.p2;
    __half* o = dst + (size_t)blockIdx.z * n;
    size_t i = ((size_t)blockIdx.x * 256 + threadIdx.x) * 4;
    if (i >= n) return;
    float4 v = *reinterpret_cast<const float4*>(in + i);
    __half h[4];
    h[0] = __float2half_rn(v.x); h[1] = __float2half_rn(v.y);
    h[2] = __float2half_rn(v.z); h[3] = __float2half_rn(v.w);
    *reinterpret_cast<uint2*>(o + i) = *reinterpret_cast<const uint2*>(h);
}

// ---------------------------------------------------------------------------
// fp32 W[in,out] -> fp16 W^T[out,in], 3 weights in one launch (grid.z)
// ---------------------------------------------------------------------------
__global__ __launch_bounds__(256)
void transpose3_kernel(Src3 src, __half* __restrict__ dst, int R, int C)
{
    __shared__ float t[32][33];
    const float* in = (blockIdx.z == 0) ? src.p0 : (blockIdx.z == 1) ? src.p1 : src.p2;
    __half* oh = dst + (size_t)blockIdx.z * R * C;
    const int c0 = blockIdx.x * 32, r0 = blockIdx.y * 32;
    const int tx = threadIdx.x, ty = threadIdx.y;  // 32 x 8
#pragma unroll
    for (int j = 0; j < 4; ++j)
        t[ty + 8 * j][tx] = in[(size_t)(r0 + ty + 8 * j) * C + c0 + tx];
    __syncthreads();
#pragma unroll
    for (int j = 0; j < 4; ++j) {
        const size_t o = (size_t)(c0 + ty + 8 * j) * R + r0 + tx;
        oh[o] = __float2half_rn(t[tx][ty + 8 * j]);
    }
}

// ---------------------------------------------------------------------------
// Row softmax (2048 cols) -> fp16 output
// ---------------------------------------------------------------------------
__inline__ __device__ float warp_max(float v) {
#pragma unroll
    for (int o = 16; o; o >>= 1) v = fmaxf(v, __shfl_xor_sync(0xFFFFFFFFu, v, o));
    return v;
}
__inline__ __device__ float warp_sum(float v) {
#pragma unroll
    for (int o = 16; o; o >>= 1) v += __shfl_xor_sync(0xFFFFFFFFu, v, o);
    return v;
}

__global__ __launch_bounds__(256)
void softmax_h_kernel(const float* __restrict__ P,
                      __half* __restrict__ oh, int n)
{
    __shared__ float red[8];
    const size_t row = blockIdx.x;
    const float* p = P + row * (size_t)n;
    const int tid  = threadIdx.x;
    const int lane = tid & 31;
    const int warp = tid >> 5;

    float vals[8];
    float m = -INFINITY;
#pragma unroll
    for (int i = 0; i < 8; i++) {
        vals[i] = p[tid + i * 256];
        m = fmaxf(m, vals[i]);
    }
    m = warp_max(m);
    if (lane == 0) red[warp] = m;
    __syncthreads();
    if (warp == 0) {
        float x = (lane < 8) ? red[lane] : -INFINITY;
        x = warp_max(x);
        if (lane == 0) red[0] = x;
    }
    __syncthreads();
    m = red[0];
    __syncthreads();

    float s = 0.f;
#pragma unroll
    for (int i = 0; i < 8; i++) {
        vals[i] = expf(vals[i] - m);
        s += vals[i];
    }
    s = warp_sum(s);
    if (lane == 0) red[warp] = s;
    __syncthreads();
    if (warp == 0) {
        float x = (lane < 8) ? red[lane] : 0.f;
        x = warp_sum(x);
        if (lane == 0) red[0] = x;
    }
    __syncthreads();
    const float inv = 1.f / red[0];

#pragma unroll
    for (int i = 0; i < 8; i++)
        oh[row * (size_t)n + tid + i * 256] = __float2half_rn(vals[i] * inv);
}

// ---------------------------------------------------------------------------
extern "C" void kernel_launch(void* const* d_in, const int* in_sizes, int n_in,
                              void* d_out, int out_size)
{
    const float* query = (const float*)d_in[0];
    const float* key   = (const float*)d_in[1];
    const float* value = (const float*)d_in[2];
    const float* Wq    = (const float*)d_in[3];
    const float* bq    = (const float*)d_in[4];
    const float* Wk    = (const float*)d_in[5];
    const float* bk    = (const float*)d_in[6];
    const float* Wv    = (const float*)d_in[7];
    const float* bv    = (const float*)d_in[8];
    float* out = (float*)d_out;

    __half *in16, *wt16, *qkv, *ph;
    float *bias3, *p32;
    cudaGetSymbolAddress((void**)&in16,  g_in);
    cudaGetSymbolAddress((void**)&wt16,  g_wt);
    cudaGetSymbolAddress((void**)&bias3, g_bias);
    cudaGetSymbolAddress((void**)&qkv,   g_qkv);
    cudaGetSymbolAddress((void**)&ph,    g_ph);
    cudaGetSymbolAddress((void**)&p32,   g_p);

    cudaFuncSetAttribute(hgemm<2, true,  false>, cudaFuncAttributeMaxDynamicSharedMemorySize, SMEM_GEMM_K);
    cudaFuncSetAttribute(hgemm<0, false, false>, cudaFuncAttributeMaxDynamicSharedMemorySize, SMEM_GEMM_K);
    cudaFuncSetAttribute(hgemm<0, false, true >, cudaFuncAttributeMaxDynamicSharedMemorySize, SMEM_GEMM_T);

    // 0) biases -> contiguous slab (D2D async copies are graph-capturable)
    cudaMemcpyAsync(bias3 + 0 * EE, bq, EE * sizeof(float), cudaMemcpyDeviceToDevice);
    cudaMemcpyAsync(bias3 + 1 * EE, bk, EE * sizeof(float), cudaMemcpyDeviceToDevice);
    cudaMemcpyAsync(bias3 + 2 * EE, bv, EE * sizeof(float), cudaMemcpyDeviceToDevice);

    // 1) convert fp32 inputs -> fp16 slabs (one launch)
    {
        Src3 s{query, key, value};
        dim3 g((unsigned)(NBS / (256 * 4)), 1, 3);
        convert3_kernel<<<g, 256>>>(s, in16, NBS);
    }
    // 2) transpose weights -> fp16 W^T slabs (one launch)
    {
        Src3 s{Wq, Wk, Wv};
        dim3 g(EE / 32, EE / 32, 3), b(32, 8);
        transpose3_kernel<<<g, b>>>(s, wt16, EE, EE);
    }
    // 3) q,k,v projections in ONE launch (z strides over slabs)
    {
        dim3 g(EE / 256, (BB * SS) / 128, 3);
        hgemm<2, true, false><<<g, 256, SMEM_GEMM_K>>>(
            in16, wt16, bias3, nullptr, qkv,
            BB * SS, EE, EE,
            (long long)NBS, (long long)NW, (long long)NBS,
            EE, 1.0f);
    }
    // 4) scores: P = (q @ k^T) / 32, per batch
    {
        dim3 g(SS / 256, SS / 128, BB);
        hgemm<0, false, false><<<g, 256, SMEM_GEMM_K>>>(
            qkv /*q slab*/, qkv + NBS /*k slab*/, nullptr, p32, nullptr,
            SS, SS, EE,
            (long long)SS * EE, (long long)SS * EE, (long long)SS * SS,
            0, 1.0f / 32.0f);
    }
    // 5) softmax -> fp16
    softmax_h_kernel<<<BB * SS, 256>>>(p32, ph, SS);
    // 6) out = P @ V (V row-major via TRANS_B), per batch -> d_out (fp32)
    {
        dim3 g(EE / 256, SS / 128, BB);
        hgemm<0, false, true><<<g, 256, SMEM_GEMM_T>>>(
            ph, qkv + 2 * NBS /*v slab [S,E]*/, nullptr, out, nullptr,
            SS, EE, SS,
            (long long)SS * SS, (long long)SS * EE, (long long)SS * EE,
            0, 1.0f);
    }
}

// round 10
// speedup vs baseline: 6.5457x; 1.0901x over previous
#include <cuda_runtime.h>
#include <cuda_fp16.h>
#include <math.h>
#include <stdint.h>

#define BB 4
#define SS 2048
#define EE 1024

#define NBS ((size_t)BB * SS * EE)   // 8388608
#define NW  ((size_t)EE * EE)        // 1048576
#define NP  ((size_t)BB * SS * SS)   // 16777216

// ---------------------------------------------------------------------------
// Scratch (__device__ globals) — contiguous slabs so grid.z can stride
// ---------------------------------------------------------------------------
__device__ __align__(256) __half g_in[3 * NBS];    // fp16 inputs   (q,k,v slabs)
__device__ __align__(256) __half g_wt[3 * NW];     // fp16 W^T      (q,k,v slabs)
__device__ __align__(256) float  g_bias[3 * EE];   // fp32 biases   (q,k,v slabs)
__device__ __align__(256) __half g_qkv[3 * NBS];   // fp16 q,k,v projections
__device__ __align__(256) float  g_p[NP];          // fp32 scores
__device__ __align__(256) __half g_ph[NP];         // fp16 probs

struct Src3 { const float* p0; const float* p1; const float* p2; };

// ---------------------------------------------------------------------------
// Baseline-PTX primitives (compute_103-safe)
// ---------------------------------------------------------------------------
__device__ __forceinline__ uint32_t smem_u32(const void* p) {
    uint32_t a;
    asm("{ .reg .u64 t; cvta.to.shared.u64 t, %1; cvt.u32.u64 %0, t; }"
        : "=r"(a) : "l"(p));
    return a;
}

__device__ __forceinline__ void cp_async16(uint32_t s, const void* g) {
    asm volatile("cp.async.cg.shared.global [%0], [%1], 16;" :: "r"(s), "l"(g));
}
__device__ __forceinline__ void cp_commit() {
    asm volatile("cp.async.commit_group;" ::: "memory");
}
__device__ __forceinline__ void cp_wait1() {
    asm volatile("cp.async.wait_group 1;" ::: "memory");
}

__device__ __forceinline__ void ldsm4(uint32_t* r, uint32_t addr) {
    asm volatile("ldmatrix.sync.aligned.m8n8.x4.shared.b16 {%0,%1,%2,%3}, [%4];"
        : "=r"(r[0]), "=r"(r[1]), "=r"(r[2]), "=r"(r[3]) : "r"(addr));
}
__device__ __forceinline__ void ldsm4t(uint32_t* r, uint32_t addr) {
    asm volatile("ldmatrix.sync.aligned.m8n8.x4.trans.shared.b16 {%0,%1,%2,%3}, [%4];"
        : "=r"(r[0]), "=r"(r[1]), "=r"(r[2]), "=r"(r[3]) : "r"(addr));
}

__device__ __forceinline__ void mma16816(float* c, const uint32_t* a,
                                         const uint32_t* b) {
    asm volatile(
        "mma.sync.aligned.m16n8k16.row.col.f32.f16.f16.f32 "
        "{%0,%1,%2,%3}, {%4,%5,%6,%7}, {%8,%9}, {%0,%1,%2,%3};"
        : "+f"(c[0]), "+f"(c[1]), "+f"(c[2]), "+f"(c[3])
        : "r"(a[0]), "r"(a[1]), "r"(a[2]), "r"(a[3]), "r"(b[0]), "r"(b[1]));
}

// ---------------------------------------------------------------------------
// HMMA fp16 GEMM, 2 CTAs/SM.
//   TRANS_B = false: C = alpha*(A[M,K] @ B[N,K]^T)+bias  (B K-major)
//   TRANS_B = true : C = alpha*(A[M,K] @ B[K,N])+bias    (B N-major, e.g. V[S,E])
//   CTA 128x128, BK=64, 8 warps (2x4), warp tile 64x32, 3-stage cp.async.
//   OUT_MODE: 0 = fp32, 2 = fp16
// ---------------------------------------------------------------------------
#define ROWH 72                           // K-major pitch: 64 + 8 pad halves
#define TBPITCH 136                       // N-major pitch: 128 + 8 pad halves
#define TILE_A (128 * ROWH * 2)           // 18432 B
#define TILE_BK (128 * ROWH * 2)          // 18432 B
#define TILE_BT (64 * TBPITCH * 2)        // 17408 B

template <int OUT_MODE, bool HAS_BIAS, bool TRANS_B>
__global__ __launch_bounds__(256, 2)
void hgemm(const __half* __restrict__ A, const __half* __restrict__ B,
           const float* __restrict__ bias,
           float* __restrict__ Cf, __half* __restrict__ Ch,
           int M, int N, int K,
           long long sA, long long sB, long long sC,
           int biasStride, float alpha)
{
    constexpr int TILE_BSZ = TRANS_B ? TILE_BT : TILE_BK;
    constexpr int STAGE = TILE_A + TILE_BSZ;
    extern __shared__ __half sm[];
    const uint32_t sbase = smem_u32(sm);

    const int tid  = threadIdx.x;
    const int lane = tid & 31;
    const int wid  = tid >> 5;
    const int wm   = (wid >> 2) * 64;      // 0,64
    const int wn   = (wid & 3) * 32;       // 0..96

    const int n0 = blockIdx.x * 128;
    const int m0 = blockIdx.y * 128;

    A += (size_t)blockIdx.z * sA;
    B += (size_t)blockIdx.z * sB;
    if (HAS_BIAS) bias += (size_t)blockIdx.z * biasStride;

    const int nch = K >> 6;                // BK = 64

    auto issue_stage = [&](int c, int buf) {
        const int kt = c << 6;
        const uint32_t st = (uint32_t)buf * STAGE;
        // A: 128 rows x 8 chunks = 1024 chunks, 4/thread
#pragma unroll
        for (int it = 0; it < 4; ++it) {
            const int i = it * 256 + tid;
            const int r  = i >> 3;
            const int cm = i & 7;
            const __half* g = A + (size_t)(m0 + r) * K + kt + cm * 8;
            const uint32_t s = sbase + st + (uint32_t)r * (ROWH * 2)
                             + (uint32_t)cm * 16;
            cp_async16(s, g);
        }
        if (!TRANS_B) {
            // B: 128 n-rows x 8 chunks = 1024 chunks, 4/thread
#pragma unroll
            for (int it = 0; it < 4; ++it) {
                const int i = it * 256 + tid;
                const int r  = i >> 3;
                const int cm = i & 7;
                const __half* g = B + (size_t)(n0 + r) * K + kt + cm * 8;
                const uint32_t s = sbase + st + (uint32_t)TILE_A
                                 + (uint32_t)r * (ROWH * 2) + (uint32_t)cm * 16;
                cp_async16(s, g);
            }
        } else {
            // B: 64 k-rows x 16 chunks = 1024 chunks, 4/thread
#pragma unroll
            for (int it = 0; it < 4; ++it) {
                const int i = it * 256 + tid;
                const int r  = i >> 4;
                const int cm = i & 15;
                const __half* g = B + (size_t)(kt + r) * N + n0 + cm * 8;
                const uint32_t s = sbase + st + (uint32_t)TILE_A
                                 + (uint32_t)r * (TBPITCH * 2) + (uint32_t)cm * 16;
                cp_async16(s, g);
            }
        }
        cp_commit();
    };

    float acc[4][4][4];
#pragma unroll
    for (int i = 0; i < 4; ++i)
#pragma unroll
        for (int j = 0; j < 4; ++j)
#pragma unroll
            for (int q = 0; q < 4; ++q) acc[i][j][q] = 0.f;

    issue_stage(0, 0);
    issue_stage(1, 1);

    for (int c = 0; c < nch; ++c) {
        cp_wait1();
        __syncthreads();

        if (c + 2 < nch) issue_stage(c + 2, (c + 2) % 3);
        else             cp_commit();   // keep group counts aligned

        const uint32_t st = (uint32_t)(c % 3) * STAGE;
        const uint32_t sA_ = sbase + st;
        const uint32_t sB_ = sA_ + TILE_A;

#pragma unroll
        for (int ks = 0; ks < 64; ks += 16) {
            uint32_t ah[4][4];
            {
                const int row = wm + (lane & 15);
                const int col = ks + ((lane >> 4) << 3);
#pragma unroll
                for (int mi = 0; mi < 4; ++mi)
                    ldsm4(ah[mi], sA_ + (uint32_t)(row + mi * 16) * (ROWH * 2)
                                      + (uint32_t)col * 2);
            }
            uint32_t bh[2][4];
            if (!TRANS_B) {
                const int nrow = wn + ((lane >> 4) << 3) + (lane & 7);
                const int col  = ks + (((lane >> 3) & 1) << 3);
#pragma unroll
                for (int nb = 0; nb < 2; ++nb)
                    ldsm4(bh[nb], sB_ + (uint32_t)(nrow + nb * 16) * (ROWH * 2)
                                      + (uint32_t)col * 2);
            } else {
                // B smem tile is [k][n]; ldsm.trans yields b[n][k] fragments.
                const int srow = ks + (((lane >> 3) & 1) << 3) + (lane & 7);
                const int ecol = ((lane >> 4) << 3);
#pragma unroll
                for (int nb = 0; nb < 2; ++nb)
                    ldsm4t(bh[nb], sB_ + (uint32_t)srow * (TBPITCH * 2)
                                       + (uint32_t)(wn + nb * 16 + ecol) * 2);
            }
#pragma unroll
            for (int mi = 0; mi < 4; ++mi)
#pragma unroll
                for (int nf = 0; nf < 4; ++nf)
                    mma16816(acc[mi][nf], ah[mi], &bh[nf >> 1][(nf & 1) << 1]);
        }
    }

    // ---- epilogue: each warp writes 64x32 ----
    const long long cbo = (long long)blockIdx.z * sC;
#pragma unroll
    for (int mi = 0; mi < 4; ++mi) {
        const int r0 = m0 + wm + mi * 16 + (lane >> 2);
#pragma unroll
        for (int nf = 0; nf < 4; ++nf) {
            const int col = n0 + wn + nf * 8 + (lane & 3) * 2;
            float b0 = 0.f, b1 = 0.f;
            if (HAS_BIAS) { b0 = __ldg(&bias[col]); b1 = __ldg(&bias[col + 1]); }
            const float v0 = acc[mi][nf][0] * alpha + b0;
            const float v1 = acc[mi][nf][1] * alpha + b1;
            const float v2 = acc[mi][nf][2] * alpha + b0;
            const float v3 = acc[mi][nf][3] * alpha + b1;
            const long long o0 = cbo + (long long)r0 * N + col;
            const long long o1 = o0 + 8LL * N;
            if (OUT_MODE == 0) {
                *reinterpret_cast<float2*>(Cf + o0) = make_float2(v0, v1);
                *reinterpret_cast<float2*>(Cf + o1) = make_float2(v2, v3);
            } else {
                *reinterpret_cast<__half2*>(Ch + o0) =
                    __halves2half2(__float2half_rn(v0), __float2half_rn(v1));
                *reinterpret_cast<__half2*>(Ch + o1) =
                    __halves2half2(__float2half_rn(v2), __float2half_rn(v3));
            }
        }
    }
}

#define SMEM_GEMM_K (3 * (TILE_A + TILE_BK))   // 110592 B
#define SMEM_GEMM_T (3 * (TILE_A + TILE_BT))   // 107520 B

// ---------------------------------------------------------------------------
// fp32 -> fp16 convert, 3 tensors in one launch (grid.z)
// ---------------------------------------------------------------------------
__global__ __launch_bounds__(256)
void convert3_kernel(Src3 src, __half* __restrict__ dst, size_t n)
{
    const float* in = (blockIdx.z == 0) ? src.p0 : (blockIdx.z == 1) ? src.p1 : src.p2;
    __half* o = dst + (size_t)blockIdx.z * n;
    size_t i = ((size_t)blockIdx.x * 256 + threadIdx.x) * 4;
    if (i >= n) return;
    float4 v = *reinterpret_cast<const float4*>(in + i);
    __half h[4];
    h[0] = __float2half_rn(v.x); h[1] = __float2half_rn(v.y);
    h[2] = __float2half_rn(v.z); h[3] = __float2half_rn(v.w);
    *reinterpret_cast<uint2*>(o + i) = *reinterpret_cast<const uint2*>(h);
}

// ---------------------------------------------------------------------------
// fp32 W[in,out] -> fp16 W^T[out,in], 3 weights in one launch (grid.z)
// ---------------------------------------------------------------------------
__global__ __launch_bounds__(256)
void transpose3_kernel(Src3 src, __half* __restrict__ dst, int R, int C)
{
    __shared__ float t[32][33];
    const float* in = (blockIdx.z == 0) ? src.p0 : (blockIdx.z == 1) ? src.p1 : src.p2;
    __half* oh = dst + (size_t)blockIdx.z * R * C;
    const int c0 = blockIdx.x * 32, r0 = blockIdx.y * 32;
    const int tx = threadIdx.x, ty = threadIdx.y;  // 32 x 8
#pragma unroll
    for (int j = 0; j < 4; ++j)
        t[ty + 8 * j][tx] = in[(size_t)(r0 + ty + 8 * j) * C + c0 + tx];
    __syncthreads();
#pragma unroll
    for (int j = 0; j < 4; ++j) {
        const size_t o = (size_t)(c0 + ty + 8 * j) * R + r0 + tx;
        oh[o] = __float2half_rn(t[tx][ty + 8 * j]);
    }
}

// ---------------------------------------------------------------------------
// Row softmax (2048 cols) -> fp16 output
// ---------------------------------------------------------------------------
__inline__ __device__ float warp_max(float v) {
#pragma unroll
    for (int o = 16; o; o >>= 1) v = fmaxf(v, __shfl_xor_sync(0xFFFFFFFFu, v, o));
    return v;
}
__inline__ __device__ float warp_sum(float v) {
#pragma unroll
    for (int o = 16; o; o >>= 1) v += __shfl_xor_sync(0xFFFFFFFFu, v, o);
    return v;
}

__global__ __launch_bounds__(256)
void softmax_h_kernel(const float* __restrict__ P,
                      __half* __restrict__ oh, int n)
{
    __shared__ float red[8];
    const size_t row = blockIdx.x;
    const float* p = P + row * (size_t)n;
    const int tid  = threadIdx.x;
    const int lane = tid & 31;
    const int warp = tid >> 5;

    float vals[8];
    float m = -INFINITY;
#pragma unroll
    for (int i = 0; i < 8; i++) {
        vals[i] = p[tid + i * 256];
        m = fmaxf(m, vals[i]);
    }
    m = warp_max(m);
    if (lane == 0) red[warp] = m;
    __syncthreads();
    if (warp == 0) {
        float x = (lane < 8) ? red[lane] : -INFINITY;
        x = warp_max(x);
        if (lane == 0) red[0] = x;
    }
    __syncthreads();
    m = red[0];
    __syncthreads();

    float s = 0.f;
#pragma unroll
    for (int i = 0; i < 8; i++) {
        vals[i] = expf(vals[i] - m);
        s += vals[i];
    }
    s = warp_sum(s);
    if (lane == 0) red[warp] = s;
    __syncthreads();
    if (warp == 0) {
        float x = (lane < 8) ? red[lane] : 0.f;
        x = warp_sum(x);
        if (lane == 0) red[0] = x;
    }
    __syncthreads();
    const float inv = 1.f / red[0];

#pragma unroll
    for (int i = 0; i < 8; i++)
        oh[row * (size_t)n + tid + i * 256] = __float2half_rn(vals[i] * inv);
}

// ---------------------------------------------------------------------------
extern "C" void kernel_launch(void* const* d_in, const int* in_sizes, int n_in,
                              void* d_out, int out_size)
{
    const float* query = (const float*)d_in[0];
    const float* key   = (const float*)d_in[1];
    const float* value = (const float*)d_in[2];
    const float* Wq    = (const float*)d_in[3];
    const float* bq    = (const float*)d_in[4];
    const float* Wk    = (const float*)d_in[5];
    const float* bk    = (const float*)d_in[6];
    const float* Wv    = (const float*)d_in[7];
    const float* bv    = (const float*)d_in[8];
    float* out = (float*)d_out;

    __half *in16, *wt16, *qkv, *ph;
    float *bias3, *p32;
    cudaGetSymbolAddress((void**)&in16,  g_in);
    cudaGetSymbolAddress((void**)&wt16,  g_wt);
    cudaGetSymbolAddress((void**)&bias3, g_bias);
    cudaGetSymbolAddress((void**)&qkv,   g_qkv);
    cudaGetSymbolAddress((void**)&ph,    g_ph);
    cudaGetSymbolAddress((void**)&p32,   g_p);

    cudaFuncSetAttribute(hgemm<2, true,  false>, cudaFuncAttributeMaxDynamicSharedMemorySize, SMEM_GEMM_K);
    cudaFuncSetAttribute(hgemm<0, false, false>, cudaFuncAttributeMaxDynamicSharedMemorySize, SMEM_GEMM_K);
    cudaFuncSetAttribute(hgemm<0, false, true >, cudaFuncAttributeMaxDynamicSharedMemorySize, SMEM_GEMM_T);

    // 0) biases -> contiguous slab (D2D async copies are graph-capturable)
    cudaMemcpyAsync(bias3 + 0 * EE, bq, EE * sizeof(float), cudaMemcpyDeviceToDevice);
    cudaMemcpyAsync(bias3 + 1 * EE, bk, EE * sizeof(float), cudaMemcpyDeviceToDevice);
    cudaMemcpyAsync(bias3 + 2 * EE, bv, EE * sizeof(float), cudaMemcpyDeviceToDevice);

    // 1) convert fp32 inputs -> fp16 slabs (one launch)
    {
        Src3 s{query, key, value};
        dim3 g((unsigned)(NBS / (256 * 4)), 1, 3);
        convert3_kernel<<<g, 256>>>(s, in16, NBS);
    }
    // 2) transpose weights -> fp16 W^T slabs (one launch)
    {
        Src3 s{Wq, Wk, Wv};
        dim3 g(EE / 32, EE / 32, 3), b(32, 8);
        transpose3_kernel<<<g, b>>>(s, wt16, EE, EE);
    }
    // 3) q,k,v projections in ONE launch (z strides over slabs)
    {
        dim3 g(EE / 128, (BB * SS) / 128, 3);
        hgemm<2, true, false><<<g, 256, SMEM_GEMM_K>>>(
            in16, wt16, bias3, nullptr, qkv,
            BB * SS, EE, EE,
            (long long)NBS, (long long)NW, (long long)NBS,
            EE, 1.0f);
    }
    // 4) scores: P = (q @ k^T) / 32, per batch
    {
        dim3 g(SS / 128, SS / 128, BB);
        hgemm<0, false, false><<<g, 256, SMEM_GEMM_K>>>(
            qkv /*q slab*/, qkv + NBS /*k slab*/, nullptr, p32, nullptr,
            SS, SS, EE,
            (long long)SS * EE, (long long)SS * EE, (long long)SS * SS,
            0, 1.0f / 32.0f);
    }
    // 5) softmax -> fp16
    softmax_h_kernel<<<BB * SS, 256>>>(p32, ph, SS);
    // 6) out = P @ V (V row-major via TRANS_B), per batch -> d_out (fp32)
    {
        dim3 g(EE / 128, SS / 128, BB);
        hgemm<0, false, true><<<g, 256, SMEM_GEMM_T>>>(
            ph, qkv + 2 * NBS /*v slab [S,E]*/, nullptr, out, nullptr,
            SS, EE, SS,
            (long long)SS * SS, (long long)SS * EE, (long long)SS * EE,
            0, 1.0f);
    }
}

// round 11
// speedup vs baseline: 6.5952x; 1.0076x over previous
#include <cuda_runtime.h>
#include <cuda_fp16.h>
#include <math.h>
#include <stdint.h>

#define BB 4
#define SS 2048
#define EE 1024

#define NBS ((size_t)BB * SS * EE)   // 8388608
#define NW  ((size_t)EE * EE)        // 1048576
#define NP  ((size_t)BB * SS * SS)   // 16777216

// ---------------------------------------------------------------------------
// Scratch (__device__ globals) — contiguous slabs so grid.z can stride
// ---------------------------------------------------------------------------
__device__ __align__(256) __half g_in[3 * NBS];    // fp16 inputs   (q,k,v slabs)
__device__ __align__(256) __half g_wt[3 * NW];     // fp16 W^T      (q,k,v slabs)
__device__ __align__(256) float  g_bias[3 * EE];   // fp32 biases   (q,k,v slabs)
__device__ __align__(256) __half g_qkv[3 * NBS];   // fp16 q,k,v projections
__device__ __align__(256) __half g_ph[NP];         // fp16 scores -> probs (in-place)

struct Src3 { const float* p0; const float* p1; const float* p2; };

// ---------------------------------------------------------------------------
// Baseline-PTX primitives (compute_103-safe)
// ---------------------------------------------------------------------------
__device__ __forceinline__ uint32_t smem_u32(const void* p) {
    uint32_t a;
    asm("{ .reg .u64 t; cvta.to.shared.u64 t, %1; cvt.u32.u64 %0, t; }"
        : "=r"(a) : "l"(p));
    return a;
}

__device__ __forceinline__ void cp_async16(uint32_t s, const void* g) {
    asm volatile("cp.async.cg.shared.global [%0], [%1], 16;" :: "r"(s), "l"(g));
}
__device__ __forceinline__ void cp_commit() {
    asm volatile("cp.async.commit_group;" ::: "memory");
}
__device__ __forceinline__ void cp_wait1() {
    asm volatile("cp.async.wait_group 1;" ::: "memory");
}

__device__ __forceinline__ void ldsm4(uint32_t* r, uint32_t addr) {
    asm volatile("ldmatrix.sync.aligned.m8n8.x4.shared.b16 {%0,%1,%2,%3}, [%4];"
        : "=r"(r[0]), "=r"(r[1]), "=r"(r[2]), "=r"(r[3]) : "r"(addr));
}
__device__ __forceinline__ void ldsm4t(uint32_t* r, uint32_t addr) {
    asm volatile("ldmatrix.sync.aligned.m8n8.x4.trans.shared.b16 {%0,%1,%2,%3}, [%4];"
        : "=r"(r[0]), "=r"(r[1]), "=r"(r[2]), "=r"(r[3]) : "r"(addr));
}

__device__ __forceinline__ void mma16816(float* c, const uint32_t* a,
                                         const uint32_t* b) {
    asm volatile(
        "mma.sync.aligned.m16n8k16.row.col.f32.f16.f16.f32 "
        "{%0,%1,%2,%3}, {%4,%5,%6,%7}, {%8,%9}, {%0,%1,%2,%3};"
        : "+f"(c[0]), "+f"(c[1]), "+f"(c[2]), "+f"(c[3])
        : "r"(a[0]), "r"(a[1]), "r"(a[2]), "r"(a[3]), "r"(b[0]), "r"(b[1]));
}

// ---------------------------------------------------------------------------
// HMMA fp16 GEMM, 2 CTAs/SM.
//   TRANS_B = false: C = alpha*(A[M,K] @ B[N,K]^T)+bias  (B K-major)
//   TRANS_B = true : C = alpha*(A[M,K] @ B[K,N])+bias    (B N-major, e.g. V[S,E])
//   CTA 128x128, BK=64, 8 warps (2x4), warp tile 64x32, 3-stage cp.async.
//   OUT_MODE: 0 = fp32, 2 = fp16
// ---------------------------------------------------------------------------
#define ROWH 72                           // K-major pitch: 64 + 8 pad halves
#define TBPITCH 136                       // N-major pitch: 128 + 8 pad halves
#define TILE_A (128 * ROWH * 2)           // 18432 B
#define TILE_BK (128 * ROWH * 2)          // 18432 B
#define TILE_BT (64 * TBPITCH * 2)        // 17408 B

template <int OUT_MODE, bool HAS_BIAS, bool TRANS_B>
__global__ __launch_bounds__(256, 2)
void hgemm(const __half* __restrict__ A, const __half* __restrict__ B,
           const float* __restrict__ bias,
           float* __restrict__ Cf, __half* __restrict__ Ch,
           int M, int N, int K,
           long long sA, long long sB, long long sC,
           int biasStride, float alpha)
{
    constexpr int TILE_BSZ = TRANS_B ? TILE_BT : TILE_BK;
    constexpr int STAGE = TILE_A + TILE_BSZ;
    extern __shared__ __half sm[];
    const uint32_t sbase = smem_u32(sm);

    const int tid  = threadIdx.x;
    const int lane = tid & 31;
    const int wid  = tid >> 5;
    const int wm   = (wid >> 2) * 64;      // 0,64
    const int wn   = (wid & 3) * 32;       // 0..96

    const int n0 = blockIdx.x * 128;
    const int m0 = blockIdx.y * 128;

    A += (size_t)blockIdx.z * sA;
    B += (size_t)blockIdx.z * sB;
    if (HAS_BIAS) bias += (size_t)blockIdx.z * biasStride;

    const int nch = K >> 6;                // BK = 64

    auto issue_stage = [&](int c, int buf) {
        const int kt = c << 6;
        const uint32_t st = (uint32_t)buf * STAGE;
        // A: 128 rows x 8 chunks = 1024 chunks, 4/thread
#pragma unroll
        for (int it = 0; it < 4; ++it) {
            const int i = it * 256 + tid;
            const int r  = i >> 3;
            const int cm = i & 7;
            const __half* g = A + (size_t)(m0 + r) * K + kt + cm * 8;
            const uint32_t s = sbase + st + (uint32_t)r * (ROWH * 2)
                             + (uint32_t)cm * 16;
            cp_async16(s, g);
        }
        if (!TRANS_B) {
            // B: 128 n-rows x 8 chunks = 1024 chunks, 4/thread
#pragma unroll
            for (int it = 0; it < 4; ++it) {
                const int i = it * 256 + tid;
                const int r  = i >> 3;
                const int cm = i & 7;
                const __half* g = B + (size_t)(n0 + r) * K + kt + cm * 8;
                const uint32_t s = sbase + st + (uint32_t)TILE_A
                                 + (uint32_t)r * (ROWH * 2) + (uint32_t)cm * 16;
                cp_async16(s, g);
            }
        } else {
            // B: 64 k-rows x 16 chunks = 1024 chunks, 4/thread
#pragma unroll
            for (int it = 0; it < 4; ++it) {
                const int i = it * 256 + tid;
                const int r  = i >> 4;
                const int cm = i & 15;
                const __half* g = B + (size_t)(kt + r) * N + n0 + cm * 8;
                const uint32_t s = sbase + st + (uint32_t)TILE_A
                                 + (uint32_t)r * (TBPITCH * 2) + (uint32_t)cm * 16;
                cp_async16(s, g);
            }
        }
        cp_commit();
    };

    float acc[4][4][4];
#pragma unroll
    for (int i = 0; i < 4; ++i)
#pragma unroll
        for (int j = 0; j < 4; ++j)
#pragma unroll
            for (int q = 0; q < 4; ++q) acc[i][j][q] = 0.f;

    issue_stage(0, 0);
    issue_stage(1, 1);

    for (int c = 0; c < nch; ++c) {
        cp_wait1();
        __syncthreads();

        if (c + 2 < nch) issue_stage(c + 2, (c + 2) % 3);
        else             cp_commit();   // keep group counts aligned

        const uint32_t st = (uint32_t)(c % 3) * STAGE;
        const uint32_t sA_ = sbase + st;
        const uint32_t sB_ = sA_ + TILE_A;

#pragma unroll
        for (int ks = 0; ks < 64; ks += 16) {
            uint32_t ah[4][4];
            {
                const int row = wm + (lane & 15);
                const int col = ks + ((lane >> 4) << 3);
#pragma unroll
                for (int mi = 0; mi < 4; ++mi)
                    ldsm4(ah[mi], sA_ + (uint32_t)(row + mi * 16) * (ROWH * 2)
                                      + (uint32_t)col * 2);
            }
            uint32_t bh[2][4];
            if (!TRANS_B) {
                const int nrow = wn + ((lane >> 4) << 3) + (lane & 7);
                const int col  = ks + (((lane >> 3) & 1) << 3);
#pragma unroll
                for (int nb = 0; nb < 2; ++nb)
                    ldsm4(bh[nb], sB_ + (uint32_t)(nrow + nb * 16) * (ROWH * 2)
                                      + (uint32_t)col * 2);
            } else {
                // B smem tile is [k][n]; ldsm.trans yields b[n][k] fragments.
                const int srow = ks + (((lane >> 3) & 1) << 3) + (lane & 7);
                const int ecol = ((lane >> 4) << 3);
#pragma unroll
                for (int nb = 0; nb < 2; ++nb)
                    ldsm4t(bh[nb], sB_ + (uint32_t)srow * (TBPITCH * 2)
                                       + (uint32_t)(wn + nb * 16 + ecol) * 2);
            }
#pragma unroll
            for (int mi = 0; mi < 4; ++mi)
#pragma unroll
                for (int nf = 0; nf < 4; ++nf)
                    mma16816(acc[mi][nf], ah[mi], &bh[nf >> 1][(nf & 1) << 1]);
        }
    }

    // ---- epilogue: each warp writes 64x32 ----
    const long long cbo = (long long)blockIdx.z * sC;
#pragma unroll
    for (int mi = 0; mi < 4; ++mi) {
        const int r0 = m0 + wm + mi * 16 + (lane >> 2);
#pragma unroll
        for (int nf = 0; nf < 4; ++nf) {
            const int col = n0 + wn + nf * 8 + (lane & 3) * 2;
            float b0 = 0.f, b1 = 0.f;
            if (HAS_BIAS) { b0 = __ldg(&bias[col]); b1 = __ldg(&bias[col + 1]); }
            const float v0 = acc[mi][nf][0] * alpha + b0;
            const float v1 = acc[mi][nf][1] * alpha + b1;
            const float v2 = acc[mi][nf][2] * alpha + b0;
            const float v3 = acc[mi][nf][3] * alpha + b1;
            const long long o0 = cbo + (long long)r0 * N + col;
            const long long o1 = o0 + 8LL * N;
            if (OUT_MODE == 0) {
                *reinterpret_cast<float2*>(Cf + o0) = make_float2(v0, v1);
                *reinterpret_cast<float2*>(Cf + o1) = make_float2(v2, v3);
            } else {
                *reinterpret_cast<__half2*>(Ch + o0) =
                    __halves2half2(__float2half_rn(v0), __float2half_rn(v1));
                *reinterpret_cast<__half2*>(Ch + o1) =
                    __halves2half2(__float2half_rn(v2), __float2half_rn(v3));
            }
        }
    }
}

#define SMEM_GEMM_K (3 * (TILE_A + TILE_BK))   // 110592 B
#define SMEM_GEMM_T (3 * (TILE_A + TILE_BT))   // 107520 B

// ---------------------------------------------------------------------------
// fp32 -> fp16 convert, 3 tensors in one launch (grid.z)
// ---------------------------------------------------------------------------
__global__ __launch_bounds__(256)
void convert3_kernel(Src3 src, __half* __restrict__ dst, size_t n)
{
    const float* in = (blockIdx.z == 0) ? src.p0 : (blockIdx.z == 1) ? src.p1 : src.p2;
    __half* o = dst + (size_t)blockIdx.z * n;
    size_t i = ((size_t)blockIdx.x * 256 + threadIdx.x) * 4;
    if (i >= n) return;
    float4 v = *reinterpret_cast<const float4*>(in + i);
    __half h[4];
    h[0] = __float2half_rn(v.x); h[1] = __float2half_rn(v.y);
    h[2] = __float2half_rn(v.z); h[3] = __float2half_rn(v.w);
    *reinterpret_cast<uint2*>(o + i) = *reinterpret_cast<const uint2*>(h);
}

// ---------------------------------------------------------------------------
// fp32 W[in,out] -> fp16 W^T[out,in], 3 weights in one launch (grid.z)
// ---------------------------------------------------------------------------
__global__ __launch_bounds__(256)
void transpose3_kernel(Src3 src, __half* __restrict__ dst, int R, int C)
{
    __shared__ float t[32][33];
    const float* in = (blockIdx.z == 0) ? src.p0 : (blockIdx.z == 1) ? src.p1 : src.p2;
    __half* oh = dst + (size_t)blockIdx.z * R * C;
    const int c0 = blockIdx.x * 32, r0 = blockIdx.y * 32;
    const int tx = threadIdx.x, ty = threadIdx.y;  // 32 x 8
#pragma unroll
    for (int j = 0; j < 4; ++j)
        t[ty + 8 * j][tx] = in[(size_t)(r0 + ty + 8 * j) * C + c0 + tx];
    __syncthreads();
#pragma unroll
    for (int j = 0; j < 4; ++j) {
        const size_t o = (size_t)(c0 + ty + 8 * j) * R + r0 + tx;
        oh[o] = __float2half_rn(t[tx][ty + 8 * j]);
    }
}

// ---------------------------------------------------------------------------
// In-place row softmax on fp16 (2048 cols), fp32 math, half2 vectorized
// ---------------------------------------------------------------------------
__inline__ __device__ float warp_max(float v) {
#pragma unroll
    for (int o = 16; o; o >>= 1) v = fmaxf(v, __shfl_xor_sync(0xFFFFFFFFu, v, o));
    return v;
}
__inline__ __device__ float warp_sum(float v) {
#pragma unroll
    for (int o = 16; o; o >>= 1) v += __shfl_xor_sync(0xFFFFFFFFu, v, o);
    return v;
}

__global__ __launch_bounds__(256)
void softmax_h_inplace_kernel(__half* __restrict__ P, int n)
{
    __shared__ float red[8];
    const size_t row = blockIdx.x;
    __half2* p2 = reinterpret_cast<__half2*>(P + row * (size_t)n);
    const int tid  = threadIdx.x;
    const int lane = tid & 31;
    const int warp = tid >> 5;

    // 1024 half2 per row, 4 per thread
    float2 vals[4];
    float m = -INFINITY;
#pragma unroll
    for (int i = 0; i < 4; i++) {
        vals[i] = __half22float2(p2[tid + i * 256]);
        m = fmaxf(m, fmaxf(vals[i].x, vals[i].y));
    }
    m = warp_max(m);
    if (lane == 0) red[warp] = m;
    __syncthreads();
    if (warp == 0) {
        float x = (lane < 8) ? red[lane] : -INFINITY;
        x = warp_max(x);
        if (lane == 0) red[0] = x;
    }
    __syncthreads();
    m = red[0];
    __syncthreads();

    float s = 0.f;
#pragma unroll
    for (int i = 0; i < 4; i++) {
        vals[i].x = expf(vals[i].x - m);
        vals[i].y = expf(vals[i].y - m);
        s += vals[i].x + vals[i].y;
    }
    s = warp_sum(s);
    if (lane == 0) red[warp] = s;
    __syncthreads();
    if (warp == 0) {
        float x = (lane < 8) ? red[lane] : 0.f;
        x = warp_sum(x);
        if (lane == 0) red[0] = x;
    }
    __syncthreads();
    const float inv = 1.f / red[0];

#pragma unroll
    for (int i = 0; i < 4; i++) {
        float2 o = make_float2(vals[i].x * inv, vals[i].y * inv);
        p2[tid + i * 256] = __float22half2_rn(o);
    }
}

// ---------------------------------------------------------------------------
extern "C" void kernel_launch(void* const* d_in, const int* in_sizes, int n_in,
                              void* d_out, int out_size)
{
    const float* query = (const float*)d_in[0];
    const float* key   = (const float*)d_in[1];
    const float* value = (const float*)d_in[2];
    const float* Wq    = (const float*)d_in[3];
    const float* bq    = (const float*)d_in[4];
    const float* Wk    = (const float*)d_in[5];
    const float* bk    = (const float*)d_in[6];
    const float* Wv    = (const float*)d_in[7];
    const float* bv    = (const float*)d_in[8];
    float* out = (float*)d_out;

    __half *in16, *wt16, *qkv, *ph;
    float *bias3;
    cudaGetSymbolAddress((void**)&in16,  g_in);
    cudaGetSymbolAddress((void**)&wt16,  g_wt);
    cudaGetSymbolAddress((void**)&bias3, g_bias);
    cudaGetSymbolAddress((void**)&qkv,   g_qkv);
    cudaGetSymbolAddress((void**)&ph,    g_ph);

    cudaFuncSetAttribute(hgemm<2, true,  false>, cudaFuncAttributeMaxDynamicSharedMemorySize, SMEM_GEMM_K);
    cudaFuncSetAttribute(hgemm<2, false, false>, cudaFuncAttributeMaxDynamicSharedMemorySize, SMEM_GEMM_K);
    cudaFuncSetAttribute(hgemm<0, false, true >, cudaFuncAttributeMaxDynamicSharedMemorySize, SMEM_GEMM_T);

    // 0) biases -> contiguous slab (D2D async copies are graph-capturable)
    cudaMemcpyAsync(bias3 + 0 * EE, bq, EE * sizeof(float), cudaMemcpyDeviceToDevice);
    cudaMemcpyAsync(bias3 + 1 * EE, bk, EE * sizeof(float), cudaMemcpyDeviceToDevice);
    cudaMemcpyAsync(bias3 + 2 * EE, bv, EE * sizeof(float), cudaMemcpyDeviceToDevice);

    // 1) convert fp32 inputs -> fp16 slabs (one launch)
    {
        Src3 s{query, key, value};
        dim3 g((unsigned)(NBS / (256 * 4)), 1, 3);
        convert3_kernel<<<g, 256>>>(s, in16, NBS);
    }
    // 2) transpose weights -> fp16 W^T slabs (one launch)
    {
        Src3 s{Wq, Wk, Wv};
        dim3 g(EE / 32, EE / 32, 3), b(32, 8);
        transpose3_kernel<<<g, b>>>(s, wt16, EE, EE);
    }
    // 3) q,k,v projections in ONE launch (z strides over slabs)
    {
        dim3 g(EE / 128, (BB * SS) / 128, 3);
        hgemm<2, true, false><<<g, 256, SMEM_GEMM_K>>>(
            in16, wt16, bias3, nullptr, qkv,
            BB * SS, EE, EE,
            (long long)NBS, (long long)NW, (long long)NBS,
            EE, 1.0f);
    }
    // 4) scores: S = (q @ k^T) / 32, per batch -> fp16 g_ph
    {
        dim3 g(SS / 128, SS / 128, BB);
        hgemm<2, false, false><<<g, 256, SMEM_GEMM_K>>>(
            qkv /*q slab*/, qkv + NBS /*k slab*/, nullptr, nullptr, ph,
            SS, SS, EE,
            (long long)SS * EE, (long long)SS * EE, (long long)SS * SS,
            0, 1.0f / 32.0f);
    }
    // 5) softmax in-place on fp16
    softmax_h_inplace_kernel<<<BB * SS, 256>>>(ph, SS);
    // 6) out = P @ V (V row-major via TRANS_B), per batch -> d_out (fp32)
    {
        dim3 g(EE / 128, SS / 128, BB);
        hgemm<0, false, true><<<g, 256, SMEM_GEMM_T>>>(
            ph, qkv + 2 * NBS /*v slab [S,E]*/, nullptr, out, nullptr,
            SS, EE, SS,
            (long long)SS * SS, (long long)SS * EE, (long long)SS * EE,
            0, 1.0f);
    }
}

// round 12
// speedup vs baseline: 6.6782x; 1.0126x over previous
#include <cuda_runtime.h>
#include <cuda_fp16.h>
#include <math.h>
#include <stdint.h>

#define BB 4
#define SS 2048
#define EE 1024

#define NBS ((size_t)BB * SS * EE)   // 8388608
#define NW  ((size_t)EE * EE)        // 1048576
#define NP  ((size_t)BB * SS * SS)   // 16777216

// ---------------------------------------------------------------------------
// Scratch (__device__ globals) — contiguous slabs so grid.z can stride
// ---------------------------------------------------------------------------
__device__ __align__(256) __half g_in[3 * NBS];    // fp16 inputs   (q,k,v slabs)
__device__ __align__(256) __half g_wt[3 * NW];     // fp16 W^T      (q,k,v slabs)
__device__ __align__(256) float  g_bias[3 * EE];   // fp32 biases   (q,k,v slabs)
__device__ __align__(256) __half g_qkv[3 * NBS];   // fp16 q,k,v projections
__device__ __align__(256) __half g_ph[NP];         // fp16 scores -> probs (in-place)

struct Src3 { const float* p0; const float* p1; const float* p2; };

// ---------------------------------------------------------------------------
// Baseline-PTX primitives (compute_103-safe)
// ---------------------------------------------------------------------------
__device__ __forceinline__ uint32_t smem_u32(const void* p) {
    uint32_t a;
    asm("{ .reg .u64 t; cvta.to.shared.u64 t, %1; cvt.u32.u64 %0, t; }"
        : "=r"(a) : "l"(p));
    return a;
}

__device__ __forceinline__ void cp_async16(uint32_t s, const void* g) {
    asm volatile("cp.async.cg.shared.global [%0], [%1], 16;" :: "r"(s), "l"(g));
}
__device__ __forceinline__ void cp_commit() {
    asm volatile("cp.async.commit_group;" ::: "memory");
}
__device__ __forceinline__ void cp_wait1() {
    asm volatile("cp.async.wait_group 1;" ::: "memory");
}

__device__ __forceinline__ void ldsm4(uint32_t* r, uint32_t addr) {
    asm volatile("ldmatrix.sync.aligned.m8n8.x4.shared.b16 {%0,%1,%2,%3}, [%4];"
        : "=r"(r[0]), "=r"(r[1]), "=r"(r[2]), "=r"(r[3]) : "r"(addr));
}
__device__ __forceinline__ void ldsm4t(uint32_t* r, uint32_t addr) {
    asm volatile("ldmatrix.sync.aligned.m8n8.x4.trans.shared.b16 {%0,%1,%2,%3}, [%4];"
        : "=r"(r[0]), "=r"(r[1]), "=r"(r[2]), "=r"(r[3]) : "r"(addr));
}

__device__ __forceinline__ void mma16816(float* c, const uint32_t* a,
                                         const uint32_t* b) {
    asm volatile(
        "mma.sync.aligned.m16n8k16.row.col.f32.f16.f16.f32 "
        "{%0,%1,%2,%3}, {%4,%5,%6,%7}, {%8,%9}, {%0,%1,%2,%3};"
        : "+f"(c[0]), "+f"(c[1]), "+f"(c[2]), "+f"(c[3])
        : "r"(a[0]), "r"(a[1]), "r"(a[2]), "r"(a[3]), "r"(b[0]), "r"(b[1]));
}

// ---------------------------------------------------------------------------
// HMMA fp16 GEMM, 2 CTAs/SM, fragment-double-buffered inner loop.
//   TRANS_B = false: C = alpha*(A[M,K] @ B[N,K]^T)+bias  (B K-major)
//   TRANS_B = true : C = alpha*(A[M,K] @ B[K,N])+bias    (B N-major, e.g. V[S,E])
//   CTA 128x128, BK=64, 8 warps (2x4), warp tile 64x32, 3-stage cp.async.
//   OUT_MODE: 0 = fp32, 2 = fp16
// ---------------------------------------------------------------------------
#define ROWH 72                           // K-major pitch: 64 + 8 pad halves
#define TBPITCH 136                       // N-major pitch: 128 + 8 pad halves
#define TILE_A (128 * ROWH * 2)           // 18432 B
#define TILE_BK (128 * ROWH * 2)          // 18432 B
#define TILE_BT (64 * TBPITCH * 2)        // 17408 B

template <int OUT_MODE, bool HAS_BIAS, bool TRANS_B>
__global__ __launch_bounds__(256, 2)
void hgemm(const __half* __restrict__ A, const __half* __restrict__ B,
           const float* __restrict__ bias,
           float* __restrict__ Cf, __half* __restrict__ Ch,
           int M, int N, int K,
           long long sA, long long sB, long long sC,
           int biasStride, float alpha)
{
    constexpr int TILE_BSZ = TRANS_B ? TILE_BT : TILE_BK;
    constexpr int STAGE = TILE_A + TILE_BSZ;
    extern __shared__ __half sm[];
    const uint32_t sbase = smem_u32(sm);

    const int tid  = threadIdx.x;
    const int lane = tid & 31;
    const int wid  = tid >> 5;
    const int wm   = (wid >> 2) * 64;      // 0,64
    const int wn   = (wid & 3) * 32;       // 0..96

    const int n0 = blockIdx.x * 128;
    const int m0 = blockIdx.y * 128;

    A += (size_t)blockIdx.z * sA;
    B += (size_t)blockIdx.z * sB;
    if (HAS_BIAS) bias += (size_t)blockIdx.z * biasStride;

    const int nch = K >> 6;                // BK = 64

    auto issue_stage = [&](int c, int buf) {
        const int kt = c << 6;
        const uint32_t st = (uint32_t)buf * STAGE;
        // A: 128 rows x 8 chunks = 1024 chunks, 4/thread
#pragma unroll
        for (int it = 0; it < 4; ++it) {
            const int i = it * 256 + tid;
            const int r  = i >> 3;
            const int cm = i & 7;
            const __half* g = A + (size_t)(m0 + r) * K + kt + cm * 8;
            const uint32_t s = sbase + st + (uint32_t)r * (ROWH * 2)
                             + (uint32_t)cm * 16;
            cp_async16(s, g);
        }
        if (!TRANS_B) {
            // B: 128 n-rows x 8 chunks = 1024 chunks, 4/thread
#pragma unroll
            for (int it = 0; it < 4; ++it) {
                const int i = it * 256 + tid;
                const int r  = i >> 3;
                const int cm = i & 7;
                const __half* g = B + (size_t)(n0 + r) * K + kt + cm * 8;
                const uint32_t s = sbase + st + (uint32_t)TILE_A
                                 + (uint32_t)r * (ROWH * 2) + (uint32_t)cm * 16;
                cp_async16(s, g);
            }
        } else {
            // B: 64 k-rows x 16 chunks = 1024 chunks, 4/thread
#pragma unroll
            for (int it = 0; it < 4; ++it) {
                const int i = it * 256 + tid;
                const int r  = i >> 4;
                const int cm = i & 15;
                const __half* g = B + (size_t)(kt + r) * N + n0 + cm * 8;
                const uint32_t s = sbase + st + (uint32_t)TILE_A
                                 + (uint32_t)r * (TBPITCH * 2) + (uint32_t)cm * 16;
                cp_async16(s, g);
            }
        }
        cp_commit();
    };

    float acc[4][4][4];
#pragma unroll
    for (int i = 0; i < 4; ++i)
#pragma unroll
        for (int j = 0; j < 4; ++j)
#pragma unroll
            for (int q = 0; q < 4; ++q) acc[i][j][q] = 0.f;

    issue_stage(0, 0);
    issue_stage(1, 1);

    // fragment double buffers
    uint32_t ah[2][4][4];
    uint32_t bh[2][2][4];

    for (int c = 0; c < nch; ++c) {
        cp_wait1();
        __syncthreads();

        if (c + 2 < nch) issue_stage(c + 2, (c + 2) % 3);
        else             cp_commit();   // keep group counts aligned

        const uint32_t st = (uint32_t)(c % 3) * STAGE;
        const uint32_t sA_ = sbase + st;
        const uint32_t sB_ = sA_ + TILE_A;

        // per-thread invariant address components
        const uint32_t aAddr = sA_ + (uint32_t)(wm + (lane & 15)) * (ROWH * 2)
                             + (uint32_t)((lane >> 4) << 3) * 2;
        uint32_t bAddrK = 0, bAddrT = 0;
        if (!TRANS_B)
            bAddrK = sB_ + (uint32_t)(wn + ((lane >> 4) << 3) + (lane & 7)) * (ROWH * 2)
                   + (uint32_t)(((lane >> 3) & 1) << 3) * 2;
        else
            bAddrT = sB_ + (uint32_t)((((lane >> 3) & 1) << 3) + (lane & 7)) * (TBPITCH * 2)
                   + (uint32_t)(wn + ((lane >> 4) << 3)) * 2;

        auto load_a = [&](int buf, int ks) {
#pragma unroll
            for (int mi = 0; mi < 4; ++mi)
                ldsm4(ah[buf][mi], aAddr + (uint32_t)(mi * 16) * (ROWH * 2)
                                         + (uint32_t)ks * 2);
        };
        auto load_b = [&](int buf, int ks) {
            if (!TRANS_B) {
#pragma unroll
                for (int nb = 0; nb < 2; ++nb)
                    ldsm4(bh[buf][nb], bAddrK + (uint32_t)(nb * 16) * (ROWH * 2)
                                              + (uint32_t)ks * 2);
            } else {
#pragma unroll
                for (int nb = 0; nb < 2; ++nb)
                    ldsm4t(bh[buf][nb], bAddrT + (uint32_t)ks * (TBPITCH * 2)
                                               + (uint32_t)(nb * 16) * 2);
            }
        };

        load_a(0, 0);
        load_b(0, 0);

#pragma unroll
        for (int s = 0; s < 4; ++s) {
            const int cur = s & 1;
            const int nxt = cur ^ 1;
            if (s < 3) {                // prefetch next ks-step's fragments
                load_a(nxt, (s + 1) * 16);
                load_b(nxt, (s + 1) * 16);
            }
#pragma unroll
            for (int mi = 0; mi < 4; ++mi)
#pragma unroll
                for (int nf = 0; nf < 4; ++nf)
                    mma16816(acc[mi][nf], ah[cur][mi],
                             &bh[cur][nf >> 1][(nf & 1) << 1]);
        }
    }

    // ---- epilogue: each warp writes 64x32 ----
    const long long cbo = (long long)blockIdx.z * sC;
#pragma unroll
    for (int mi = 0; mi < 4; ++mi) {
        const int r0 = m0 + wm + mi * 16 + (lane >> 2);
#pragma unroll
        for (int nf = 0; nf < 4; ++nf) {
            const int col = n0 + wn + nf * 8 + (lane & 3) * 2;
            float b0 = 0.f, b1 = 0.f;
            if (HAS_BIAS) { b0 = __ldg(&bias[col]); b1 = __ldg(&bias[col + 1]); }
            const float v0 = acc[mi][nf][0] * alpha + b0;
            const float v1 = acc[mi][nf][1] * alpha + b1;
            const float v2 = acc[mi][nf][2] * alpha + b0;
            const float v3 = acc[mi][nf][3] * alpha + b1;
            const long long o0 = cbo + (long long)r0 * N + col;
            const long long o1 = o0 + 8LL * N;
            if (OUT_MODE == 0) {
                *reinterpret_cast<float2*>(Cf + o0) = make_float2(v0, v1);
                *reinterpret_cast<float2*>(Cf + o1) = make_float2(v2, v3);
            } else {
                *reinterpret_cast<__half2*>(Ch + o0) =
                    __halves2half2(__float2half_rn(v0), __float2half_rn(v1));
                *reinterpret_cast<__half2*>(Ch + o1) =
                    __halves2half2(__float2half_rn(v2), __float2half_rn(v3));
            }
        }
    }
}

#define SMEM_GEMM_K (3 * (TILE_A + TILE_BK))   // 110592 B
#define SMEM_GEMM_T (3 * (TILE_A + TILE_BT))   // 107520 B

// ---------------------------------------------------------------------------
// fp32 -> fp16 convert, 3 tensors in one launch (grid.z)
// ---------------------------------------------------------------------------
__global__ __launch_bounds__(256)
void convert3_kernel(Src3 src, __half* __restrict__ dst, size_t n)
{
    const float* in = (blockIdx.z == 0) ? src.p0 : (blockIdx.z == 1) ? src.p1 : src.p2;
    __half* o = dst + (size_t)blockIdx.z * n;
    size_t i = ((size_t)blockIdx.x * 256 + threadIdx.x) * 4;
    if (i >= n) return;
    float4 v = *reinterpret_cast<const float4*>(in + i);
    __half h[4];
    h[0] = __float2half_rn(v.x); h[1] = __float2half_rn(v.y);
    h[2] = __float2half_rn(v.z); h[3] = __float2half_rn(v.w);
    *reinterpret_cast<uint2*>(o + i) = *reinterpret_cast<const uint2*>(h);
}

// ---------------------------------------------------------------------------
// fp32 W[in,out] -> fp16 W^T[out,in], 3 weights in one launch (grid.z)
// ---------------------------------------------------------------------------
__global__ __launch_bounds__(256)
void transpose3_kernel(Src3 src, __half* __restrict__ dst, int R, int C)
{
    __shared__ float t[32][33];
    const float* in = (blockIdx.z == 0) ? src.p0 : (blockIdx.z == 1) ? src.p1 : src.p2;
    __half* oh = dst + (size_t)blockIdx.z * R * C;
    const int c0 = blockIdx.x * 32, r0 = blockIdx.y * 32;
    const int tx = threadIdx.x, ty = threadIdx.y;  // 32 x 8
#pragma unroll
    for (int j = 0; j < 4; ++j)
        t[ty + 8 * j][tx] = in[(size_t)(r0 + ty + 8 * j) * C + c0 + tx];
    __syncthreads();
#pragma unroll
    for (int j = 0; j < 4; ++j) {
        const size_t o = (size_t)(c0 + ty + 8 * j) * R + r0 + tx;
        oh[o] = __float2half_rn(t[tx][ty + 8 * j]);
    }
}

// ---------------------------------------------------------------------------
// In-place row softmax on fp16 (2048 cols), fp32 math, half2 vectorized
// ---------------------------------------------------------------------------
__inline__ __device__ float warp_max(float v) {
#pragma unroll
    for (int o = 16; o; o >>= 1) v = fmaxf(v, __shfl_xor_sync(0xFFFFFFFFu, v, o));
    return v;
}
__inline__ __device__ float warp_sum(float v) {
#pragma unroll
    for (int o = 16; o; o >>= 1) v += __shfl_xor_sync(0xFFFFFFFFu, v, o);
    return v;
}

__global__ __launch_bounds__(256)
void softmax_h_inplace_kernel(__half* __restrict__ P, int n)
{
    __shared__ float red[8];
    const size_t row = blockIdx.x;
    __half2* p2 = reinterpret_cast<__half2*>(P + row * (size_t)n);
    const int tid  = threadIdx.x;
    const int lane = tid & 31;
    const int warp = tid >> 5;

    float2 vals[4];
    float m = -INFINITY;
#pragma unroll
    for (int i = 0; i < 4; i++) {
        vals[i] = __half22float2(p2[tid + i * 256]);
        m = fmaxf(m, fmaxf(vals[i].x, vals[i].y));
    }
    m = warp_max(m);
    if (lane == 0) red[warp] = m;
    __syncthreads();
    if (warp == 0) {
        float x = (lane < 8) ? red[lane] : -INFINITY;
        x = warp_max(x);
        if (lane == 0) red[0] = x;
    }
    __syncthreads();
    m = red[0];
    __syncthreads();

    float s = 0.f;
#pragma unroll
    for (int i = 0; i < 4; i++) {
        vals[i].x = expf(vals[i].x - m);
        vals[i].y = expf(vals[i].y - m);
        s += vals[i].x + vals[i].y;
    }
    s = warp_sum(s);
    if (lane == 0) red[warp] = s;
    __syncthreads();
    if (warp == 0) {
        float x = (lane < 8) ? red[lane] : 0.f;
        x = warp_sum(x);
        if (lane == 0) red[0] = x;
    }
    __syncthreads();
    const float inv = 1.f / red[0];

#pragma unroll
    for (int i = 0; i < 4; i++) {
        float2 o = make_float2(vals[i].x * inv, vals[i].y * inv);
        p2[tid + i * 256] = __float22half2_rn(o);
    }
}

// ---------------------------------------------------------------------------
extern "C" void kernel_launch(void* const* d_in, const int* in_sizes, int n_in,
                              void* d_out, int out_size)
{
    const float* query = (const float*)d_in[0];
    const float* key   = (const float*)d_in[1];
    const float* value = (const float*)d_in[2];
    const float* Wq    = (const float*)d_in[3];
    const float* bq    = (const float*)d_in[4];
    const float* Wk    = (const float*)d_in[5];
    const float* bk    = (const float*)d_in[6];
    const float* Wv    = (const float*)d_in[7];
    const float* bv    = (const float*)d_in[8];
    float* out = (float*)d_out;

    __half *in16, *wt16, *qkv, *ph;
    float *bias3;
    cudaGetSymbolAddress((void**)&in16,  g_in);
    cudaGetSymbolAddress((void**)&wt16,  g_wt);
    cudaGetSymbolAddress((void**)&bias3, g_bias);
    cudaGetSymbolAddress((void**)&qkv,   g_qkv);
    cudaGetSymbolAddress((void**)&ph,    g_ph);

    cudaFuncSetAttribute(hgemm<2, true,  false>, cudaFuncAttributeMaxDynamicSharedMemorySize, SMEM_GEMM_K);
    cudaFuncSetAttribute(hgemm<2, false, false>, cudaFuncAttributeMaxDynamicSharedMemorySize, SMEM_GEMM_K);
    cudaFuncSetAttribute(hgemm<0, false, true >, cudaFuncAttributeMaxDynamicSharedMemorySize, SMEM_GEMM_T);

    // 0) biases -> contiguous slab (D2D async copies are graph-capturable)
    cudaMemcpyAsync(bias3 + 0 * EE, bq, EE * sizeof(float), cudaMemcpyDeviceToDevice);
    cudaMemcpyAsync(bias3 + 1 * EE, bk, EE * sizeof(float), cudaMemcpyDeviceToDevice);
    cudaMemcpyAsync(bias3 + 2 * EE, bv, EE * sizeof(float), cudaMemcpyDeviceToDevice);

    // 1) convert fp32 inputs -> fp16 slabs (one launch)
    {
        Src3 s{query, key, value};
        dim3 g((unsigned)(NBS / (256 * 4)), 1, 3);
        convert3_kernel<<<g, 256>>>(s, in16, NBS);
    }
    // 2) transpose weights -> fp16 W^T slabs (one launch)
    {
        Src3 s{Wq, Wk, Wv};
        dim3 g(EE / 32, EE / 32, 3), b(32, 8);
        transpose3_kernel<<<g, b>>>(s, wt16, EE, EE);
    }
    // 3) q,k,v projections in ONE launch (z strides over slabs)
    {
        dim3 g(EE / 128, (BB * SS) / 128, 3);
        hgemm<2, true, false><<<g, 256, SMEM_GEMM_K>>>(
            in16, wt16, bias3, nullptr, qkv,
            BB * SS, EE, EE,
            (long long)NBS, (long long)NW, (long long)NBS,
            EE, 1.0f);
    }
    // 4) scores: S = (q @ k^T) / 32, per batch -> fp16 g_ph
    {
        dim3 g(SS / 128, SS / 128, BB);
        hgemm<2, false, false><<<g, 256, SMEM_GEMM_K>>>(
            qkv /*q slab*/, qkv + NBS /*k slab*/, nullptr, nullptr, ph,
            SS, SS, EE,
            (long long)SS * EE, (long long)SS * EE, (long long)SS * SS,
            0, 1.0f / 32.0f);
    }
    // 5) softmax in-place on fp16
    softmax_h_inplace_kernel<<<BB * SS, 256>>>(ph, SS);
    // 6) out = P @ V (V row-major via TRANS_B), per batch -> d_out (fp32)
    {
        dim3 g(EE / 128, SS / 128, BB);
        hgemm<0, false, true><<<g, 256, SMEM_GEMM_T>>>(
            ph, qkv + 2 * NBS /*v slab [S,E]*/, nullptr, out, nullptr,
            SS, EE, SS,
            (long long)SS * SS, (long long)SS * EE, (long long)SS * EE,
            0, 1.0f);
    }
}

// round 13
// speedup vs baseline: 6.6802x; 1.0003x over previous
#include <cuda_runtime.h>
#include <cuda_fp16.h>
#include <math.h>
#include <stdint.h>

#define BB 4
#define SS 2048
#define EE 1024

#define NBS ((size_t)BB * SS * EE)   // 8388608
#define NW  ((size_t)EE * EE)        // 1048576
#define NP  ((size_t)BB * SS * SS)   // 16777216

// ---------------------------------------------------------------------------
// Scratch (__device__ globals) — contiguous slabs so grid.z can stride
// ---------------------------------------------------------------------------
__device__ __align__(256) __half g_in[3 * NBS];    // fp16 inputs   (q,k,v slabs)
__device__ __align__(256) __half g_wt[3 * NW];     // fp16 W^T      (q,k,v slabs)
__device__ __align__(256) float  g_bias[3 * EE];   // fp32 biases   (q,k,v slabs)
__device__ __align__(256) __half g_qkv[3 * NBS];   // fp16 q,k,v projections
__device__ __align__(256) __half g_ph[NP];         // fp16 scores -> probs (in-place)

struct Src3 { const float* p0; const float* p1; const float* p2; };

// ---------------------------------------------------------------------------
// Baseline-PTX primitives (compute_103-safe)
// ---------------------------------------------------------------------------
__device__ __forceinline__ uint32_t smem_u32(const void* p) {
    uint32_t a;
    asm("{ .reg .u64 t; cvta.to.shared.u64 t, %1; cvt.u32.u64 %0, t; }"
        : "=r"(a) : "l"(p));
    return a;
}

__device__ __forceinline__ void cp_async16(uint32_t s, const void* g) {
    asm volatile("cp.async.cg.shared.global [%0], [%1], 16;" :: "r"(s), "l"(g));
}
__device__ __forceinline__ void cp_commit() {
    asm volatile("cp.async.commit_group;" ::: "memory");
}
__device__ __forceinline__ void cp_wait1() {
    asm volatile("cp.async.wait_group 1;" ::: "memory");
}

__device__ __forceinline__ void ldsm4(uint32_t* r, uint32_t addr) {
    asm volatile("ldmatrix.sync.aligned.m8n8.x4.shared.b16 {%0,%1,%2,%3}, [%4];"
        : "=r"(r[0]), "=r"(r[1]), "=r"(r[2]), "=r"(r[3]) : "r"(addr));
}
__device__ __forceinline__ void ldsm4t(uint32_t* r, uint32_t addr) {
    asm volatile("ldmatrix.sync.aligned.m8n8.x4.trans.shared.b16 {%0,%1,%2,%3}, [%4];"
        : "=r"(r[0]), "=r"(r[1]), "=r"(r[2]), "=r"(r[3]) : "r"(addr));
}

__device__ __forceinline__ void mma16816(float* c, const uint32_t* a,
                                         const uint32_t* b) {
    asm volatile(
        "mma.sync.aligned.m16n8k16.row.col.f32.f16.f16.f32 "
        "{%0,%1,%2,%3}, {%4,%5,%6,%7}, {%8,%9}, {%0,%1,%2,%3};"
        : "+f"(c[0]), "+f"(c[1]), "+f"(c[2]), "+f"(c[3])
        : "r"(a[0]), "r"(a[1]), "r"(a[2]), "r"(a[3]), "r"(b[0]), "r"(b[1]));
}

// ---------------------------------------------------------------------------
// HMMA fp16 GEMM, 2 CTAs/SM, fragment-double-buffered inner loop.
//   TRANS_B = false: C = alpha*(A[M,K] @ B[N,K]^T)+bias  (B K-major)
//   TRANS_B = true : C = alpha*(A[M,K] @ B[K,N])+bias    (B N-major, e.g. V[S,E])
//   CTA 128x128, BK=64, 8 warps (2x4), warp tile 64x32, 3-stage cp.async.
//   OUT_MODE: 0 = fp32, 2 = fp16
// ---------------------------------------------------------------------------
#define ROWH 72                           // K-major pitch: 64 + 8 pad halves
#define TBPITCH 136                       // N-major pitch: 128 + 8 pad halves
#define TILE_A (128 * ROWH * 2)           // 18432 B
#define TILE_BK (128 * ROWH * 2)          // 18432 B
#define TILE_BT (64 * TBPITCH * 2)        // 17408 B

template <int OUT_MODE, bool HAS_BIAS, bool TRANS_B>
__global__ __launch_bounds__(256, 2)
void hgemm(const __half* __restrict__ A, const __half* __restrict__ B,
           const float* __restrict__ bias,
           float* __restrict__ Cf, __half* __restrict__ Ch,
           int M, int N, int K,
           long long sA, long long sB, long long sC,
           int biasStride, float alpha)
{
    constexpr int TILE_BSZ = TRANS_B ? TILE_BT : TILE_BK;
    constexpr int STAGE = TILE_A + TILE_BSZ;
    extern __shared__ __half sm[];
    const uint32_t sbase = smem_u32(sm);

    const int tid  = threadIdx.x;
    const int lane = tid & 31;
    const int wid  = tid >> 5;
    const int wm   = (wid >> 2) * 64;      // 0,64
    const int wn   = (wid & 3) * 32;       // 0..96

    const int n0 = blockIdx.x * 128;
    const int m0 = blockIdx.y * 128;

    A += (size_t)blockIdx.z * sA;
    B += (size_t)blockIdx.z * sB;
    if (HAS_BIAS) bias += (size_t)blockIdx.z * biasStride;

    const int nch = K >> 6;                // BK = 64

    auto issue_stage = [&](int c, int buf) {
        const int kt = c << 6;
        const uint32_t st = (uint32_t)buf * STAGE;
        // A: 128 rows x 8 chunks = 1024 chunks, 4/thread
#pragma unroll
        for (int it = 0; it < 4; ++it) {
            const int i = it * 256 + tid;
            const int r  = i >> 3;
            const int cm = i & 7;
            const __half* g = A + (size_t)(m0 + r) * K + kt + cm * 8;
            const uint32_t s = sbase + st + (uint32_t)r * (ROWH * 2)
                             + (uint32_t)cm * 16;
            cp_async16(s, g);
        }
        if (!TRANS_B) {
            // B: 128 n-rows x 8 chunks = 1024 chunks, 4/thread
#pragma unroll
            for (int it = 0; it < 4; ++it) {
                const int i = it * 256 + tid;
                const int r  = i >> 3;
                const int cm = i & 7;
                const __half* g = B + (size_t)(n0 + r) * K + kt + cm * 8;
                const uint32_t s = sbase + st + (uint32_t)TILE_A
                                 + (uint32_t)r * (ROWH * 2) + (uint32_t)cm * 16;
                cp_async16(s, g);
            }
        } else {
            // B: 64 k-rows x 16 chunks = 1024 chunks, 4/thread
#pragma unroll
            for (int it = 0; it < 4; ++it) {
                const int i = it * 256 + tid;
                const int r  = i >> 4;
                const int cm = i & 15;
                const __half* g = B + (size_t)(kt + r) * N + n0 + cm * 8;
                const uint32_t s = sbase + st + (uint32_t)TILE_A
                                 + (uint32_t)r * (TBPITCH * 2) + (uint32_t)cm * 16;
                cp_async16(s, g);
            }
        }
        cp_commit();
    };

    float acc[4][4][4];
#pragma unroll
    for (int i = 0; i < 4; ++i)
#pragma unroll
        for (int j = 0; j < 4; ++j)
#pragma unroll
            for (int q = 0; q < 4; ++q) acc[i][j][q] = 0.f;

    issue_stage(0, 0);
    issue_stage(1, 1);

    // fragment double buffers
    uint32_t ah[2][4][4];
    uint32_t bh[2][2][4];

    for (int c = 0; c < nch; ++c) {
        cp_wait1();
        __syncthreads();

        if (c + 2 < nch) issue_stage(c + 2, (c + 2) % 3);
        else             cp_commit();   // keep group counts aligned

        const uint32_t st = (uint32_t)(c % 3) * STAGE;
        const uint32_t sA_ = sbase + st;
        const uint32_t sB_ = sA_ + TILE_A;

        // per-thread invariant address components
        const uint32_t aAddr = sA_ + (uint32_t)(wm + (lane & 15)) * (ROWH * 2)
                             + (uint32_t)((lane >> 4) << 3) * 2;
        uint32_t bAddrK = 0, bAddrT = 0;
        if (!TRANS_B)
            bAddrK = sB_ + (uint32_t)(wn + ((lane >> 4) << 3) + (lane & 7)) * (ROWH * 2)
                   + (uint32_t)(((lane >> 3) & 1) << 3) * 2;
        else
            bAddrT = sB_ + (uint32_t)((((lane >> 3) & 1) << 3) + (lane & 7)) * (TBPITCH * 2)
                   + (uint32_t)(wn + ((lane >> 4) << 3)) * 2;

        auto load_a = [&](int buf, int ks) {
#pragma unroll
            for (int mi = 0; mi < 4; ++mi)
                ldsm4(ah[buf][mi], aAddr + (uint32_t)(mi * 16) * (ROWH * 2)
                                         + (uint32_t)ks * 2);
        };
        auto load_b = [&](int buf, int ks) {
            if (!TRANS_B) {
#pragma unroll
                for (int nb = 0; nb < 2; ++nb)
                    ldsm4(bh[buf][nb], bAddrK + (uint32_t)(nb * 16) * (ROWH * 2)
                                              + (uint32_t)ks * 2);
            } else {
#pragma unroll
                for (int nb = 0; nb < 2; ++nb)
                    ldsm4t(bh[buf][nb], bAddrT + (uint32_t)ks * (TBPITCH * 2)
                                               + (uint32_t)(nb * 16) * 2);
            }
        };

        load_a(0, 0);
        load_b(0, 0);

#pragma unroll
        for (int s = 0; s < 4; ++s) {
            const int cur = s & 1;
            const int nxt = cur ^ 1;
            if (s < 3) {                // prefetch next ks-step's fragments
                load_a(nxt, (s + 1) * 16);
                load_b(nxt, (s + 1) * 16);
            }
#pragma unroll
            for (int mi = 0; mi < 4; ++mi)
#pragma unroll
                for (int nf = 0; nf < 4; ++nf)
                    mma16816(acc[mi][nf], ah[cur][mi],
                             &bh[cur][nf >> 1][(nf & 1) << 1]);
        }
    }

    // ---- epilogue: each warp writes 64x32 ----
    const long long cbo = (long long)blockIdx.z * sC;
#pragma unroll
    for (int mi = 0; mi < 4; ++mi) {
        const int r0 = m0 + wm + mi * 16 + (lane >> 2);
#pragma unroll
        for (int nf = 0; nf < 4; ++nf) {
            const int col = n0 + wn + nf * 8 + (lane & 3) * 2;
            float b0 = 0.f, b1 = 0.f;
            if (HAS_BIAS) { b0 = __ldg(&bias[col]); b1 = __ldg(&bias[col + 1]); }
            const float v0 = acc[mi][nf][0] * alpha + b0;
            const float v1 = acc[mi][nf][1] * alpha + b1;
            const float v2 = acc[mi][nf][2] * alpha + b0;
            const float v3 = acc[mi][nf][3] * alpha + b1;
            const long long o0 = cbo + (long long)r0 * N + col;
            const long long o1 = o0 + 8LL * N;
            if (OUT_MODE == 0) {
                *reinterpret_cast<float2*>(Cf + o0) = make_float2(v0, v1);
                *reinterpret_cast<float2*>(Cf + o1) = make_float2(v2, v3);
            } else {
                *reinterpret_cast<__half2*>(Ch + o0) =
                    __halves2half2(__float2half_rn(v0), __float2half_rn(v1));
                *reinterpret_cast<__half2*>(Ch + o1) =
                    __halves2half2(__float2half_rn(v2), __float2half_rn(v3));
            }
        }
    }
}

#define SMEM_GEMM_K (3 * (TILE_A + TILE_BK))   // 110592 B
#define SMEM_GEMM_T (3 * (TILE_A + TILE_BT))   // 107520 B

// ---------------------------------------------------------------------------
// fp32 -> fp16 convert, 3 tensors in one launch (grid.z)
// ---------------------------------------------------------------------------
__global__ __launch_bounds__(256)
void convert3_kernel(Src3 src, __half* __restrict__ dst, size_t n)
{
    const float* in = (blockIdx.z == 0) ? src.p0 : (blockIdx.z == 1) ? src.p1 : src.p2;
    __half* o = dst + (size_t)blockIdx.z * n;
    size_t i = ((size_t)blockIdx.x * 256 + threadIdx.x) * 4;
    if (i >= n) return;
    float4 v = *reinterpret_cast<const float4*>(in + i);
    __half h[4];
    h[0] = __float2half_rn(v.x); h[1] = __float2half_rn(v.y);
    h[2] = __float2half_rn(v.z); h[3] = __float2half_rn(v.w);
    *reinterpret_cast<uint2*>(o + i) = *reinterpret_cast<const uint2*>(h);
}

// ---------------------------------------------------------------------------
// fp32 W[in,out] -> fp16 W^T[out,in], 3 weights in one launch (grid.z)
// ---------------------------------------------------------------------------
__global__ __launch_bounds__(256)
void transpose3_kernel(Src3 src, __half* __restrict__ dst, int R, int C)
{
    __shared__ float t[32][33];
    const float* in = (blockIdx.z == 0) ? src.p0 : (blockIdx.z == 1) ? src.p1 : src.p2;
    __half* oh = dst + (size_t)blockIdx.z * R * C;
    const int c0 = blockIdx.x * 32, r0 = blockIdx.y * 32;
    const int tx = threadIdx.x, ty = threadIdx.y;  // 32 x 8
#pragma unroll
    for (int j = 0; j < 4; ++j)
        t[ty + 8 * j][tx] = in[(size_t)(r0 + ty + 8 * j) * C + c0 + tx];
    __syncthreads();
#pragma unroll
    for (int j = 0; j < 4; ++j) {
        const size_t o = (size_t)(c0 + ty + 8 * j) * R + r0 + tx;
        oh[o] = __float2half_rn(t[tx][ty + 8 * j]);
    }
}

// ---------------------------------------------------------------------------
// In-place row softmax on fp16 (2048 cols), fp32 math, half2 vectorized
// ---------------------------------------------------------------------------
__inline__ __device__ float warp_max(float v) {
#pragma unroll
    for (int o = 16; o; o >>= 1) v = fmaxf(v, __shfl_xor_sync(0xFFFFFFFFu, v, o));
    return v;
}
__inline__ __device__ float warp_sum(float v) {
#pragma unroll
    for (int o = 16; o; o >>= 1) v += __shfl_xor_sync(0xFFFFFFFFu, v, o);
    return v;
}

__global__ __launch_bounds__(256)
void softmax_h_inplace_kernel(__half* __restrict__ P, int n)
{
    __shared__ float red[8];
    const size_t row = blockIdx.x;
    __half2* p2 = reinterpret_cast<__half2*>(P + row * (size_t)n);
    const int tid  = threadIdx.x;
    const int lane = tid & 31;
    const int warp = tid >> 5;

    float2 vals[4];
    float m = -INFINITY;
#pragma unroll
    for (int i = 0; i < 4; i++) {
        vals[i] = __half22float2(p2[tid + i * 256]);
        m = fmaxf(m, fmaxf(vals[i].x, vals[i].y));
    }
    m = warp_max(m);
    if (lane == 0) red[warp] = m;
    __syncthreads();
    if (warp == 0) {
        float x = (lane < 8) ? red[lane] : -INFINITY;
        x = warp_max(x);
        if (lane == 0) red[0] = x;
    }
    __syncthreads();
    m = red[0];
    __syncthreads();

    float s = 0.f;
#pragma unroll
    for (int i = 0; i < 4; i++) {
        vals[i].x = expf(vals[i].x - m);
        vals[i].y = expf(vals[i].y - m);
        s += vals[i].x + vals[i].y;
    }
    s = warp_sum(s);
    if (lane == 0) red[warp] = s;
    __syncthreads();
    if (warp == 0) {
        float x = (lane < 8) ? red[lane] : 0.f;
        x = warp_sum(x);
        if (lane == 0) red[0] = x;
    }
    __syncthreads();
    const float inv = 1.f / red[0];

#pragma unroll
    for (int i = 0; i < 4; i++) {
        float2 o = make_float2(vals[i].x * inv, vals[i].y * inv);
        p2[tid + i * 256] = __float22half2_rn(o);
    }
}

// ---------------------------------------------------------------------------
extern "C" void kernel_launch(void* const* d_in, const int* in_sizes, int n_in,
                              void* d_out, int out_size)
{
    const float* query = (const float*)d_in[0];
    const float* key   = (const float*)d_in[1];
    const float* value = (const float*)d_in[2];
    const float* Wq    = (const float*)d_in[3];
    const float* bq    = (const float*)d_in[4];
    const float* Wk    = (const float*)d_in[5];
    const float* bk    = (const float*)d_in[6];
    const float* Wv    = (const float*)d_in[7];
    const float* bv    = (const float*)d_in[8];
    float* out = (float*)d_out;

    __half *in16, *wt16, *qkv, *ph;
    float *bias3;
    cudaGetSymbolAddress((void**)&in16,  g_in);
    cudaGetSymbolAddress((void**)&wt16,  g_wt);
    cudaGetSymbolAddress((void**)&bias3, g_bias);
    cudaGetSymbolAddress((void**)&qkv,   g_qkv);
    cudaGetSymbolAddress((void**)&ph,    g_ph);

    cudaFuncSetAttribute(hgemm<2, true,  false>, cudaFuncAttributeMaxDynamicSharedMemorySize, SMEM_GEMM_K);
    cudaFuncSetAttribute(hgemm<2, false, false>, cudaFuncAttributeMaxDynamicSharedMemorySize, SMEM_GEMM_K);
    cudaFuncSetAttribute(hgemm<0, false, true >, cudaFuncAttributeMaxDynamicSharedMemorySize, SMEM_GEMM_T);

    // 0) biases -> contiguous slab (D2D async copies are graph-capturable)
    cudaMemcpyAsync(bias3 + 0 * EE, bq, EE * sizeof(float), cudaMemcpyDeviceToDevice);
    cudaMemcpyAsync(bias3 + 1 * EE, bk, EE * sizeof(float), cudaMemcpyDeviceToDevice);
    cudaMemcpyAsync(bias3 + 2 * EE, bv, EE * sizeof(float), cudaMemcpyDeviceToDevice);

    // 1) convert fp32 inputs -> fp16 slabs (one launch)
    {
        Src3 s{query, key, value};
        dim3 g((unsigned)(NBS / (256 * 4)), 1, 3);
        convert3_kernel<<<g, 256>>>(s, in16, NBS);
    }
    // 2) transpose weights -> fp16 W^T slabs (one launch)
    {
        Src3 s{Wq, Wk, Wv};
        dim3 g(EE / 32, EE / 32, 3), b(32, 8);
        transpose3_kernel<<<g, b>>>(s, wt16, EE, EE);
    }
    // 3) q,k,v projections in ONE launch (z strides over slabs)
    {
        dim3 g(EE / 128, (BB * SS) / 128, 3);
        hgemm<2, true, false><<<g, 256, SMEM_GEMM_K>>>(
            in16, wt16, bias3, nullptr, qkv,
            BB * SS, EE, EE,
            (long long)NBS, (long long)NW, (long long)NBS,
            EE, 1.0f);
    }
    // 4) scores: S = (q @ k^T) / 32, per batch -> fp16 g_ph
    {
        dim3 g(SS / 128, SS / 128, BB);
        hgemm<2, false, false><<<g, 256, SMEM_GEMM_K>>>(
            qkv /*q slab*/, qkv + NBS /*k slab*/, nullptr, nullptr, ph,
            SS, SS, EE,
            (long long)SS * EE, (long long)SS * EE, (long long)SS * SS,
            0, 1.0f / 32.0f);
    }
    // 5) softmax in-place on fp16
    softmax_h_inplace_kernel<<<BB * SS, 256>>>(ph, SS);
    // 6) out = P @ V (V row-major via TRANS_B), per batch -> d_out (fp32)
    {
        dim3 g(EE / 128, SS / 128, BB);
        hgemm<0, false, true><<<g, 256, SMEM_GEMM_T>>>(
            ph, qkv + 2 * NBS /*v slab [S,E]*/, nullptr, out, nullptr,
            SS, EE, SS,
            (long long)SS * SS, (long long)SS * EE, (long long)SS * EE,
            0, 1.0f);
    }
}

// round 14
// speedup vs baseline: 6.7046x; 1.0037x over previous
#include <cuda_runtime.h>
#include <cuda_fp16.h>
#include <math.h>
#include <stdint.h>

#define BB 4
#define SS 2048
#define EE 1024

#define NBS ((size_t)BB * SS * EE)   // 8388608
#define NW  ((size_t)EE * EE)        // 1048576
#define NP  ((size_t)BB * SS * SS)   // 16777216

// ---------------------------------------------------------------------------
// Scratch (__device__ globals) — contiguous slabs so grid.z can stride
// ---------------------------------------------------------------------------
__device__ __align__(256) __half g_in[3 * NBS];    // fp16 inputs   (q,k,v slabs)
__device__ __align__(256) __half g_wt[3 * NW];     // fp16 W^T      (q,k,v slabs)
__device__ __align__(256) float  g_bias[3 * EE];   // fp32 biases   (q,k,v slabs)
__device__ __align__(256) __half g_qkv[3 * NBS];   // fp16 q,k,v projections
__device__ __align__(256) __half g_ph[NP];         // fp16 scores -> probs (in-place)

struct Src3 { const float* p0; const float* p1; const float* p2; };

// ---------------------------------------------------------------------------
// Baseline-PTX primitives (compute_103-safe)
// ---------------------------------------------------------------------------
__device__ __forceinline__ uint32_t smem_u32(const void* p) {
    uint32_t a;
    asm("{ .reg .u64 t; cvta.to.shared.u64 t, %1; cvt.u32.u64 %0, t; }"
        : "=r"(a) : "l"(p));
    return a;
}

__device__ __forceinline__ void cp_async16(uint32_t s, const void* g) {
    asm volatile("cp.async.cg.shared.global [%0], [%1], 16;" :: "r"(s), "l"(g));
}
__device__ __forceinline__ void cp_commit() {
    asm volatile("cp.async.commit_group;" ::: "memory");
}
__device__ __forceinline__ void cp_wait1() {
    asm volatile("cp.async.wait_group 1;" ::: "memory");
}

__device__ __forceinline__ void ldsm4(uint32_t* r, uint32_t addr) {
    asm volatile("ldmatrix.sync.aligned.m8n8.x4.shared.b16 {%0,%1,%2,%3}, [%4];"
        : "=r"(r[0]), "=r"(r[1]), "=r"(r[2]), "=r"(r[3]) : "r"(addr));
}
__device__ __forceinline__ void ldsm4t(uint32_t* r, uint32_t addr) {
    asm volatile("ldmatrix.sync.aligned.m8n8.x4.trans.shared.b16 {%0,%1,%2,%3}, [%4];"
        : "=r"(r[0]), "=r"(r[1]), "=r"(r[2]), "=r"(r[3]) : "r"(addr));
}

__device__ __forceinline__ void mma16816(float* c, const uint32_t* a,
                                         const uint32_t* b) {
    asm volatile(
        "mma.sync.aligned.m16n8k16.row.col.f32.f16.f16.f32 "
        "{%0,%1,%2,%3}, {%4,%5,%6,%7}, {%8,%9}, {%0,%1,%2,%3};"
        : "+f"(c[0]), "+f"(c[1]), "+f"(c[2]), "+f"(c[3])
        : "r"(a[0]), "r"(a[1]), "r"(a[2]), "r"(a[3]), "r"(b[0]), "r"(b[1]));
}

// ---------------------------------------------------------------------------
// HMMA fp16 GEMM, 2 CTAs/SM, fragment-double-buffered inner loop.
//   TRANS_B = false: C = alpha*(A[M,K] @ B[N,K]^T)+bias  (B K-major)
//   TRANS_B = true : C = alpha*(A[M,K] @ B[K,N])+bias    (B N-major, e.g. V[S,E])
//   CTA 128x128, BK=64, 8 warps (2x4), warp tile 64x32, 3-stage cp.async.
//   OUT_MODE: 0 = fp32, 2 = fp16
// ---------------------------------------------------------------------------
#define ROWH 72                           // K-major pitch: 64 + 8 pad halves
#define TBPITCH 136                       // N-major pitch: 128 + 8 pad halves
#define TILE_A (128 * ROWH * 2)           // 18432 B
#define TILE_BK (128 * ROWH * 2)          // 18432 B
#define TILE_BT (64 * TBPITCH * 2)        // 17408 B

template <int OUT_MODE, bool HAS_BIAS, bool TRANS_B>
__global__ __launch_bounds__(256, 2)
void hgemm(const __half* __restrict__ A, const __half* __restrict__ B,
           const float* __restrict__ bias,
           float* __restrict__ Cf, __half* __restrict__ Ch,
           int M, int N, int K,
           long long sA, long long sB, long long sC,
           int biasStride, float alpha)
{
    constexpr int TILE_BSZ = TRANS_B ? TILE_BT : TILE_BK;
    constexpr int STAGE = TILE_A + TILE_BSZ;
    extern __shared__ __half sm[];
    const uint32_t sbase = smem_u32(sm);

    const int tid  = threadIdx.x;
    const int lane = tid & 31;
    const int wid  = tid >> 5;
    const int wm   = (wid >> 2) * 64;      // 0,64
    const int wn   = (wid & 3) * 32;       // 0..96

    const int n0 = blockIdx.x * 128;
    const int m0 = blockIdx.y * 128;

    A += (size_t)blockIdx.z * sA;
    B += (size_t)blockIdx.z * sB;
    if (HAS_BIAS) bias += (size_t)blockIdx.z * biasStride;

    const int nch = K >> 6;                // BK = 64

    auto issue_stage = [&](int c, int buf) {
        const int kt = c << 6;
        const uint32_t st = (uint32_t)buf * STAGE;
        // A: 128 rows x 8 chunks = 1024 chunks, 4/thread
#pragma unroll
        for (int it = 0; it < 4; ++it) {
            const int i = it * 256 + tid;
            const int r  = i >> 3;
            const int cm = i & 7;
            const __half* g = A + (size_t)(m0 + r) * K + kt + cm * 8;
            const uint32_t s = sbase + st + (uint32_t)r * (ROWH * 2)
                             + (uint32_t)cm * 16;
            cp_async16(s, g);
        }
        if (!TRANS_B) {
            // B: 128 n-rows x 8 chunks = 1024 chunks, 4/thread
#pragma unroll
            for (int it = 0; it < 4; ++it) {
                const int i = it * 256 + tid;
                const int r  = i >> 3;
                const int cm = i & 7;
                const __half* g = B + (size_t)(n0 + r) * K + kt + cm * 8;
                const uint32_t s = sbase + st + (uint32_t)TILE_A
                                 + (uint32_t)r * (ROWH * 2) + (uint32_t)cm * 16;
                cp_async16(s, g);
            }
        } else {
            // B: 64 k-rows x 16 chunks = 1024 chunks, 4/thread
#pragma unroll
            for (int it = 0; it < 4; ++it) {
                const int i = it * 256 + tid;
                const int r  = i >> 4;
                const int cm = i & 15;
                const __half* g = B + (size_t)(kt + r) * N + n0 + cm * 8;
                const uint32_t s = sbase + st + (uint32_t)TILE_A
                                 + (uint32_t)r * (TBPITCH * 2) + (uint32_t)cm * 16;
                cp_async16(s, g);
            }
        }
        cp_commit();
    };

    float acc[4][4][4];
#pragma unroll
    for (int i = 0; i < 4; ++i)
#pragma unroll
        for (int j = 0; j < 4; ++j)
#pragma unroll
            for (int q = 0; q < 4; ++q) acc[i][j][q] = 0.f;

    issue_stage(0, 0);
    issue_stage(1, 1);

    // fragment double buffers
    uint32_t ah[2][4][4];
    uint32_t bh[2][2][4];

    for (int c = 0; c < nch; ++c) {
        cp_wait1();
        __syncthreads();

        if (c + 2 < nch) issue_stage(c + 2, (c + 2) % 3);
        else             cp_commit();   // keep group counts aligned

        const uint32_t st = (uint32_t)(c % 3) * STAGE;
        const uint32_t sA_ = sbase + st;
        const uint32_t sB_ = sA_ + TILE_A;

        // per-thread invariant address components
        const uint32_t aAddr = sA_ + (uint32_t)(wm + (lane & 15)) * (ROWH * 2)
                             + (uint32_t)((lane >> 4) << 3) * 2;
        uint32_t bAddrK = 0, bAddrT = 0;
        if (!TRANS_B)
            bAddrK = sB_ + (uint32_t)(wn + ((lane >> 4) << 3) + (lane & 7)) * (ROWH * 2)
                   + (uint32_t)(((lane >> 3) & 1) << 3) * 2;
        else
            bAddrT = sB_ + (uint32_t)((((lane >> 3) & 1) << 3) + (lane & 7)) * (TBPITCH * 2)
                   + (uint32_t)(wn + ((lane >> 4) << 3)) * 2;

        auto load_a = [&](int buf, int ks) {
#pragma unroll
            for (int mi = 0; mi < 4; ++mi)
                ldsm4(ah[buf][mi], aAddr + (uint32_t)(mi * 16) * (ROWH * 2)
                                         + (uint32_t)ks * 2);
        };
        auto load_b = [&](int buf, int ks) {
            if (!TRANS_B) {
#pragma unroll
                for (int nb = 0; nb < 2; ++nb)
                    ldsm4(bh[buf][nb], bAddrK + (uint32_t)(nb * 16) * (ROWH * 2)
                                              + (uint32_t)ks * 2);
            } else {
#pragma unroll
                for (int nb = 0; nb < 2; ++nb)
                    ldsm4t(bh[buf][nb], bAddrT + (uint32_t)ks * (TBPITCH * 2)
                                               + (uint32_t)(nb * 16) * 2);
            }
        };

        load_a(0, 0);
        load_b(0, 0);

#pragma unroll
        for (int s = 0; s < 4; ++s) {
            const int cur = s & 1;
            const int nxt = cur ^ 1;
            if (s < 3) {                // prefetch next ks-step's fragments
                load_a(nxt, (s + 1) * 16);
                load_b(nxt, (s + 1) * 16);
            }
#pragma unroll
            for (int mi = 0; mi < 4; ++mi)
#pragma unroll
                for (int nf = 0; nf < 4; ++nf)
                    mma16816(acc[mi][nf], ah[cur][mi],
                             &bh[cur][nf >> 1][(nf & 1) << 1]);
        }
    }

    // ---- epilogue: each warp writes 64x32 ----
    const long long cbo = (long long)blockIdx.z * sC;
#pragma unroll
    for (int mi = 0; mi < 4; ++mi) {
        const int r0 = m0 + wm + mi * 16 + (lane >> 2);
#pragma unroll
        for (int nf = 0; nf < 4; ++nf) {
            const int col = n0 + wn + nf * 8 + (lane & 3) * 2;
            float b0 = 0.f, b1 = 0.f;
            if (HAS_BIAS) { b0 = __ldg(&bias[col]); b1 = __ldg(&bias[col + 1]); }
            const float v0 = acc[mi][nf][0] * alpha + b0;
            const float v1 = acc[mi][nf][1] * alpha + b1;
            const float v2 = acc[mi][nf][2] * alpha + b0;
            const float v3 = acc[mi][nf][3] * alpha + b1;
            const long long o0 = cbo + (long long)r0 * N + col;
            const long long o1 = o0 + 8LL * N;
            if (OUT_MODE == 0) {
                *reinterpret_cast<float2*>(Cf + o0) = make_float2(v0, v1);
                *reinterpret_cast<float2*>(Cf + o1) = make_float2(v2, v3);
            } else {
                *reinterpret_cast<__half2*>(Ch + o0) =
                    __halves2half2(__float2half_rn(v0), __float2half_rn(v1));
                *reinterpret_cast<__half2*>(Ch + o1) =
                    __halves2half2(__float2half_rn(v2), __float2half_rn(v3));
            }
        }
    }
}

#define SMEM_GEMM_K (3 * (TILE_A + TILE_BK))   // 110592 B
#define SMEM_GEMM_T (3 * (TILE_A + TILE_BT))   // 107520 B

// ---------------------------------------------------------------------------
// fp32 -> fp16 convert, 3 tensors in one launch (grid.z)
// ---------------------------------------------------------------------------
__global__ __launch_bounds__(256)
void convert3_kernel(Src3 src, __half* __restrict__ dst, size_t n)
{
    const float* in = (blockIdx.z == 0) ? src.p0 : (blockIdx.z == 1) ? src.p1 : src.p2;
    __half* o = dst + (size_t)blockIdx.z * n;
    size_t i = ((size_t)blockIdx.x * 256 + threadIdx.x) * 4;
    if (i >= n) return;
    float4 v = *reinterpret_cast<const float4*>(in + i);
    __half h[4];
    h[0] = __float2half_rn(v.x); h[1] = __float2half_rn(v.y);
    h[2] = __float2half_rn(v.z); h[3] = __float2half_rn(v.w);
    *reinterpret_cast<uint2*>(o + i) = *reinterpret_cast<const uint2*>(h);
}

// ---------------------------------------------------------------------------
// fp32 W[in,out] -> fp16 W^T[out,in], 3 weights in one launch (grid.z)
// ---------------------------------------------------------------------------
__global__ __launch_bounds__(256)
void transpose3_kernel(Src3 src, __half* __restrict__ dst, int R, int C)
{
    __shared__ float t[32][33];
    const float* in = (blockIdx.z == 0) ? src.p0 : (blockIdx.z == 1) ? src.p1 : src.p2;
    __half* oh = dst + (size_t)blockIdx.z * R * C;
    const int c0 = blockIdx.x * 32, r0 = blockIdx.y * 32;
    const int tx = threadIdx.x, ty = threadIdx.y;  // 32 x 8
#pragma unroll
    for (int j = 0; j < 4; ++j)
        t[ty + 8 * j][tx] = in[(size_t)(r0 + ty + 8 * j) * C + c0 + tx];
    __syncthreads();
#pragma unroll
    for (int j = 0; j < 4; ++j) {
        const size_t o = (size_t)(c0 + ty + 8 * j) * R + r0 + tx;
        oh[o] = __float2half_rn(t[tx][ty + 8 * j]);
    }
}

// ---------------------------------------------------------------------------
// In-place row softmax on fp16 (2048 cols), fp32 math, half2 vectorized
// ---------------------------------------------------------------------------
__inline__ __device__ float warp_max(float v) {
#pragma unroll
    for (int o = 16; o; o >>= 1) v = fmaxf(v, __shfl_xor_sync(0xFFFFFFFFu, v, o));
    return v;
}
__inline__ __device__ float warp_sum(float v) {
#pragma unroll
    for (int o = 16; o; o >>= 1) v += __shfl_xor_sync(0xFFFFFFFFu, v, o);
    return v;
}

__global__ __launch_bounds__(256)
void softmax_h_inplace_kernel(__half* __restrict__ P, int n)
{
    __shared__ float red[8];
    const size_t row = blockIdx.x;
    __half2* p2 = reinterpret_cast<__half2*>(P + row * (size_t)n);
    const int tid  = threadIdx.x;
    const int lane = tid & 31;
    const int warp = tid >> 5;

    float2 vals[4];
    float m = -INFINITY;
#pragma unroll
    for (int i = 0; i < 4; i++) {
        vals[i] = __half22float2(p2[tid + i * 256]);
        m = fmaxf(m, fmaxf(vals[i].x, vals[i].y));
    }
    m = warp_max(m);
    if (lane == 0) red[warp] = m;
    __syncthreads();
    if (warp == 0) {
        float x = (lane < 8) ? red[lane] : -INFINITY;
        x = warp_max(x);
        if (lane == 0) red[0] = x;
    }
    __syncthreads();
    m = red[0];
    __syncthreads();

    float s = 0.f;
#pragma unroll
    for (int i = 0; i < 4; i++) {
        vals[i].x = expf(vals[i].x - m);
        vals[i].y = expf(vals[i].y - m);
        s += vals[i].x + vals[i].y;
    }
    s = warp_sum(s);
    if (lane == 0) red[warp] = s;
    __syncthreads();
    if (warp == 0) {
        float x = (lane < 8) ? red[lane] : 0.f;
        x = warp_sum(x);
        if (lane == 0) red[0] = x;
    }
    __syncthreads();
    const float inv = 1.f / red[0];

#pragma unroll
    for (int i = 0; i < 4; i++) {
        float2 o = make_float2(vals[i].x * inv, vals[i].y * inv);
        p2[tid + i * 256] = __float22half2_rn(o);
    }
}

// ---------------------------------------------------------------------------
extern "C" void kernel_launch(void* const* d_in, const int* in_sizes, int n_in,
                              void* d_out, int out_size)
{
    const float* query = (const float*)d_in[0];
    const float* key   = (const float*)d_in[1];
    const float* value = (const float*)d_in[2];
    const float* Wq    = (const float*)d_in[3];
    const float* bq    = (const float*)d_in[4];
    const float* Wk    = (const float*)d_in[5];
    const float* bk    = (const float*)d_in[6];
    const float* Wv    = (const float*)d_in[7];
    const float* bv    = (const float*)d_in[8];
    float* out = (float*)d_out;

    __half *in16, *wt16, *qkv, *ph;
    float *bias3;
    cudaGetSymbolAddress((void**)&in16,  g_in);
    cudaGetSymbolAddress((void**)&wt16,  g_wt);
    cudaGetSymbolAddress((void**)&bias3, g_bias);
    cudaGetSymbolAddress((void**)&qkv,   g_qkv);
    cudaGetSymbolAddress((void**)&ph,    g_ph);

    cudaFuncSetAttribute(hgemm<2, true,  false>, cudaFuncAttributeMaxDynamicSharedMemorySize, SMEM_GEMM_K);
    cudaFuncSetAttribute(hgemm<2, false, false>, cudaFuncAttributeMaxDynamicSharedMemorySize, SMEM_GEMM_K);
    cudaFuncSetAttribute(hgemm<0, false, true >, cudaFuncAttributeMaxDynamicSharedMemorySize, SMEM_GEMM_T);

    // 0) biases -> contiguous slab (D2D async copies are graph-capturable)
    cudaMemcpyAsync(bias3 + 0 * EE, bq, EE * sizeof(float), cudaMemcpyDeviceToDevice);
    cudaMemcpyAsync(bias3 + 1 * EE, bk, EE * sizeof(float), cudaMemcpyDeviceToDevice);
    cudaMemcpyAsync(bias3 + 2 * EE, bv, EE * sizeof(float), cudaMemcpyDeviceToDevice);

    // 1) convert fp32 inputs -> fp16 slabs (one launch)
    {
        Src3 s{query, key, value};
        dim3 g((unsigned)(NBS / (256 * 4)), 1, 3);
        convert3_kernel<<<g, 256>>>(s, in16, NBS);
    }
    // 2) transpose weights -> fp16 W^T slabs (one launch)
    {
        Src3 s{Wq, Wk, Wv};
        dim3 g(EE / 32, EE / 32, 3), b(32, 8);
        transpose3_kernel<<<g, b>>>(s, wt16, EE, EE);
    }
    // 3) q,k,v projections in ONE launch (z strides over slabs)
    {
        dim3 g(EE / 128, (BB * SS) / 128, 3);
        hgemm<2, true, false><<<g, 256, SMEM_GEMM_K>>>(
            in16, wt16, bias3, nullptr, qkv,
            BB * SS, EE, EE,
            (long long)NBS, (long long)NW, (long long)NBS,
            EE, 1.0f);
    }
    // 4) scores: S = (q @ k^T) / 32, per batch -> fp16 g_ph
    {
        dim3 g(SS / 128, SS / 128, BB);
        hgemm<2, false, false><<<g, 256, SMEM_GEMM_K>>>(
            qkv /*q slab*/, qkv + NBS /*k slab*/, nullptr, nullptr, ph,
            SS, SS, EE,
            (long long)SS * EE, (long long)SS * EE, (long long)SS * SS,
            0, 1.0f / 32.0f);
    }
    // 5) softmax in-place on fp16
    softmax_h_inplace_kernel<<<BB * SS, 256>>>(ph, SS);
    // 6) out = P @ V (V row-major via TRANS_B), per batch -> d_out (fp32)
    {
        dim3 g(EE / 128, SS / 128, BB);
        hgemm<0, false, true><<<g, 256, SMEM_GEMM_T>>>(
            ph, qkv + 2 * NBS /*v slab [S,E]*/, nullptr, out, nullptr,
            SS, EE, SS,
            (long long)SS * SS, (long long)SS * EE, (long long)SS * EE,
            0, 1.0f);
    }
}